// round 5
// baseline (speedup 1.0000x reference)
#include <cuda_runtime.h>
#include <math.h>
#include <stdint.h>

#define EPS_LN  1e-5f
#define EPS_ATT 1e-6f

// ---------------------------------------------------------------------------
// helpers
// ---------------------------------------------------------------------------
__device__ __forceinline__ uint32_t smem_u32(const void* p) {
    uint32_t a;
    asm("{ .reg .u64 t; cvta.to.shared.u64 t, %1; cvt.u32.u64 %0, t; }" : "=r"(a) : "l"(p));
    return a;
}
__device__ __forceinline__ uint32_t f2tf(float x) {
    uint32_t r;
    asm("cvt.rna.tf32.f32 %0, %1;" : "=r"(r) : "f"(x));
    return r;
}
#define CP_ASYNC16(dst, src) \
    asm volatile("cp.async.cg.shared.global [%0], [%1], 16;" :: "r"(dst), "l"(src))
#define CP_COMMIT() asm volatile("cp.async.commit_group;")
#define CP_WAIT1()  asm volatile("cp.async.wait_group 1;" ::: "memory")
#define CP_WAIT0()  asm volatile("cp.async.wait_group 0;" ::: "memory")

__device__ __forceinline__ void mma8(float* c, const uint32_t* a, const uint32_t* b) {
    asm volatile(
        "mma.sync.aligned.m16n8k8.row.col.f32.tf32.tf32.f32 "
        "{%0,%1,%2,%3}, {%4,%5,%6,%7}, {%8,%9}, {%0,%1,%2,%3};"
        : "+f"(c[0]), "+f"(c[1]), "+f"(c[2]), "+f"(c[3])
        : "r"(a[0]), "r"(a[1]), "r"(a[2]), "r"(a[3]), "r"(b[0]), "r"(b[1]));
}

// ---------------------------------------------------------------------------
// Scratch
// ---------------------------------------------------------------------------
__device__ float g_wsrB[256 * 4096];        // conv weight [o][k=rr*256+i]
__device__ float g_part[8 * 2048 * 256];    // conv split-K partials
__device__ float g_src [2048 * 256];
__device__ float g_kmat[2048 * 256];
__device__ float g_vmat[2048 * 256];
__device__ float g_kv  [64 * 32 * 32];
__device__ float g_ksum[64 * 32];
__device__ float g_qmat[8 * 4096 * 256];
__device__ float g_msg [8 * 4096 * 256];
__device__ float g_msgn[8 * 4096 * 256];
__device__ float g_hmid[8 * 4096 * 512];

// sr_w OIHW [o][i][4][4] -> wsrB[o*4096 + rr*256 + i]
__global__ void repack_srw(const float* __restrict__ w, float* __restrict__ wb) {
    int idx = blockIdx.x * blockDim.x + threadIdx.x;   // 65536
    int o = idx >> 8, i = idx & 255;
    const float* p = w + ((size_t)(o * 256 + i)) * 16;
#pragma unroll
    for (int rr = 0; rr < 16; rr++)
        wb[(size_t)o * 4096 + rr * 256 + i] = p[rr];
}

// ---------------------------------------------------------------------------
// Split-K reduce + bias + LayerNorm -> src. grid 256, 256 thr.
// ---------------------------------------------------------------------------
__global__ void reduce_ln(const float* __restrict__ part, const float* __restrict__ bias,
                          const float* __restrict__ g, const float* __restrict__ bb,
                          float* __restrict__ out) {
    int lane = threadIdx.x & 31, w = threadIdx.x >> 5;
    int row = blockIdx.x * 8 + w;
    float v[8];
#pragma unroll
    for (int j = 0; j < 8; j++) {
        int c = lane + j * 32;
        float s = 0.f;
#pragma unroll
        for (int ks = 0; ks < 8; ks++)
            s += part[((size_t)ks * 2048 + row) * 256 + c];
        v[j] = s + bias[c];
    }
    float sum = 0.f;
#pragma unroll
    for (int j = 0; j < 8; j++) sum += v[j];
#pragma unroll
    for (int o = 16; o; o >>= 1) sum += __shfl_xor_sync(0xffffffffu, sum, o);
    float mean = sum * (1.f / 256.f);
    float ss = 0.f;
#pragma unroll
    for (int j = 0; j < 8; j++) { float d = v[j] - mean; ss += d * d; }
#pragma unroll
    for (int o = 16; o; o >>= 1) ss += __shfl_xor_sync(0xffffffffu, ss, o);
    float inv = rsqrtf(ss * (1.f / 256.f) + EPS_LN);
#pragma unroll
    for (int j = 0; j < 8; j++) {
        int c = lane + j * 32;
        out[(size_t)row * 256 + c] = (v[j] - mean) * inv * g[c] + bb[c];
    }
}

// ---------------------------------------------------------------------------
// tf32 mma.sync GEMM. BM=128, BN=256, BK=32. 512 threads, 16 warps (4x4),
// warp tile 32x64. 3-stage cp.async pipeline, ONE sync per stage.
// MODE: 0=plain A[m][Kloc], 1=concat(A0,A1), 2=conv gather + split-K,
//       3=fused k/v (blockIdx.y: 0 -> Bw/elu -> C, 1 -> Bw2/plain -> C2)
// EPI: 0 plain, 1 elu+1, 2 relu, 3 LN, 4 LN+resid
// ---------------------------------------------------------------------------
#define EPI_PLAIN    0
#define EPI_ELU1     1
#define EPI_RELU     2
#define EPI_LN       3
#define EPI_LN_RESID 4

#define ASTRIDE   36
#define STAGE_F   13824            // (128+256)*36 floats
#define AF        4608             // 128*36
#define EPISTRIDE 260
#define SMEM_REQ  165888           // 3 stages * 13824 floats * 4B

template <int EPI, int MODE>
__global__ __launch_bounds__(512, 1)
void mma_gemm(const float* __restrict__ A0, const float* __restrict__ A1,
              const float* __restrict__ Bw, float* __restrict__ C,
              int Kloc, int KB, int Ntot,
              const float* __restrict__ gamma, const float* __restrict__ beta,
              const float* __restrict__ resid,
              const float* __restrict__ Bw2, float* __restrict__ C2) {
    extern __shared__ float dsm[];
    const uint32_t sb = smem_u32(dsm);

    const int tid  = threadIdx.x;
    const int lane = tid & 31;
    const int wid  = tid >> 5;          // 0..15
    const int g    = lane >> 2;         // 0..7
    const int t    = lane & 3;          // 0..3
    const int warp_m = wid & 3;         // 4 -> rows 32 each
    const int warp_n = wid >> 2;        // 4 -> cols 64 each

    const int mtile = blockIdx.x * 128;
    int ncol0, kstart;
    float* Cblk = C;
    const float* Bsrc = Bw;
    if (MODE == 2) { ncol0 = 0; kstart = blockIdx.y * 512; Cblk = C + (size_t)blockIdx.y * 2048 * 256; }
    else if (MODE == 3) { ncol0 = 0; kstart = 0; if (blockIdx.y) { Bsrc = Bw2; Cblk = C2; } }
    else { ncol0 = blockIdx.y * 256; kstart = 0; }
    const int KT = Kloc / 32;

    float acc[2][8][4];
#pragma unroll
    for (int i = 0; i < 2; i++)
#pragma unroll
        for (int j = 0; j < 8; j++)
#pragma unroll
            for (int q = 0; q < 4; q++) acc[i][j][q] = 0.f;

    // ---- async tile loader (one commit group per stage) ----
    auto load_tile = [&](int kt, int s) {
        const int kbase = kstart + kt * 32;
        const uint32_t sA = sb + (uint32_t)s * (STAGE_F * 4);
        const uint32_t sB = sA + AF * 4;
        // A: 128x32 = 1024 float4, 2 per thread
#pragma unroll
        for (int p = 0; p < 2; p++) {
            int idx = p * 512 + tid;
            int m = idx >> 3, c = idx & 7;
            int kk = kbase + c * 4;
            const float* gp;
            if (MODE == 2) {
                int mg = mtile + m;
                int b = mg >> 8, s5 = mg & 255;
                int rr = kk >> 8, i = kk & 255;
                int n = (((s5 >> 4) * 4 + (rr >> 2)) << 6) + ((s5 & 15) << 2) + (rr & 3);
                gp = A0 + (((size_t)b << 12) + n) * 256 + i;
            } else if (MODE == 1) {
                gp = (kk < 256) ? (A0 + (size_t)(mtile + m) * 256 + kk)
                                : (A1 + (size_t)(mtile + m) * 256 + (kk - 256));
            } else {
                gp = A0 + (size_t)(mtile + m) * Kloc + kk;
            }
            CP_ASYNC16(sA + (uint32_t)(m * ASTRIDE + c * 4) * 4, gp);
        }
        // B: 256x32 = 2048 float4, 4 per thread
#pragma unroll
        for (int p = 0; p < 4; p++) {
            int idx = p * 512 + tid;
            int n = idx >> 3, c = idx & 7;
            const float* gp = Bsrc + (size_t)(ncol0 + n) * KB + kbase + c * 4;
            CP_ASYNC16(sB + (uint32_t)(n * ASTRIDE + c * 4) * 4, gp);
        }
        CP_COMMIT();
    };

    int arow[2], brow[8];
#pragma unroll
    for (int mf = 0; mf < 2; mf++) arow[mf] = (warp_m * 32 + mf * 16 + g) * ASTRIDE;
#pragma unroll
    for (int nf = 0; nf < 8; nf++) brow[nf] = (warp_n * 64 + nf * 8 + g) * ASTRIDE;

    // prologue: fill 2 of 3 stages
    load_tile(0, 0);
    if (KT > 1) load_tile(1, 1);

    for (int kt = 0; kt < KT; kt++) {
        if (kt + 1 < KT) { CP_WAIT1(); } else { CP_WAIT0(); }
        __syncthreads();
        if (kt + 2 < KT) load_tile(kt + 2, (kt + 2) % 3);

        const float* As = dsm + (kt % 3) * STAGE_F;
        const float* Bs = As + AF;
#pragma unroll
        for (int ks8 = 0; ks8 < 4; ks8++) {
            const int k0 = ks8 * 8 + t;
            uint32_t a[2][4], b[8][2];
#pragma unroll
            for (int mf = 0; mf < 2; mf++) {
                a[mf][0] = f2tf(As[arow[mf] + k0]);
                a[mf][1] = f2tf(As[arow[mf] + 8 * ASTRIDE + k0]);
                a[mf][2] = f2tf(As[arow[mf] + k0 + 4]);
                a[mf][3] = f2tf(As[arow[mf] + 8 * ASTRIDE + k0 + 4]);
            }
#pragma unroll
            for (int nf = 0; nf < 8; nf++) {
                b[nf][0] = f2tf(Bs[brow[nf] + k0]);
                b[nf][1] = f2tf(Bs[brow[nf] + k0 + 4]);
            }
#pragma unroll
            for (int mf = 0; mf < 2; mf++)
#pragma unroll
                for (int nf = 0; nf < 8; nf++)
                    mma8(acc[mf][nf], a[mf], b[nf]);
        }
    }
    __syncthreads();

    // ---- epilogue: stage accumulators to smem ----
    float* sepi   = dsm;
    float* s_mean = dsm + 33280;
    float* s_inv  = dsm + 33408;
    const bool doAct = (MODE != 3) || (blockIdx.y == 0);

#pragma unroll
    for (int mf = 0; mf < 2; mf++) {
        int r0 = warp_m * 32 + mf * 16 + g;
#pragma unroll
        for (int nf = 0; nf < 8; nf++) {
            int c0 = warp_n * 64 + nf * 8 + 2 * t;
            float v0 = acc[mf][nf][0], v1 = acc[mf][nf][1];
            float v2 = acc[mf][nf][2], v3 = acc[mf][nf][3];
            if (EPI == EPI_ELU1 && doAct) {
                v0 = (v0 > 0.f) ? v0 + 1.f : __expf(v0);
                v1 = (v1 > 0.f) ? v1 + 1.f : __expf(v1);
                v2 = (v2 > 0.f) ? v2 + 1.f : __expf(v2);
                v3 = (v3 > 0.f) ? v3 + 1.f : __expf(v3);
            }
            if (EPI == EPI_RELU) {
                v0 = fmaxf(v0, 0.f); v1 = fmaxf(v1, 0.f);
                v2 = fmaxf(v2, 0.f); v3 = fmaxf(v3, 0.f);
            }
            *(float2*)&sepi[r0 * EPISTRIDE + c0]       = make_float2(v0, v1);
            *(float2*)&sepi[(r0 + 8) * EPISTRIDE + c0] = make_float2(v2, v3);
        }
    }
    __syncthreads();

    if ((EPI == EPI_LN || EPI == EPI_LN_RESID) && tid < 128) {
        const float* rowp = sepi + tid * EPISTRIDE;
        float sum = 0.f, ss = 0.f;
#pragma unroll 8
        for (int j = 0; j < 64; j++) {
            float4 v = *(const float4*)&rowp[j * 4];
            sum += v.x + v.y + v.z + v.w;
            ss  += v.x * v.x + v.y * v.y + v.z * v.z + v.w * v.w;
        }
        float mean = sum * (1.f / 256.f);
        float var  = ss * (1.f / 256.f) - mean * mean;
        s_mean[tid] = mean;
        s_inv[tid]  = rsqrtf(var + EPS_LN);
    }
    if (EPI == EPI_LN || EPI == EPI_LN_RESID) __syncthreads();

    // coalesced store (+ LN transform / residual): 8192 float4 / 512 thr
#pragma unroll 4
    for (int p = 0; p < 16; p++) {
        int idx4 = p * 512 + tid;
        int row = idx4 >> 6;
        int c4  = (idx4 & 63) << 2;
        float4 v = *(const float4*)&sepi[row * EPISTRIDE + c4];
        if (EPI == EPI_LN || EPI == EPI_LN_RESID) {
            float m = s_mean[row], iv = s_inv[row];
            float4 gm = *(const float4*)&gamma[c4];
            float4 bt = *(const float4*)&beta[c4];
            v.x = (v.x - m) * iv * gm.x + bt.x;
            v.y = (v.y - m) * iv * gm.y + bt.y;
            v.z = (v.z - m) * iv * gm.z + bt.z;
            v.w = (v.w - m) * iv * gm.w + bt.w;
            if (EPI == EPI_LN_RESID) {
                float4 r = *(const float4*)&resid[(size_t)(mtile + row) * 256 + c4];
                v.x += r.x; v.y += r.y; v.z += r.z; v.w += r.w;
            }
        }
        *(float4*)&Cblk[(size_t)(mtile + row) * Ntot + ncol0 + c4] = v;
    }
}

// ---------------------------------------------------------------------------
// KV = sum_s K^T V, Ksum = sum_s K. grid 64, 256 thr.
// ---------------------------------------------------------------------------
__global__ void kv_kernel(const float* __restrict__ kmat, const float* __restrict__ vmat,
                          float* __restrict__ kv, float* __restrict__ ksum) {
    __shared__ float Ks[128][32];
    __shared__ float Vs[128][32];
    int bh = blockIdx.x, b = bh >> 3, h = bh & 7;
    int tid = threadIdx.x;
    int d = tid & 31, vg = tid >> 5;
    float acc0 = 0.f, acc1 = 0.f, acc2 = 0.f, acc3 = 0.f, ka = 0.f;

    for (int ch = 0; ch < 2; ch++) {
        int sl = tid >> 3, c4 = tid & 7;
#pragma unroll
        for (int ss = 0; ss < 4; ss++) {
            int srow = ch * 128 + ss * 32 + sl;
            size_t base = ((size_t)(b * 256 + srow)) * 256 + h * 32 + c4 * 4;
            *(float4*)&Ks[ss * 32 + sl][c4 * 4] = *(const float4*)&kmat[base];
            *(float4*)&Vs[ss * 32 + sl][c4 * 4] = *(const float4*)&vmat[base];
        }
        __syncthreads();
#pragma unroll 4
        for (int s = 0; s < 128; s++) {
            float kd = Ks[s][d];
            float4 vv = *(float4*)&Vs[s][vg * 4];
            acc0 += kd * vv.x; acc1 += kd * vv.y;
            acc2 += kd * vv.z; acc3 += kd * vv.w;
            if (vg == 0) ka += kd;
        }
        __syncthreads();
    }
    float* kvp = kv + ((size_t)bh * 32 + d) * 32 + vg * 4;
    kvp[0] = acc0; kvp[1] = acc1; kvp[2] = acc2; kvp[3] = acc3;
    if (vg == 0) ksum[bh * 32 + d] = ka;
}

// ---------------------------------------------------------------------------
// msg = z * (Q @ KV), z = 1/(Q.Ksum + eps). grid (256, 8).
// ---------------------------------------------------------------------------
__global__ void attn_apply(const float* __restrict__ qmat, const float* __restrict__ kv,
                           const float* __restrict__ ksum, float* __restrict__ msg) {
    __shared__ float Qs[16 * 256];
    __shared__ float zs[16][8];
    __shared__ float ksums[256];
    int b = blockIdx.y;
    int t0 = blockIdx.x * 16;
    int tid = threadIdx.x;

    const float4* qsrc = (const float4*)(qmat + ((size_t)b * 4096 + t0) * 256);
    float4* qd = (float4*)Qs;
#pragma unroll
    for (int q = 0; q < 4; q++) qd[tid + q * 256] = qsrc[tid + q * 256];
    ksums[tid] = ksum[b * 256 + tid];
    __syncthreads();

    if (tid < 128) {
        int t = tid >> 3, h = tid & 7;
        const float* qrow = Qs + t * 256 + h * 32;
        const float* kr = ksums + h * 32;
        float z = 0.f;
#pragma unroll
        for (int dd = 0; dd < 32; dd++) z += qrow[dd] * kr[dd];
        zs[t][h] = 1.f / (z + EPS_ATT);
    }
    __syncthreads();

    int h = tid >> 5, v = tid & 31;
    float kvr[32];
#pragma unroll
    for (int dd = 0; dd < 32; dd++)
        kvr[dd] = kv[(((size_t)(b * 8 + h)) * 32 + dd) * 32 + v];
#pragma unroll 2
    for (int t = 0; t < 16; t++) {
        const float* qrow = Qs + t * 256 + h * 32;
        float m = 0.f;
#pragma unroll
        for (int dd = 0; dd < 32; dd++) m += qrow[dd] * kvr[dd];
        msg[((size_t)b * 4096 + t0 + t) * 256 + tid] = m * zs[t][h];
    }
}

// ---------------------------------------------------------------------------
// Launch
// ---------------------------------------------------------------------------
extern "C" void kernel_launch(void* const* d_in, const int* in_sizes, int n_in,
                              void* d_out, int out_size) {
    const float* x      = (const float*)d_in[0];
    const float* sr_w   = (const float*)d_in[1];
    const float* sr_b   = (const float*)d_in[2];
    const float* norm_g = (const float*)d_in[3];
    const float* norm_b = (const float*)d_in[4];
    const float* wq     = (const float*)d_in[5];
    const float* wk     = (const float*)d_in[6];
    const float* wv     = (const float*)d_in[7];
    const float* wm     = (const float*)d_in[8];
    const float* w1     = (const float*)d_in[9];
    const float* w2     = (const float*)d_in[10];
    const float* n1g    = (const float*)d_in[11];
    const float* n1b    = (const float*)d_in[12];
    const float* n2g    = (const float*)d_in[13];
    const float* n2b    = (const float*)d_in[14];
    float* out = (float*)d_out;

    float *wsrB, *part, *src, *kmat, *vmat, *kvp, *ksump, *qmat, *msg, *msgn, *hmid;
    cudaGetSymbolAddress((void**)&wsrB, g_wsrB);
    cudaGetSymbolAddress((void**)&part, g_part);
    cudaGetSymbolAddress((void**)&src,  g_src);
    cudaGetSymbolAddress((void**)&kmat, g_kmat);
    cudaGetSymbolAddress((void**)&vmat, g_vmat);
    cudaGetSymbolAddress((void**)&kvp,  g_kv);
    cudaGetSymbolAddress((void**)&ksump,g_ksum);
    cudaGetSymbolAddress((void**)&qmat, g_qmat);
    cudaGetSymbolAddress((void**)&msg,  g_msg);
    cudaGetSymbolAddress((void**)&msgn, g_msgn);
    cudaGetSymbolAddress((void**)&hmid, g_hmid);

    cudaFuncSetAttribute(mma_gemm<EPI_PLAIN, 2>,    cudaFuncAttributeMaxDynamicSharedMemorySize, SMEM_REQ);
    cudaFuncSetAttribute(mma_gemm<EPI_ELU1, 3>,     cudaFuncAttributeMaxDynamicSharedMemorySize, SMEM_REQ);
    cudaFuncSetAttribute(mma_gemm<EPI_ELU1, 0>,     cudaFuncAttributeMaxDynamicSharedMemorySize, SMEM_REQ);
    cudaFuncSetAttribute(mma_gemm<EPI_LN, 0>,       cudaFuncAttributeMaxDynamicSharedMemorySize, SMEM_REQ);
    cudaFuncSetAttribute(mma_gemm<EPI_RELU, 1>,     cudaFuncAttributeMaxDynamicSharedMemorySize, SMEM_REQ);
    cudaFuncSetAttribute(mma_gemm<EPI_LN_RESID, 0>, cudaFuncAttributeMaxDynamicSharedMemorySize, SMEM_REQ);

    // conv weight repack, conv-as-GEMM (split-K=8) + reduce/bias/LN
    repack_srw<<<256, 256>>>(sr_w, wsrB);
    mma_gemm<EPI_PLAIN, 2><<<dim3(16, 8), 512, SMEM_REQ>>>(
        x, nullptr, wsrB, part, 512, 4096, 256, nullptr, nullptr, nullptr, nullptr, nullptr);
    reduce_ln<<<256, 256>>>(part, sr_b, norm_g, norm_b, src);

    // fused k/v projections (M=2048): y=0 -> wk+elu -> kmat, y=1 -> wv -> vmat
    mma_gemm<EPI_ELU1, 3><<<dim3(16, 2), 512, SMEM_REQ>>>(
        src, nullptr, wk, kmat, 256, 256, 256, nullptr, nullptr, nullptr, wv, vmat);

    kv_kernel<<<64, 256>>>(kmat, vmat, kvp, ksump);

    // q projection (M=32768) -> elu+1
    mma_gemm<EPI_ELU1, 0><<<dim3(256, 1), 512, SMEM_REQ>>>(
        x, nullptr, wq, qmat, 256, 256, 256, nullptr, nullptr, nullptr, nullptr, nullptr);

    attn_apply<<<dim3(256, 8), 256>>>(qmat, kvp, ksump, msg);

    // merge projection + LN1
    mma_gemm<EPI_LN, 0><<<dim3(256, 1), 512, SMEM_REQ>>>(
        msg, nullptr, wm, msgn, 256, 256, 256, n1g, n1b, nullptr, nullptr, nullptr);

    // MLP1: concat(x, msgn) @ w1^T -> relu (Ntot=512, 2 column blocks)
    mma_gemm<EPI_RELU, 1><<<dim3(256, 2), 512, SMEM_REQ>>>(
        x, msgn, w1, hmid, 512, 512, 512, nullptr, nullptr, nullptr, nullptr, nullptr);

    // MLP2 + LN2 + residual -> out
    mma_gemm<EPI_LN_RESID, 0><<<dim3(256, 1), 512, SMEM_REQ>>>(
        hmid, nullptr, w2, out, 512, 512, 256, n2g, n2b, x, nullptr, nullptr);
}

// round 6
// speedup vs baseline: 1.0569x; 1.0569x over previous
#include <cuda_runtime.h>
#include <math.h>
#include <stdint.h>

#define EPS_LN  1e-5f
#define EPS_ATT 1e-6f

// ---------------------------------------------------------------------------
// helpers
// ---------------------------------------------------------------------------
__device__ __forceinline__ uint32_t f2tf(float x) {
    uint32_t r;
    asm("cvt.rna.tf32.f32 %0, %1;" : "=r"(r) : "f"(x));
    return r;
}
__device__ __forceinline__ float tf32r(float x) {
    return __uint_as_float(f2tf(x));
}
__device__ __forceinline__ void mma8(float* c, const uint32_t* a, const uint32_t* b) {
    asm volatile(
        "mma.sync.aligned.m16n8k8.row.col.f32.tf32.tf32.f32 "
        "{%0,%1,%2,%3}, {%4,%5,%6,%7}, {%8,%9}, {%0,%1,%2,%3};"
        : "+f"(c[0]), "+f"(c[1]), "+f"(c[2]), "+f"(c[3])
        : "r"(a[0]), "r"(a[1]), "r"(a[2]), "r"(a[3]), "r"(b[0]), "r"(b[1]));
}

// ---------------------------------------------------------------------------
// Scratch
// ---------------------------------------------------------------------------
__device__ float g_wsrB[256 * 4096];        // conv weight [o][k], tf32-rounded
__device__ float g_wqr [256 * 256];
__device__ float g_wkr [256 * 256];
__device__ float g_wvr [256 * 256];
__device__ float g_wmr [256 * 256];
__device__ float g_w1r [512 * 512];
__device__ float g_w2r [256 * 512];
__device__ float g_part[8 * 2048 * 256];    // conv split-K partials
__device__ float g_src [2048 * 256];
__device__ float g_kmat[2048 * 256];
__device__ float g_vmat[2048 * 256];
__device__ float g_kv  [64 * 32 * 32];
__device__ float g_ksum[64 * 32];
__device__ float g_qmat[8 * 4096 * 256];
__device__ float g_msg [8 * 4096 * 256];
__device__ float g_msgn[8 * 4096 * 256];
__device__ float g_hmid[8 * 4096 * 512];

// sr_w OIHW [o][i][4][4] -> wsrB[o*4096 + rr*256 + i], tf32-rounded
__global__ void repack_srw(const float* __restrict__ w, float* __restrict__ wb) {
    int idx = blockIdx.x * blockDim.x + threadIdx.x;   // 65536
    int o = idx >> 8, i = idx & 255;
    const float* p = w + ((size_t)(o * 256 + i)) * 16;
#pragma unroll
    for (int rr = 0; rr < 16; rr++)
        wb[(size_t)o * 4096 + rr * 256 + i] = tf32r(p[rr]);
}

// Round all 6 linear weights to tf32 in one launch. 2560 blocks x 256.
__global__ void round_weights(const float* __restrict__ wq, const float* __restrict__ wk,
                              const float* __restrict__ wv, const float* __restrict__ wm,
                              const float* __restrict__ w1, const float* __restrict__ w2,
                              float* __restrict__ oq, float* __restrict__ ok,
                              float* __restrict__ ov, float* __restrict__ om,
                              float* __restrict__ o1, float* __restrict__ o2) {
    int bid = blockIdx.x;
    const float* src; float* dst; int base;
    if      (bid < 256)  { src = wq; dst = oq; base = 0; }
    else if (bid < 512)  { src = wk; dst = ok; base = 256; }
    else if (bid < 768)  { src = wv; dst = ov; base = 512; }
    else if (bid < 1024) { src = wm; dst = om; base = 768; }
    else if (bid < 2048) { src = w1; dst = o1; base = 1024; }
    else                 { src = w2; dst = o2; base = 2048; }
    int idx = (bid - base) * 256 + threadIdx.x;
    dst[idx] = tf32r(src[idx]);
}

// ---------------------------------------------------------------------------
// Split-K reduce + bias + LayerNorm -> src. grid 256, 256 thr.
// ---------------------------------------------------------------------------
__global__ void reduce_ln(const float* __restrict__ part, const float* __restrict__ bias,
                          const float* __restrict__ g, const float* __restrict__ bb,
                          float* __restrict__ out) {
    int lane = threadIdx.x & 31, w = threadIdx.x >> 5;
    int row = blockIdx.x * 8 + w;
    float v[8];
#pragma unroll
    for (int j = 0; j < 8; j++) {
        int c = lane + j * 32;
        float s = 0.f;
#pragma unroll
        for (int ks = 0; ks < 8; ks++)
            s += part[((size_t)ks * 2048 + row) * 256 + c];
        v[j] = s + bias[c];
    }
    float sum = 0.f;
#pragma unroll
    for (int j = 0; j < 8; j++) sum += v[j];
#pragma unroll
    for (int o = 16; o; o >>= 1) sum += __shfl_xor_sync(0xffffffffu, sum, o);
    float mean = sum * (1.f / 256.f);
    float ss = 0.f;
#pragma unroll
    for (int j = 0; j < 8; j++) { float d = v[j] - mean; ss += d * d; }
#pragma unroll
    for (int o = 16; o; o >>= 1) ss += __shfl_xor_sync(0xffffffffu, ss, o);
    float inv = rsqrtf(ss * (1.f / 256.f) + EPS_LN);
#pragma unroll
    for (int j = 0; j < 8; j++) {
        int c = lane + j * 32;
        out[(size_t)row * 256 + c] = (v[j] - mean) * inv * g[c] + bb[c];
    }
}

// ---------------------------------------------------------------------------
// tf32 mma.sync GEMM. BM=128, BN=256, BK=32. 256 threads, 8 warps (2x4),
// warp tile 64x64. LDG.128->reg->STS.128 double-buffer (no cp.async).
// B pre-rounded to tf32 (raw-bit fragments); A converted in-loop.
// MODE: 0=plain, 1=concat(A0,A1), 2=conv gather + split-K, 3=fused k/v
// EPI: 0 plain, 1 elu+1, 2 relu, 3 LN, 4 LN+resid
// ---------------------------------------------------------------------------
#define EPI_PLAIN    0
#define EPI_ELU1     1
#define EPI_RELU     2
#define EPI_LN       3
#define EPI_LN_RESID 4

#define ASTRIDE   36
#define STAGE_F   13824            // (128+256)*36 floats
#define AF        4608             // 128*36
#define EPISTRIDE 260
#define SMEM_REQ  134144           // max(2*13824*4, (128*260+256)*4)

template <int EPI, int MODE>
__global__ __launch_bounds__(256, 1)
void mma_gemm(const float* __restrict__ A0, const float* __restrict__ A1,
              const float* __restrict__ Bw, float* __restrict__ C,
              int Kloc, int KB, int Ntot,
              const float* __restrict__ gamma, const float* __restrict__ beta,
              const float* __restrict__ resid,
              const float* __restrict__ Bw2, float* __restrict__ C2) {
    extern __shared__ float dsm[];

    const int tid  = threadIdx.x;
    const int lane = tid & 31;
    const int wid  = tid >> 5;          // 0..7
    const int g    = lane >> 2;         // 0..7
    const int t    = lane & 3;          // 0..3
    const int warp_m = wid & 1;         // 2 -> 64 rows
    const int warp_n = wid >> 1;        // 4 -> 64 cols

    const int mtile = blockIdx.x * 128;
    int ncol0, kstart;
    float* Cblk = C;
    const float* Bsrc = Bw;
    if (MODE == 2) { ncol0 = 0; kstart = blockIdx.y * 512; Cblk = C + (size_t)blockIdx.y * 2048 * 256; }
    else if (MODE == 3) { ncol0 = 0; kstart = 0; if (blockIdx.y) { Bsrc = Bw2; Cblk = C2; } }
    else { ncol0 = blockIdx.y * 256; kstart = 0; }
    const int KT = Kloc / 32;

    float acc[4][8][4];
#pragma unroll
    for (int i = 0; i < 4; i++)
#pragma unroll
        for (int j = 0; j < 8; j++)
#pragma unroll
            for (int q = 0; q < 4; q++) acc[i][j][q] = 0.f;

    float4 rA[4], rB[8];

    auto ldg_tile = [&](int kt) {
        const int kbase = kstart + kt * 32;
#pragma unroll
        for (int p = 0; p < 4; p++) {
            int idx = p * 256 + tid;
            int m = idx >> 3, c = idx & 7;
            int kk = kbase + c * 4;
            const float* gp;
            if (MODE == 2) {
                int mg = mtile + m;
                int b = mg >> 8, s5 = mg & 255;
                int rr = kk >> 8, i = kk & 255;
                int n = (((s5 >> 4) * 4 + (rr >> 2)) << 6) + ((s5 & 15) << 2) + (rr & 3);
                gp = A0 + (((size_t)b << 12) + n) * 256 + i;
            } else if (MODE == 1) {
                gp = (kk < 256) ? (A0 + (size_t)(mtile + m) * 256 + kk)
                                : (A1 + (size_t)(mtile + m) * 256 + (kk - 256));
            } else {
                gp = A0 + (size_t)(mtile + m) * Kloc + kk;
            }
            rA[p] = *(const float4*)gp;
        }
#pragma unroll
        for (int p = 0; p < 8; p++) {
            int idx = p * 256 + tid;
            int n = idx >> 3, c = idx & 7;
            rB[p] = *(const float4*)(Bsrc + (size_t)(ncol0 + n) * KB + kbase + c * 4);
        }
    };
    auto sts_tile = [&](int s) {
        float* sA = dsm + s * STAGE_F;
        float* sB = sA + AF;
#pragma unroll
        for (int p = 0; p < 4; p++) {
            int idx = p * 256 + tid;
            int m = idx >> 3, c = idx & 7;
            *(float4*)&sA[m * ASTRIDE + c * 4] = rA[p];
        }
#pragma unroll
        for (int p = 0; p < 8; p++) {
            int idx = p * 256 + tid;
            int n = idx >> 3, c = idx & 7;
            *(float4*)&sB[n * ASTRIDE + c * 4] = rB[p];
        }
    };

    int arow[4], brow[8];
#pragma unroll
    for (int mf = 0; mf < 4; mf++) arow[mf] = (warp_m * 64 + mf * 16 + g) * ASTRIDE;
#pragma unroll
    for (int nf = 0; nf < 8; nf++) brow[nf] = (warp_n * 64 + nf * 8 + g) * ASTRIDE;

    // prologue: stage 0 into smem, stage 1 into regs
    ldg_tile(0);
    sts_tile(0);
    if (KT > 1) ldg_tile(1);
    __syncthreads();

    for (int kt = 0; kt < KT; kt++) {
        if (kt + 1 < KT) {
            sts_tile((kt + 1) & 1);       // buffer freed by trailing sync of kt-1
            if (kt + 2 < KT) ldg_tile(kt + 2);
            __syncthreads();              // make STS visible
        }
        const float* As = dsm + (kt & 1) * STAGE_F;
        const float* Bs = As + AF;
#pragma unroll
        for (int ks8 = 0; ks8 < 4; ks8++) {
            const int k0 = ks8 * 8 + t;
            uint32_t a[4][4], b[8][2];
#pragma unroll
            for (int mf = 0; mf < 4; mf++) {
                a[mf][0] = f2tf(As[arow[mf] + k0]);
                a[mf][1] = f2tf(As[arow[mf] + 8 * ASTRIDE + k0]);
                a[mf][2] = f2tf(As[arow[mf] + k0 + 4]);
                a[mf][3] = f2tf(As[arow[mf] + 8 * ASTRIDE + k0 + 4]);
            }
#pragma unroll
            for (int nf = 0; nf < 8; nf++) {
                b[nf][0] = __float_as_uint(Bs[brow[nf] + k0]);      // pre-rounded
                b[nf][1] = __float_as_uint(Bs[brow[nf] + k0 + 4]);
            }
#pragma unroll
            for (int mf = 0; mf < 4; mf++)
#pragma unroll
                for (int nf = 0; nf < 8; nf++)
                    mma8(acc[mf][nf], a[mf], b[nf]);
        }
        __syncthreads();                  // done reading smem[kt&1]
    }

    // ---- epilogue: stage accumulators to smem ----
    float* sepi   = dsm;
    float* s_mean = dsm + 33280;
    float* s_inv  = dsm + 33408;
    const bool doAct = (MODE != 3) || (blockIdx.y == 0);

#pragma unroll
    for (int mf = 0; mf < 4; mf++) {
        int r0 = warp_m * 64 + mf * 16 + g;
#pragma unroll
        for (int nf = 0; nf < 8; nf++) {
            int c0 = warp_n * 64 + nf * 8 + 2 * t;
            float v0 = acc[mf][nf][0], v1 = acc[mf][nf][1];
            float v2 = acc[mf][nf][2], v3 = acc[mf][nf][3];
            if (EPI == EPI_ELU1 && doAct) {
                v0 = (v0 > 0.f) ? v0 + 1.f : __expf(v0);
                v1 = (v1 > 0.f) ? v1 + 1.f : __expf(v1);
                v2 = (v2 > 0.f) ? v2 + 1.f : __expf(v2);
                v3 = (v3 > 0.f) ? v3 + 1.f : __expf(v3);
            }
            if (EPI == EPI_RELU) {
                v0 = fmaxf(v0, 0.f); v1 = fmaxf(v1, 0.f);
                v2 = fmaxf(v2, 0.f); v3 = fmaxf(v3, 0.f);
            }
            *(float2*)&sepi[r0 * EPISTRIDE + c0]       = make_float2(v0, v1);
            *(float2*)&sepi[(r0 + 8) * EPISTRIDE + c0] = make_float2(v2, v3);
        }
    }
    __syncthreads();

    if ((EPI == EPI_LN || EPI == EPI_LN_RESID) && tid < 128) {
        const float* rowp = sepi + tid * EPISTRIDE;
        float sum = 0.f, ss = 0.f;
#pragma unroll 8
        for (int j = 0; j < 64; j++) {
            float4 v = *(const float4*)&rowp[j * 4];
            sum += v.x + v.y + v.z + v.w;
            ss  += v.x * v.x + v.y * v.y + v.z * v.z + v.w * v.w;
        }
        float mean = sum * (1.f / 256.f);
        float var  = ss * (1.f / 256.f) - mean * mean;
        s_mean[tid] = mean;
        s_inv[tid]  = rsqrtf(var + EPS_LN);
    }
    if (EPI == EPI_LN || EPI == EPI_LN_RESID) __syncthreads();

#pragma unroll 4
    for (int p = 0; p < 32; p++) {
        int idx4 = p * 256 + tid;
        int row = idx4 >> 6;
        int c4  = (idx4 & 63) << 2;
        float4 v = *(const float4*)&sepi[row * EPISTRIDE + c4];
        if (EPI == EPI_LN || EPI == EPI_LN_RESID) {
            float m = s_mean[row], iv = s_inv[row];
            float4 gm = *(const float4*)&gamma[c4];
            float4 bt = *(const float4*)&beta[c4];
            v.x = (v.x - m) * iv * gm.x + bt.x;
            v.y = (v.y - m) * iv * gm.y + bt.y;
            v.z = (v.z - m) * iv * gm.z + bt.z;
            v.w = (v.w - m) * iv * gm.w + bt.w;
            if (EPI == EPI_LN_RESID) {
                float4 r = *(const float4*)&resid[(size_t)(mtile + row) * 256 + c4];
                v.x += r.x; v.y += r.y; v.z += r.z; v.w += r.w;
            }
        }
        *(float4*)&Cblk[(size_t)(mtile + row) * Ntot + ncol0 + c4] = v;
    }
}

// ---------------------------------------------------------------------------
// KV = sum_s K^T V, Ksum = sum_s K. grid 64, 256 thr.
// ---------------------------------------------------------------------------
__global__ void kv_kernel(const float* __restrict__ kmat, const float* __restrict__ vmat,
                          float* __restrict__ kv, float* __restrict__ ksum) {
    __shared__ float Ks[128][32];
    __shared__ float Vs[128][32];
    int bh = blockIdx.x, b = bh >> 3, h = bh & 7;
    int tid = threadIdx.x;
    int d = tid & 31, vg = tid >> 5;
    float acc0 = 0.f, acc1 = 0.f, acc2 = 0.f, acc3 = 0.f, ka = 0.f;

    for (int ch = 0; ch < 2; ch++) {
        int sl = tid >> 3, c4 = tid & 7;
#pragma unroll
        for (int ss = 0; ss < 4; ss++) {
            int srow = ch * 128 + ss * 32 + sl;
            size_t base = ((size_t)(b * 256 + srow)) * 256 + h * 32 + c4 * 4;
            *(float4*)&Ks[ss * 32 + sl][c4 * 4] = *(const float4*)&kmat[base];
            *(float4*)&Vs[ss * 32 + sl][c4 * 4] = *(const float4*)&vmat[base];
        }
        __syncthreads();
#pragma unroll 4
        for (int s = 0; s < 128; s++) {
            float kd = Ks[s][d];
            float4 vv = *(float4*)&Vs[s][vg * 4];
            acc0 += kd * vv.x; acc1 += kd * vv.y;
            acc2 += kd * vv.z; acc3 += kd * vv.w;
            if (vg == 0) ka += kd;
        }
        __syncthreads();
    }
    float* kvp = kv + ((size_t)bh * 32 + d) * 32 + vg * 4;
    kvp[0] = acc0; kvp[1] = acc1; kvp[2] = acc2; kvp[3] = acc3;
    if (vg == 0) ksum[bh * 32 + d] = ka;
}

// ---------------------------------------------------------------------------
// msg = z * (Q @ KV), z = 1/(Q.Ksum + eps). grid (256, 8).
// ---------------------------------------------------------------------------
__global__ void attn_apply(const float* __restrict__ qmat, const float* __restrict__ kv,
                           const float* __restrict__ ksum, float* __restrict__ msg) {
    __shared__ float Qs[16 * 256];
    __shared__ float zs[16][8];
    __shared__ float ksums[256];
    int b = blockIdx.y;
    int t0 = blockIdx.x * 16;
    int tid = threadIdx.x;

    const float4* qsrc = (const float4*)(qmat + ((size_t)b * 4096 + t0) * 256);
    float4* qd = (float4*)Qs;
#pragma unroll
    for (int q = 0; q < 4; q++) qd[tid + q * 256] = qsrc[tid + q * 256];
    ksums[tid] = ksum[b * 256 + tid];
    __syncthreads();

    if (tid < 128) {
        int t = tid >> 3, h = tid & 7;
        const float* qrow = Qs + t * 256 + h * 32;
        const float* kr = ksums + h * 32;
        float z = 0.f;
#pragma unroll
        for (int dd = 0; dd < 32; dd++) z += qrow[dd] * kr[dd];
        zs[t][h] = 1.f / (z + EPS_ATT);
    }
    __syncthreads();

    int h = tid >> 5, v = tid & 31;
    float kvr[32];
#pragma unroll
    for (int dd = 0; dd < 32; dd++)
        kvr[dd] = kv[(((size_t)(b * 8 + h)) * 32 + dd) * 32 + v];
#pragma unroll 2
    for (int t = 0; t < 16; t++) {
        const float* qrow = Qs + t * 256 + h * 32;
        float m = 0.f;
#pragma unroll
        for (int dd = 0; dd < 32; dd++) m += qrow[dd] * kvr[dd];
        msg[((size_t)b * 4096 + t0 + t) * 256 + tid] = m * zs[t][h];
    }
}

// ---------------------------------------------------------------------------
// Launch
// ---------------------------------------------------------------------------
extern "C" void kernel_launch(void* const* d_in, const int* in_sizes, int n_in,
                              void* d_out, int out_size) {
    const float* x      = (const float*)d_in[0];
    const float* sr_w   = (const float*)d_in[1];
    const float* sr_b   = (const float*)d_in[2];
    const float* norm_g = (const float*)d_in[3];
    const float* norm_b = (const float*)d_in[4];
    const float* wq     = (const float*)d_in[5];
    const float* wk     = (const float*)d_in[6];
    const float* wv     = (const float*)d_in[7];
    const float* wm     = (const float*)d_in[8];
    const float* w1     = (const float*)d_in[9];
    const float* w2     = (const float*)d_in[10];
    const float* n1g    = (const float*)d_in[11];
    const float* n1b    = (const float*)d_in[12];
    const float* n2g    = (const float*)d_in[13];
    const float* n2b    = (const float*)d_in[14];
    float* out = (float*)d_out;

    float *wsrB, *wqr, *wkr, *wvr, *wmr, *w1r, *w2r;
    float *part, *src, *kmat, *vmat, *kvp, *ksump, *qmat, *msg, *msgn, *hmid;
    cudaGetSymbolAddress((void**)&wsrB, g_wsrB);
    cudaGetSymbolAddress((void**)&wqr,  g_wqr);
    cudaGetSymbolAddress((void**)&wkr,  g_wkr);
    cudaGetSymbolAddress((void**)&wvr,  g_wvr);
    cudaGetSymbolAddress((void**)&wmr,  g_wmr);
    cudaGetSymbolAddress((void**)&w1r,  g_w1r);
    cudaGetSymbolAddress((void**)&w2r,  g_w2r);
    cudaGetSymbolAddress((void**)&part, g_part);
    cudaGetSymbolAddress((void**)&src,  g_src);
    cudaGetSymbolAddress((void**)&kmat, g_kmat);
    cudaGetSymbolAddress((void**)&vmat, g_vmat);
    cudaGetSymbolAddress((void**)&kvp,  g_kv);
    cudaGetSymbolAddress((void**)&ksump,g_ksum);
    cudaGetSymbolAddress((void**)&qmat, g_qmat);
    cudaGetSymbolAddress((void**)&msg,  g_msg);
    cudaGetSymbolAddress((void**)&msgn, g_msgn);
    cudaGetSymbolAddress((void**)&hmid, g_hmid);

    cudaFuncSetAttribute(mma_gemm<EPI_PLAIN, 2>,    cudaFuncAttributeMaxDynamicSharedMemorySize, SMEM_REQ);
    cudaFuncSetAttribute(mma_gemm<EPI_ELU1, 3>,     cudaFuncAttributeMaxDynamicSharedMemorySize, SMEM_REQ);
    cudaFuncSetAttribute(mma_gemm<EPI_ELU1, 0>,     cudaFuncAttributeMaxDynamicSharedMemorySize, SMEM_REQ);
    cudaFuncSetAttribute(mma_gemm<EPI_LN, 0>,       cudaFuncAttributeMaxDynamicSharedMemorySize, SMEM_REQ);
    cudaFuncSetAttribute(mma_gemm<EPI_RELU, 1>,     cudaFuncAttributeMaxDynamicSharedMemorySize, SMEM_REQ);
    cudaFuncSetAttribute(mma_gemm<EPI_LN_RESID, 0>, cudaFuncAttributeMaxDynamicSharedMemorySize, SMEM_REQ);

    // weight prep: conv repack + tf32 rounding of all linear weights
    repack_srw<<<256, 256>>>(sr_w, wsrB);
    round_weights<<<2560, 256>>>(wq, wk, wv, wm, w1, w2, wqr, wkr, wvr, wmr, w1r, w2r);

    // conv-as-GEMM (split-K=8) + reduce/bias/LN
    mma_gemm<EPI_PLAIN, 2><<<dim3(16, 8), 256, SMEM_REQ>>>(
        x, nullptr, wsrB, part, 512, 4096, 256, nullptr, nullptr, nullptr, nullptr, nullptr);
    reduce_ln<<<256, 256>>>(part, sr_b, norm_g, norm_b, src);

    // fused k/v projections (M=2048)
    mma_gemm<EPI_ELU1, 3><<<dim3(16, 2), 256, SMEM_REQ>>>(
        src, nullptr, wkr, kmat, 256, 256, 256, nullptr, nullptr, nullptr, wvr, vmat);

    kv_kernel<<<64, 256>>>(kmat, vmat, kvp, ksump);

    // q projection (M=32768) -> elu+1
    mma_gemm<EPI_ELU1, 0><<<dim3(256, 1), 256, SMEM_REQ>>>(
        x, nullptr, wqr, qmat, 256, 256, 256, nullptr, nullptr, nullptr, nullptr, nullptr);

    attn_apply<<<dim3(256, 8), 256>>>(qmat, kvp, ksump, msg);

    // merge projection + LN1
    mma_gemm<EPI_LN, 0><<<dim3(256, 1), 256, SMEM_REQ>>>(
        msg, nullptr, wmr, msgn, 256, 256, 256, n1g, n1b, nullptr, nullptr, nullptr);

    // MLP1: concat(x, msgn) @ w1^T -> relu (Ntot=512, 2 column blocks)
    mma_gemm<EPI_RELU, 1><<<dim3(256, 2), 256, SMEM_REQ>>>(
        x, msgn, w1r, hmid, 512, 512, 512, nullptr, nullptr, nullptr, nullptr, nullptr);

    // MLP2 + LN2 + residual -> out
    mma_gemm<EPI_LN_RESID, 0><<<dim3(256, 1), 256, SMEM_REQ>>>(
        hmid, nullptr, w2r, out, 512, 512, 256, n2g, n2b, x, nullptr, nullptr);
}

// round 8
// speedup vs baseline: 1.0808x; 1.0227x over previous
#include <cuda_runtime.h>
#include <math.h>
#include <stdint.h>

#define EPS_LN  1e-5f
#define EPS_ATT 1e-6f

// ---------------------------------------------------------------------------
// helpers
// ---------------------------------------------------------------------------
__device__ __forceinline__ uint32_t f2tf(float x) {
    uint32_t r;
    asm("cvt.rna.tf32.f32 %0, %1;" : "=r"(r) : "f"(x));
    return r;
}
__device__ __forceinline__ float tf32r(float x) {
    return __uint_as_float(f2tf(x));
}
__device__ __forceinline__ void mma8(float* c, const uint32_t* a, const uint32_t* b) {
    asm volatile(
        "mma.sync.aligned.m16n8k8.row.col.f32.tf32.tf32.f32 "
        "{%0,%1,%2,%3}, {%4,%5,%6,%7}, {%8,%9}, {%0,%1,%2,%3};"
        : "+f"(c[0]), "+f"(c[1]), "+f"(c[2]), "+f"(c[3])
        : "r"(a[0]), "r"(a[1]), "r"(a[2]), "r"(a[3]), "r"(b[0]), "r"(b[1]));
}

// ---------------------------------------------------------------------------
// Scratch
// ---------------------------------------------------------------------------
__device__ float g_wsrB[256 * 4096];        // conv weight [o][k], tf32-rounded
__device__ float g_wqr [256 * 256];
__device__ float g_wkr [256 * 256];
__device__ float g_wvr [256 * 256];
__device__ float g_wmr [256 * 256];
__device__ float g_w1r [512 * 512];
__device__ float g_w2r [256 * 512];
__device__ float g_part[8 * 2048 * 256];    // conv split-K partials
__device__ float g_src [2048 * 256];
__device__ float g_kmat[2048 * 256];
__device__ float g_vmat[2048 * 256];
__device__ float g_kv  [64 * 32 * 32];
__device__ float g_ksum[64 * 32];
__device__ float g_qmat[8 * 4096 * 256];
__device__ float g_msg [8 * 4096 * 256];
__device__ float g_msgn[8 * 4096 * 256];
__device__ float g_hmid[8 * 4096 * 512];

// sr_w OIHW [o][i][4][4] -> wsrB[o*4096 + rr*256 + i], tf32-rounded
__global__ void repack_srw(const float* __restrict__ w, float* __restrict__ wb) {
    int idx = blockIdx.x * blockDim.x + threadIdx.x;   // 65536
    int o = idx >> 8, i = idx & 255;
    const float* p = w + ((size_t)(o * 256 + i)) * 16;
#pragma unroll
    for (int rr = 0; rr < 16; rr++)
        wb[(size_t)o * 4096 + rr * 256 + i] = tf32r(p[rr]);
}

// Round all 6 linear weights to tf32 in one launch. 2560 blocks x 256.
__global__ void round_weights(const float* __restrict__ wq, const float* __restrict__ wk,
                              const float* __restrict__ wv, const float* __restrict__ wm,
                              const float* __restrict__ w1, const float* __restrict__ w2,
                              float* __restrict__ oq, float* __restrict__ ok,
                              float* __restrict__ ov, float* __restrict__ om,
                              float* __restrict__ o1, float* __restrict__ o2) {
    int bid = blockIdx.x;
    const float* src; float* dst; int base;
    if      (bid < 256)  { src = wq; dst = oq; base = 0; }
    else if (bid < 512)  { src = wk; dst = ok; base = 256; }
    else if (bid < 768)  { src = wv; dst = ov; base = 512; }
    else if (bid < 1024) { src = wm; dst = om; base = 768; }
    else if (bid < 2048) { src = w1; dst = o1; base = 1024; }
    else                 { src = w2; dst = o2; base = 2048; }
    int idx = (bid - base) * 256 + threadIdx.x;
    dst[idx] = tf32r(src[idx]);
}

// ---------------------------------------------------------------------------
// Split-K reduce + bias + LayerNorm -> src. grid 256, 256 thr.
// ---------------------------------------------------------------------------
__global__ void reduce_ln(const float* __restrict__ part, const float* __restrict__ bias,
                          const float* __restrict__ g, const float* __restrict__ bb,
                          float* __restrict__ out) {
    int lane = threadIdx.x & 31, w = threadIdx.x >> 5;
    int row = blockIdx.x * 8 + w;
    float v[8];
#pragma unroll
    for (int j = 0; j < 8; j++) {
        int c = lane + j * 32;
        float s = 0.f;
#pragma unroll
        for (int ks = 0; ks < 8; ks++)
            s += part[((size_t)ks * 2048 + row) * 256 + c];
        v[j] = s + bias[c];
    }
    float sum = 0.f;
#pragma unroll
    for (int j = 0; j < 8; j++) sum += v[j];
#pragma unroll
    for (int o = 16; o; o >>= 1) sum += __shfl_xor_sync(0xffffffffu, sum, o);
    float mean = sum * (1.f / 256.f);
    float ss = 0.f;
#pragma unroll
    for (int j = 0; j < 8; j++) { float d = v[j] - mean; ss += d * d; }
#pragma unroll
    for (int o = 16; o; o >>= 1) ss += __shfl_xor_sync(0xffffffffu, ss, o);
    float inv = rsqrtf(ss * (1.f / 256.f) + EPS_LN);
#pragma unroll
    for (int j = 0; j < 8; j++) {
        int c = lane + j * 32;
        out[(size_t)row * 256 + c] = (v[j] - mean) * inv * g[c] + bb[c];
    }
}

// ---------------------------------------------------------------------------
// tf32 mma.sync GEMM. BM=128, BN=NB (128 or 256), BK=32, 256 threads.
// NB=128: warp tile 32x64 (4x2 warps), 2 CTAs/SM (cross-CTA latency overlap).
// NB=256: warp tile 64x64 (2x4 warps), 1 CTA/SM (needed for row-wide LN).
// LDG.128->reg->STS.128 double-buffer; B pre-rounded tf32.
// MODE: 0=plain, 1=concat(A0,A1), 2=conv gather + split-K(z), 3=fused k/v(z)
// EPI: 0 plain, 1 elu+1, 2 relu, 3 LN, 4 LN+resid
// ---------------------------------------------------------------------------
#define EPI_PLAIN    0
#define EPI_ELU1     1
#define EPI_RELU     2
#define EPI_LN       3
#define EPI_LN_RESID 4

#define ASTRIDE 36
#define AF      4608               // 128*36 floats (A tile)

__host__ __device__ constexpr int stage_floats(int NB) { return (128 + NB) * ASTRIDE; }
__host__ __device__ constexpr int smem_req(int NB) {
    int mainloop = 2 * stage_floats(NB) * 4;
    int epi = (128 * (NB + 4) + 256) * 4;
    return mainloop > epi ? mainloop : epi;
}

template <int EPI, int MODE, int NB>
__global__ __launch_bounds__(256, (NB == 128 ? 2 : 1))
void mma_gemm(const float* __restrict__ A0, const float* __restrict__ A1,
              const float* __restrict__ Bw, float* __restrict__ C,
              int Kloc, int KB, int Ntot,
              const float* __restrict__ gamma, const float* __restrict__ beta,
              const float* __restrict__ resid,
              const float* __restrict__ Bw2, float* __restrict__ C2) {
    extern __shared__ float dsm[];

    constexpr int WM  = (NB == 256) ? 2 : 4;       // warps along M
    constexpr int MF  = 128 / WM / 16;             // 16-row frags per warp
    constexpr int MROWS = 128 / WM;                // rows per warp
    constexpr int NBF4  = NB / 32;                 // B float4 loads per thread
    constexpr int STAGE = stage_floats(NB);
    constexpr int EPIST = NB + 4;

    const int tid  = threadIdx.x;
    const int lane = tid & 31;
    const int wid  = tid >> 5;
    const int g    = lane >> 2;
    const int t    = lane & 3;
    const int warp_m = wid % WM;
    const int warp_n = wid / WM;

    const int mtile = blockIdx.x * 128;
    int ncol0 = blockIdx.y * NB, kstart = 0;
    float* Cblk = C;
    const float* Bsrc = Bw;
    if (MODE == 2) { kstart = blockIdx.z * 512; Cblk = C + (size_t)blockIdx.z * 2048 * 256; }
    if (MODE == 3) { if (blockIdx.z) { Bsrc = Bw2; Cblk = C2; } }
    const int KT = Kloc / 32;

    float acc[MF][8][4];
#pragma unroll
    for (int i = 0; i < MF; i++)
#pragma unroll
        for (int j = 0; j < 8; j++)
#pragma unroll
            for (int q = 0; q < 4; q++) acc[i][j][q] = 0.f;

    float4 rA[4], rB[NBF4];

    auto ldg_tile = [&](int kt) {
        const int kbase = kstart + kt * 32;
#pragma unroll
        for (int p = 0; p < 4; p++) {
            int idx = p * 256 + tid;
            int m = idx >> 3, c = idx & 7;
            int kk = kbase + c * 4;
            const float* gp;
            if (MODE == 2) {
                int mg = mtile + m;
                int b = mg >> 8, s5 = mg & 255;
                int rr = kk >> 8, i = kk & 255;
                int n = (((s5 >> 4) * 4 + (rr >> 2)) << 6) + ((s5 & 15) << 2) + (rr & 3);
                gp = A0 + (((size_t)b << 12) + n) * 256 + i;
            } else if (MODE == 1) {
                gp = (kk < 256) ? (A0 + (size_t)(mtile + m) * 256 + kk)
                                : (A1 + (size_t)(mtile + m) * 256 + (kk - 256));
            } else {
                gp = A0 + (size_t)(mtile + m) * Kloc + kk;
            }
            rA[p] = *(const float4*)gp;
        }
#pragma unroll
        for (int p = 0; p < NBF4; p++) {
            int idx = p * 256 + tid;
            int n = idx >> 3, c = idx & 7;
            rB[p] = *(const float4*)(Bsrc + (size_t)(ncol0 + n) * KB + kbase + c * 4);
        }
    };
    auto sts_tile = [&](int s) {
        float* sA = dsm + s * STAGE;
        float* sB = sA + AF;
#pragma unroll
        for (int p = 0; p < 4; p++) {
            int idx = p * 256 + tid;
            int m = idx >> 3, c = idx & 7;
            *(float4*)&sA[m * ASTRIDE + c * 4] = rA[p];
        }
#pragma unroll
        for (int p = 0; p < NBF4; p++) {
            int idx = p * 256 + tid;
            int n = idx >> 3, c = idx & 7;
            *(float4*)&sB[n * ASTRIDE + c * 4] = rB[p];
        }
    };

    int arow[MF], brow[8];
#pragma unroll
    for (int mf = 0; mf < MF; mf++) arow[mf] = (warp_m * MROWS + mf * 16 + g) * ASTRIDE;
#pragma unroll
    for (int nf = 0; nf < 8; nf++) brow[nf] = (warp_n * 64 + nf * 8 + g) * ASTRIDE;

    // prologue: stage 0 into smem, stage 1 into regs
    ldg_tile(0);
    sts_tile(0);
    if (KT > 1) ldg_tile(1);
    __syncthreads();

    for (int kt = 0; kt < KT; kt++) {
        if (kt + 1 < KT) {
            sts_tile((kt + 1) & 1);
            if (kt + 2 < KT) ldg_tile(kt + 2);
            __syncthreads();
        }
        const float* As = dsm + (kt & 1) * STAGE;
        const float* Bs = As + AF;
#pragma unroll
        for (int ks8 = 0; ks8 < 4; ks8++) {
            const int k0 = ks8 * 8 + t;
            uint32_t a[MF][4], b[8][2];
#pragma unroll
            for (int mf = 0; mf < MF; mf++) {
                a[mf][0] = f2tf(As[arow[mf] + k0]);
                a[mf][1] = f2tf(As[arow[mf] + 8 * ASTRIDE + k0]);
                a[mf][2] = f2tf(As[arow[mf] + k0 + 4]);
                a[mf][3] = f2tf(As[arow[mf] + 8 * ASTRIDE + k0 + 4]);
            }
#pragma unroll
            for (int nf = 0; nf < 8; nf++) {
                b[nf][0] = __float_as_uint(Bs[brow[nf] + k0]);
                b[nf][1] = __float_as_uint(Bs[brow[nf] + k0 + 4]);
            }
#pragma unroll
            for (int mf = 0; mf < MF; mf++)
#pragma unroll
                for (int nf = 0; nf < 8; nf++)
                    mma8(acc[mf][nf], a[mf], b[nf]);
        }
        __syncthreads();
    }

    // ---- epilogue: stage accumulators to smem ----
    float* sepi   = dsm;
    float* s_mean = dsm + 128 * EPIST;
    float* s_inv  = s_mean + 128;
    const bool doAct = (MODE != 3) || (blockIdx.z == 0);

#pragma unroll
    for (int mf = 0; mf < MF; mf++) {
        int r0 = warp_m * MROWS + mf * 16 + g;
#pragma unroll
        for (int nf = 0; nf < 8; nf++) {
            int c0 = warp_n * 64 + nf * 8 + 2 * t;
            float v0 = acc[mf][nf][0], v1 = acc[mf][nf][1];
            float v2 = acc[mf][nf][2], v3 = acc[mf][nf][3];
            if (EPI == EPI_ELU1 && doAct) {
                v0 = (v0 > 0.f) ? v0 + 1.f : __expf(v0);
                v1 = (v1 > 0.f) ? v1 + 1.f : __expf(v1);
                v2 = (v2 > 0.f) ? v2 + 1.f : __expf(v2);
                v3 = (v3 > 0.f) ? v3 + 1.f : __expf(v3);
            }
            if (EPI == EPI_RELU) {
                v0 = fmaxf(v0, 0.f); v1 = fmaxf(v1, 0.f);
                v2 = fmaxf(v2, 0.f); v3 = fmaxf(v3, 0.f);
            }
            *(float2*)&sepi[r0 * EPIST + c0]       = make_float2(v0, v1);
            *(float2*)&sepi[(r0 + 8) * EPIST + c0] = make_float2(v2, v3);
        }
    }
    __syncthreads();

    if ((EPI == EPI_LN || EPI == EPI_LN_RESID) && tid < 128) {
        const float* rowp = sepi + tid * EPIST;
        float sum = 0.f, ss = 0.f;
#pragma unroll 8
        for (int j = 0; j < NB / 4; j++) {
            float4 v = *(const float4*)&rowp[j * 4];
            sum += v.x + v.y + v.z + v.w;
            ss  += v.x * v.x + v.y * v.y + v.z * v.z + v.w * v.w;
        }
        float mean = sum * (1.f / 256.f);
        float var  = ss * (1.f / 256.f) - mean * mean;
        s_mean[tid] = mean;
        s_inv[tid]  = rsqrtf(var + EPS_LN);
    }
    if (EPI == EPI_LN || EPI == EPI_LN_RESID) __syncthreads();

#pragma unroll 4
    for (int p = 0; p < NB / 8; p++) {
        int idx4 = p * 256 + tid;
        int row = idx4 / (NB / 4);
        int c4  = (idx4 % (NB / 4)) << 2;
        float4 v = *(const float4*)&sepi[row * EPIST + c4];
        if (EPI == EPI_LN || EPI == EPI_LN_RESID) {
            float m = s_mean[row], iv = s_inv[row];
            float4 gm = *(const float4*)&gamma[c4];
            float4 bt = *(const float4*)&beta[c4];
            v.x = (v.x - m) * iv * gm.x + bt.x;
            v.y = (v.y - m) * iv * gm.y + bt.y;
            v.z = (v.z - m) * iv * gm.z + bt.z;
            v.w = (v.w - m) * iv * gm.w + bt.w;
            if (EPI == EPI_LN_RESID) {
                float4 r = *(const float4*)&resid[(size_t)(mtile + row) * 256 + c4];
                v.x += r.x; v.y += r.y; v.z += r.z; v.w += r.w;
            }
        }
        *(float4*)&Cblk[(size_t)(mtile + row) * Ntot + ncol0 + c4] = v;
    }
}

// ---------------------------------------------------------------------------
// KV = sum_s K^T V, Ksum = sum_s K. grid 64, 256 thr.
// ---------------------------------------------------------------------------
__global__ void kv_kernel(const float* __restrict__ kmat, const float* __restrict__ vmat,
                          float* __restrict__ kv, float* __restrict__ ksum) {
    __shared__ float Ks[128][32];
    __shared__ float Vs[128][32];
    int bh = blockIdx.x, b = bh >> 3, h = bh & 7;
    int tid = threadIdx.x;
    int d = tid & 31, vg = tid >> 5;
    float acc0 = 0.f, acc1 = 0.f, acc2 = 0.f, acc3 = 0.f, ka = 0.f;

    for (int ch = 0; ch < 2; ch++) {
        int sl = tid >> 3, c4 = tid & 7;
#pragma unroll
        for (int ss = 0; ss < 4; ss++) {
            int srow = ch * 128 + ss * 32 + sl;
            size_t base = ((size_t)(b * 256 + srow)) * 256 + h * 32 + c4 * 4;
            *(float4*)&Ks[ss * 32 + sl][c4 * 4] = *(const float4*)&kmat[base];
            *(float4*)&Vs[ss * 32 + sl][c4 * 4] = *(const float4*)&vmat[base];
        }
        __syncthreads();
#pragma unroll 4
        for (int s = 0; s < 128; s++) {
            float kd = Ks[s][d];
            float4 vv = *(float4*)&Vs[s][vg * 4];
            acc0 += kd * vv.x; acc1 += kd * vv.y;
            acc2 += kd * vv.z; acc3 += kd * vv.w;
            if (vg == 0) ka += kd;
        }
        __syncthreads();
    }
    float* kvp = kv + ((size_t)bh * 32 + d) * 32 + vg * 4;
    kvp[0] = acc0; kvp[1] = acc1; kvp[2] = acc2; kvp[3] = acc3;
    if (vg == 0) ksum[bh * 32 + d] = ka;
}

// ---------------------------------------------------------------------------
// msg = z * (Q @ KV), z = 1/(Q.Ksum + eps). grid (256, 8).
// ---------------------------------------------------------------------------
__global__ void attn_apply(const float* __restrict__ qmat, const float* __restrict__ kv,
                           const float* __restrict__ ksum, float* __restrict__ msg) {
    __shared__ float Qs[16 * 256];
    __shared__ float zs[16][8];
    __shared__ float ksums[256];
    int b = blockIdx.y;
    int t0 = blockIdx.x * 16;
    int tid = threadIdx.x;

    const float4* qsrc = (const float4*)(qmat + ((size_t)b * 4096 + t0) * 256);
    float4* qd = (float4*)Qs;
#pragma unroll
    for (int q = 0; q < 4; q++) qd[tid + q * 256] = qsrc[tid + q * 256];
    ksums[tid] = ksum[b * 256 + tid];
    __syncthreads();

    if (tid < 128) {
        int t = tid >> 3, h = tid & 7;
        const float* qrow = Qs + t * 256 + h * 32;
        const float* kr = ksums + h * 32;
        float z = 0.f;
#pragma unroll
        for (int dd = 0; dd < 32; dd++) z += qrow[dd] * kr[dd];
        zs[t][h] = 1.f / (z + EPS_ATT);
    }
    __syncthreads();

    int h = tid >> 5, v = tid & 31;
    float kvr[32];
#pragma unroll
    for (int dd = 0; dd < 32; dd++)
        kvr[dd] = kv[(((size_t)(b * 8 + h)) * 32 + dd) * 32 + v];
#pragma unroll 2
    for (int t = 0; t < 16; t++) {
        const float* qrow = Qs + t * 256 + h * 32;
        float m = 0.f;
#pragma unroll
        for (int dd = 0; dd < 32; dd++) m += qrow[dd] * kvr[dd];
        msg[((size_t)b * 4096 + t0 + t) * 256 + tid] = m * zs[t][h];
    }
}

// ---------------------------------------------------------------------------
// Launch
// ---------------------------------------------------------------------------
extern "C" void kernel_launch(void* const* d_in, const int* in_sizes, int n_in,
                              void* d_out, int out_size) {
    const float* x      = (const float*)d_in[0];
    const float* sr_w   = (const float*)d_in[1];
    const float* sr_b   = (const float*)d_in[2];
    const float* norm_g = (const float*)d_in[3];
    const float* norm_b = (const float*)d_in[4];
    const float* wq     = (const float*)d_in[5];
    const float* wk     = (const float*)d_in[6];
    const float* wv     = (const float*)d_in[7];
    const float* wm     = (const float*)d_in[8];
    const float* w1     = (const float*)d_in[9];
    const float* w2     = (const float*)d_in[10];
    const float* n1g    = (const float*)d_in[11];
    const float* n1b    = (const float*)d_in[12];
    const float* n2g    = (const float*)d_in[13];
    const float* n2b    = (const float*)d_in[14];
    float* out = (float*)d_out;

    float *wsrB, *wqr, *wkr, *wvr, *wmr, *w1r, *w2r;
    float *part, *src, *kmat, *vmat, *kvp, *ksump, *qmat, *msg, *msgn, *hmid;
    cudaGetSymbolAddress((void**)&wsrB, g_wsrB);
    cudaGetSymbolAddress((void**)&wqr,  g_wqr);
    cudaGetSymbolAddress((void**)&wkr,  g_wkr);
    cudaGetSymbolAddress((void**)&wvr,  g_wvr);
    cudaGetSymbolAddress((void**)&wmr,  g_wmr);
    cudaGetSymbolAddress((void**)&w1r,  g_w1r);
    cudaGetSymbolAddress((void**)&w2r,  g_w2r);
    cudaGetSymbolAddress((void**)&part, g_part);
    cudaGetSymbolAddress((void**)&src,  g_src);
    cudaGetSymbolAddress((void**)&kmat, g_kmat);
    cudaGetSymbolAddress((void**)&vmat, g_vmat);
    cudaGetSymbolAddress((void**)&kvp,  g_kv);
    cudaGetSymbolAddress((void**)&ksump,g_ksum);
    cudaGetSymbolAddress((void**)&qmat, g_qmat);
    cudaGetSymbolAddress((void**)&msg,  g_msg);
    cudaGetSymbolAddress((void**)&msgn, g_msgn);
    cudaGetSymbolAddress((void**)&hmid, g_hmid);

    constexpr int SM128 = smem_req(128);
    constexpr int SM256 = smem_req(256);
    cudaFuncSetAttribute(mma_gemm<EPI_PLAIN, 2, 128>,    cudaFuncAttributeMaxDynamicSharedMemorySize, SM128);
    cudaFuncSetAttribute(mma_gemm<EPI_ELU1, 3, 128>,     cudaFuncAttributeMaxDynamicSharedMemorySize, SM128);
    cudaFuncSetAttribute(mma_gemm<EPI_ELU1, 0, 128>,     cudaFuncAttributeMaxDynamicSharedMemorySize, SM128);
    cudaFuncSetAttribute(mma_gemm<EPI_RELU, 1, 128>,     cudaFuncAttributeMaxDynamicSharedMemorySize, SM128);
    cudaFuncSetAttribute(mma_gemm<EPI_LN, 0, 256>,       cudaFuncAttributeMaxDynamicSharedMemorySize, SM256);
    cudaFuncSetAttribute(mma_gemm<EPI_LN_RESID, 0, 256>, cudaFuncAttributeMaxDynamicSharedMemorySize, SM256);

    // weight prep
    repack_srw<<<256, 256>>>(sr_w, wsrB);
    round_weights<<<2560, 256>>>(wq, wk, wv, wm, w1, w2, wqr, wkr, wvr, wmr, w1r, w2r);

    // conv-as-GEMM (split-K=8 on z) + reduce/bias/LN
    mma_gemm<EPI_PLAIN, 2, 128><<<dim3(16, 2, 8), 256, SM128>>>(
        x, nullptr, wsrB, part, 512, 4096, 256, nullptr, nullptr, nullptr, nullptr, nullptr);
    reduce_ln<<<256, 256>>>(part, sr_b, norm_g, norm_b, src);

    // fused k/v projections (M=2048): z=0 -> wk+elu -> kmat, z=1 -> wv -> vmat
    mma_gemm<EPI_ELU1, 3, 128><<<dim3(16, 2, 2), 256, SM128>>>(
        src, nullptr, wkr, kmat, 256, 256, 256, nullptr, nullptr, nullptr, wvr, vmat);

    kv_kernel<<<64, 256>>>(kmat, vmat, kvp, ksump);

    // q projection (M=32768) -> elu+1
    mma_gemm<EPI_ELU1, 0, 128><<<dim3(256, 2), 256, SM128>>>(
        x, nullptr, wqr, qmat, 256, 256, 256, nullptr, nullptr, nullptr, nullptr, nullptr);

    attn_apply<<<dim3(256, 8), 256>>>(qmat, kvp, ksump, msg);

    // merge projection + LN1 (BN=256 for row-wide LN)
    mma_gemm<EPI_LN, 0, 256><<<dim3(256, 1), 256, SM256>>>(
        msg, nullptr, wmr, msgn, 256, 256, 256, n1g, n1b, nullptr, nullptr, nullptr);

    // MLP1: concat(x, msgn) @ w1^T -> relu (Ntot=512, 4 column blocks)
    mma_gemm<EPI_RELU, 1, 128><<<dim3(256, 4), 256, SM128>>>(
        x, msgn, w1r, hmid, 512, 512, 512, nullptr, nullptr, nullptr, nullptr, nullptr);

    // MLP2 + LN2 + residual -> out (BN=256)
    mma_gemm<EPI_LN_RESID, 0, 256><<<dim3(256, 1), 256, SM256>>>(
        hmid, nullptr, w2r, out, 512, 512, 256, n2g, n2b, x, nullptr, nullptr);
}

// round 9
// speedup vs baseline: 1.2524x; 1.1587x over previous
#include <cuda_runtime.h>
#include <cuda_fp16.h>
#include <math.h>
#include <stdint.h>

#define EPS_LN  1e-5f
#define EPS_ATT 1e-6f

// ---------------------------------------------------------------------------
// helpers
// ---------------------------------------------------------------------------
__device__ __forceinline__ uint32_t pack_h2(float a, float b) {
    __half2 h = __floats2half2_rn(a, b);
    return *(uint32_t*)&h;
}
__device__ __forceinline__ void mma16(float* c, const uint32_t* a, const uint32_t* b) {
    asm volatile(
        "mma.sync.aligned.m16n8k16.row.col.f32.f16.f16.f32 "
        "{%0,%1,%2,%3}, {%4,%5,%6,%7}, {%8,%9}, {%0,%1,%2,%3};"
        : "+f"(c[0]), "+f"(c[1]), "+f"(c[2]), "+f"(c[3])
        : "r"(a[0]), "r"(a[1]), "r"(a[2]), "r"(a[3]), "r"(b[0]), "r"(b[1]));
}

// ---------------------------------------------------------------------------
// Scratch
// ---------------------------------------------------------------------------
__device__ __half g_wsrB[256 * 4096];       // conv weight [o][k], fp16
__device__ __half g_wqr [256 * 256];
__device__ __half g_wkr [256 * 256];
__device__ __half g_wvr [256 * 256];
__device__ __half g_wmr [256 * 256];
__device__ __half g_w1r [512 * 512];
__device__ __half g_w2r [256 * 512];
__device__ float g_part[4 * 2048 * 256];    // conv split-K partials
__device__ float g_src [2048 * 256];
__device__ float g_kmat[2048 * 256];
__device__ float g_vmat[2048 * 256];
__device__ float g_kv  [64 * 32 * 32];
__device__ float g_ksum[64 * 32];
__device__ float g_qmat[8 * 4096 * 256];
__device__ float g_msg [8 * 4096 * 256];
__device__ float g_msgn[8 * 4096 * 256];
__device__ float g_hmid[8 * 4096 * 512];

// sr_w OIHW [o][i][4][4] -> wsrB[o*4096 + rr*256 + i], fp16
__global__ void repack_srw(const float* __restrict__ w, __half* __restrict__ wb) {
    int idx = blockIdx.x * blockDim.x + threadIdx.x;   // 65536
    int o = idx >> 8, i = idx & 255;
    const float* p = w + ((size_t)(o * 256 + i)) * 16;
#pragma unroll
    for (int rr = 0; rr < 16; rr++)
        wb[(size_t)o * 4096 + rr * 256 + i] = __float2half_rn(p[rr]);
}

// Convert all 6 linear weights to fp16. 2560 blocks x 256.
__global__ void round_weights(const float* __restrict__ wq, const float* __restrict__ wk,
                              const float* __restrict__ wv, const float* __restrict__ wm,
                              const float* __restrict__ w1, const float* __restrict__ w2,
                              __half* __restrict__ oq, __half* __restrict__ ok,
                              __half* __restrict__ ov, __half* __restrict__ om,
                              __half* __restrict__ o1, __half* __restrict__ o2) {
    int bid = blockIdx.x;
    const float* src; __half* dst; int base;
    if      (bid < 256)  { src = wq; dst = oq; base = 0; }
    else if (bid < 512)  { src = wk; dst = ok; base = 256; }
    else if (bid < 768)  { src = wv; dst = ov; base = 512; }
    else if (bid < 1024) { src = wm; dst = om; base = 768; }
    else if (bid < 2048) { src = w1; dst = o1; base = 1024; }
    else                 { src = w2; dst = o2; base = 2048; }
    int idx = (bid - base) * 256 + threadIdx.x;
    dst[idx] = __float2half_rn(src[idx]);
}

// ---------------------------------------------------------------------------
// Split-K(4) reduce + bias + LayerNorm -> src. grid 256, 256 thr.
// ---------------------------------------------------------------------------
__global__ void reduce_ln(const float* __restrict__ part, const float* __restrict__ bias,
                          const float* __restrict__ g, const float* __restrict__ bb,
                          float* __restrict__ out) {
    int lane = threadIdx.x & 31, w = threadIdx.x >> 5;
    int row = blockIdx.x * 8 + w;
    float v[8];
#pragma unroll
    for (int j = 0; j < 8; j++) {
        int c = lane + j * 32;
        float s = 0.f;
#pragma unroll
        for (int ks = 0; ks < 4; ks++)
            s += part[((size_t)ks * 2048 + row) * 256 + c];
        v[j] = s + bias[c];
    }
    float sum = 0.f;
#pragma unroll
    for (int j = 0; j < 8; j++) sum += v[j];
#pragma unroll
    for (int o = 16; o; o >>= 1) sum += __shfl_xor_sync(0xffffffffu, sum, o);
    float mean = sum * (1.f / 256.f);
    float ss = 0.f;
#pragma unroll
    for (int j = 0; j < 8; j++) { float d = v[j] - mean; ss += d * d; }
#pragma unroll
    for (int o = 16; o; o >>= 1) ss += __shfl_xor_sync(0xffffffffu, ss, o);
    float inv = rsqrtf(ss * (1.f / 256.f) + EPS_LN);
#pragma unroll
    for (int j = 0; j < 8; j++) {
        int c = lane + j * 32;
        out[(size_t)row * 256 + c] = (v[j] - mean) * inv * g[c] + bb[c];
    }
}

// ---------------------------------------------------------------------------
// fp16 mma.sync m16n8k16 GEMM. BM=128, BN=NB, BK=32 halfs, 256 threads.
// NB=128: warp 32x64 (4x2), 2 CTAs/SM. NB=256: warp 64x64 (2x4), 1 CTA/SM.
// A (fp32 gmem) converted to half in the LDG->STS path; B pre-converted fp16.
// Smem rows padded to 40 halfs (20 words) -> all fragment LDS conflict-free.
// MODE: 0=plain, 1=concat(A0,A1), 2=conv gather + split-K(z), 3=fused k/v(z)
// EPI: 0 plain, 1 elu+1, 2 relu, 3 LN, 4 LN+resid
// ---------------------------------------------------------------------------
#define EPI_PLAIN    0
#define EPI_ELU1     1
#define EPI_RELU     2
#define EPI_LN       3
#define EPI_LN_RESID 4

#define RSTRIDE_H 40                       // halfs per smem row (20 words)
#define A_ROWS    128

__host__ __device__ constexpr int stage_halfs(int NB) { return (128 + NB) * RSTRIDE_H; }
__host__ __device__ constexpr int smem_req(int NB) {
    int mainloop = 2 * stage_halfs(NB) * 2;
    int epi = (128 * (NB + 4) + 256) * 4;
    return mainloop > epi ? mainloop : epi;
}

template <int EPI, int MODE, int NB>
__global__ __launch_bounds__(256, (NB == 128 ? 2 : 1))
void mma_gemm(const float* __restrict__ A0, const float* __restrict__ A1,
              const __half* __restrict__ Bw, float* __restrict__ C,
              int Kloc, int KB, int Ntot,
              const float* __restrict__ gamma, const float* __restrict__ beta,
              const float* __restrict__ resid,
              const __half* __restrict__ Bw2, float* __restrict__ C2) {
    extern __shared__ __half dsm_h[];

    constexpr int WM    = (NB == 256) ? 2 : 4;
    constexpr int MF    = 128 / WM / 16;
    constexpr int MROWS = 128 / WM;
    constexpr int NBLD  = NB / 64;           // B uint4 loads per thread
    constexpr int STAGE = stage_halfs(NB);
    constexpr int EPIST = NB + 4;

    const int tid  = threadIdx.x;
    const int lane = tid & 31;
    const int wid  = tid >> 5;
    const int g    = lane >> 2;
    const int t    = lane & 3;
    const int warp_m = wid % WM;
    const int warp_n = wid / WM;

    const int mtile = blockIdx.x * 128;
    int ncol0 = blockIdx.y * NB, kstart = 0;
    float* Cblk = C;
    const __half* Bsrc = Bw;
    if (MODE == 2) { kstart = blockIdx.z * 1024; Cblk = C + (size_t)blockIdx.z * 2048 * 256; }
    if (MODE == 3) { if (blockIdx.z) { Bsrc = Bw2; Cblk = C2; } }
    const int KT = Kloc / 32;

    float acc[MF][8][4];
#pragma unroll
    for (int i = 0; i < MF; i++)
#pragma unroll
        for (int j = 0; j < 8; j++)
#pragma unroll
            for (int q = 0; q < 4; q++) acc[i][j][q] = 0.f;

    uint2 rA[4];
    uint4 rB[NBLD];

    auto ldg_tile = [&](int kt) {
        const int kbase = kstart + kt * 32;
        // A: 128 rows x 32 halfs; sources are fp32 -> convert
#pragma unroll
        for (int p = 0; p < 4; p++) {
            int idx = p * 256 + tid;
            int m = idx >> 3, c = idx & 7;
            int kk = kbase + c * 4;
            const float* gp;
            if (MODE == 2) {
                int mg = mtile + m;
                int b = mg >> 8, s5 = mg & 255;
                int rr = kk >> 8, i = kk & 255;
                int n = (((s5 >> 4) * 4 + (rr >> 2)) << 6) + ((s5 & 15) << 2) + (rr & 3);
                gp = A0 + (((size_t)b << 12) + n) * 256 + i;
            } else if (MODE == 1) {
                gp = (kk < 256) ? (A0 + (size_t)(mtile + m) * 256 + kk)
                                : (A1 + (size_t)(mtile + m) * 256 + (kk - 256));
            } else {
                gp = A0 + (size_t)(mtile + m) * Kloc + kk;
            }
            float4 v = *(const float4*)gp;
            rA[p].x = pack_h2(v.x, v.y);
            rA[p].y = pack_h2(v.z, v.w);
        }
        // B: NB rows x 32 halfs, already fp16 in gmem
#pragma unroll
        for (int p = 0; p < NBLD; p++) {
            int idx = p * 256 + tid;
            int n = idx >> 2, c = idx & 3;
            rB[p] = *(const uint4*)(Bsrc + (size_t)(ncol0 + n) * KB + kbase + c * 8);
        }
    };
    auto sts_tile = [&](int s) {
        __half* sA = dsm_h + s * STAGE;
        __half* sB = sA + A_ROWS * RSTRIDE_H;
#pragma unroll
        for (int p = 0; p < 4; p++) {
            int idx = p * 256 + tid;
            int m = idx >> 3, c = idx & 7;
            *(uint2*)&sA[m * RSTRIDE_H + c * 4] = rA[p];
        }
#pragma unroll
        for (int p = 0; p < NBLD; p++) {
            int idx = p * 256 + tid;
            int n = idx >> 2, c = idx & 3;
            *(uint4*)&sB[n * RSTRIDE_H + c * 8] = rB[p];
        }
    };

    int arow[MF], brow[8];
#pragma unroll
    for (int mf = 0; mf < MF; mf++) arow[mf] = (warp_m * MROWS + mf * 16 + g) * 20;
#pragma unroll
    for (int nf = 0; nf < 8; nf++) brow[nf] = (warp_n * 64 + nf * 8 + g) * 20;

    // prologue
    ldg_tile(0);
    sts_tile(0);
    if (KT > 1) ldg_tile(1);
    __syncthreads();

    for (int kt = 0; kt < KT; kt++) {
        if (kt + 1 < KT) {
            sts_tile((kt + 1) & 1);
            if (kt + 2 < KT) ldg_tile(kt + 2);
            __syncthreads();
        }
        const uint32_t* As2 = (const uint32_t*)(dsm_h + (kt & 1) * STAGE);
        const uint32_t* Bs2 = As2 + A_ROWS * 20;
#pragma unroll
        for (int ks = 0; ks < 2; ks++) {
            const int base = ks * 8 + t;
            uint32_t a[MF][4], b[8][2];
#pragma unroll
            for (int mf = 0; mf < MF; mf++) {
                a[mf][0] = As2[arow[mf] + base];
                a[mf][1] = As2[arow[mf] + 160 + base];
                a[mf][2] = As2[arow[mf] + base + 4];
                a[mf][3] = As2[arow[mf] + 160 + base + 4];
            }
#pragma unroll
            for (int nf = 0; nf < 8; nf++) {
                b[nf][0] = Bs2[brow[nf] + base];
                b[nf][1] = Bs2[brow[nf] + base + 4];
            }
#pragma unroll
            for (int mf = 0; mf < MF; mf++)
#pragma unroll
                for (int nf = 0; nf < 8; nf++)
                    mma16(acc[mf][nf], a[mf], b[nf]);
        }
        __syncthreads();
    }

    // ---- epilogue: stage accumulators to smem (fp32 view) ----
    float* sepi   = (float*)dsm_h;
    float* s_mean = sepi + 128 * EPIST;
    float* s_inv  = s_mean + 128;
    const bool doAct = (MODE != 3) || (blockIdx.z == 0);

#pragma unroll
    for (int mf = 0; mf < MF; mf++) {
        int r0 = warp_m * MROWS + mf * 16 + g;
#pragma unroll
        for (int nf = 0; nf < 8; nf++) {
            int c0 = warp_n * 64 + nf * 8 + 2 * t;
            float v0 = acc[mf][nf][0], v1 = acc[mf][nf][1];
            float v2 = acc[mf][nf][2], v3 = acc[mf][nf][3];
            if (EPI == EPI_ELU1 && doAct) {
                v0 = (v0 > 0.f) ? v0 + 1.f : __expf(v0);
                v1 = (v1 > 0.f) ? v1 + 1.f : __expf(v1);
                v2 = (v2 > 0.f) ? v2 + 1.f : __expf(v2);
                v3 = (v3 > 0.f) ? v3 + 1.f : __expf(v3);
            }
            if (EPI == EPI_RELU) {
                v0 = fmaxf(v0, 0.f); v1 = fmaxf(v1, 0.f);
                v2 = fmaxf(v2, 0.f); v3 = fmaxf(v3, 0.f);
            }
            *(float2*)&sepi[r0 * EPIST + c0]       = make_float2(v0, v1);
            *(float2*)&sepi[(r0 + 8) * EPIST + c0] = make_float2(v2, v3);
        }
    }
    __syncthreads();

    if ((EPI == EPI_LN || EPI == EPI_LN_RESID) && tid < 128) {
        const float* rowp = sepi + tid * EPIST;
        float sum = 0.f, ss = 0.f;
#pragma unroll 8
        for (int j = 0; j < NB / 4; j++) {
            float4 v = *(const float4*)&rowp[j * 4];
            sum += v.x + v.y + v.z + v.w;
            ss  += v.x * v.x + v.y * v.y + v.z * v.z + v.w * v.w;
        }
        float mean = sum * (1.f / 256.f);
        float var  = ss * (1.f / 256.f) - mean * mean;
        s_mean[tid] = mean;
        s_inv[tid]  = rsqrtf(var + EPS_LN);
    }
    if (EPI == EPI_LN || EPI == EPI_LN_RESID) __syncthreads();

#pragma unroll 4
    for (int p = 0; p < NB / 8; p++) {
        int idx4 = p * 256 + tid;
        int row = idx4 / (NB / 4);
        int c4  = (idx4 % (NB / 4)) << 2;
        float4 v = *(const float4*)&sepi[row * EPIST + c4];
        if (EPI == EPI_LN || EPI == EPI_LN_RESID) {
            float m = s_mean[row], iv = s_inv[row];
            float4 gm = *(const float4*)&gamma[c4];
            float4 bt = *(const float4*)&beta[c4];
            v.x = (v.x - m) * iv * gm.x + bt.x;
            v.y = (v.y - m) * iv * gm.y + bt.y;
            v.z = (v.z - m) * iv * gm.z + bt.z;
            v.w = (v.w - m) * iv * gm.w + bt.w;
            if (EPI == EPI_LN_RESID) {
                float4 r = *(const float4*)&resid[(size_t)(mtile + row) * 256 + c4];
                v.x += r.x; v.y += r.y; v.z += r.z; v.w += r.w;
            }
        }
        *(float4*)&Cblk[(size_t)(mtile + row) * Ntot + ncol0 + c4] = v;
    }
}

// ---------------------------------------------------------------------------
// KV = sum_s K^T V, Ksum = sum_s K. grid 64, 256 thr.
// ---------------------------------------------------------------------------
__global__ void kv_kernel(const float* __restrict__ kmat, const float* __restrict__ vmat,
                          float* __restrict__ kv, float* __restrict__ ksum) {
    __shared__ float Ks[128][32];
    __shared__ float Vs[128][32];
    int bh = blockIdx.x, b = bh >> 3, h = bh & 7;
    int tid = threadIdx.x;
    int d = tid & 31, vg = tid >> 5;
    float acc0 = 0.f, acc1 = 0.f, acc2 = 0.f, acc3 = 0.f, ka = 0.f;

    for (int ch = 0; ch < 2; ch++) {
        int sl = tid >> 3, c4 = tid & 7;
#pragma unroll
        for (int ss = 0; ss < 4; ss++) {
            int srow = ch * 128 + ss * 32 + sl;
            size_t base = ((size_t)(b * 256 + srow)) * 256 + h * 32 + c4 * 4;
            *(float4*)&Ks[ss * 32 + sl][c4 * 4] = *(const float4*)&kmat[base];
            *(float4*)&Vs[ss * 32 + sl][c4 * 4] = *(const float4*)&vmat[base];
        }
        __syncthreads();
#pragma unroll 4
        for (int s = 0; s < 128; s++) {
            float kd = Ks[s][d];
            float4 vv = *(float4*)&Vs[s][vg * 4];
            acc0 += kd * vv.x; acc1 += kd * vv.y;
            acc2 += kd * vv.z; acc3 += kd * vv.w;
            if (vg == 0) ka += kd;
        }
        __syncthreads();
    }
    float* kvp = kv + ((size_t)bh * 32 + d) * 32 + vg * 4;
    kvp[0] = acc0; kvp[1] = acc1; kvp[2] = acc2; kvp[3] = acc3;
    if (vg == 0) ksum[bh * 32 + d] = ka;
}

// ---------------------------------------------------------------------------
// msg = z * (Q @ KV), z = 1/(Q.Ksum + eps). grid (256, 8).
// ---------------------------------------------------------------------------
__global__ void attn_apply(const float* __restrict__ qmat, const float* __restrict__ kv,
                           const float* __restrict__ ksum, float* __restrict__ msg) {
    __shared__ float Qs[16 * 256];
    __shared__ float zs[16][8];
    __shared__ float ksums[256];
    int b = blockIdx.y;
    int t0 = blockIdx.x * 16;
    int tid = threadIdx.x;

    const float4* qsrc = (const float4*)(qmat + ((size_t)b * 4096 + t0) * 256);
    float4* qd = (float4*)Qs;
#pragma unroll
    for (int q = 0; q < 4; q++) qd[tid + q * 256] = qsrc[tid + q * 256];
    ksums[tid] = ksum[b * 256 + tid];
    __syncthreads();

    if (tid < 128) {
        int t = tid >> 3, h = tid & 7;
        const float* qrow = Qs + t * 256 + h * 32;
        const float* kr = ksums + h * 32;
        float z = 0.f;
#pragma unroll
        for (int dd = 0; dd < 32; dd++) z += qrow[dd] * kr[dd];
        zs[t][h] = 1.f / (z + EPS_ATT);
    }
    __syncthreads();

    int h = tid >> 5, v = tid & 31;
    float kvr[32];
#pragma unroll
    for (int dd = 0; dd < 32; dd++)
        kvr[dd] = kv[(((size_t)(b * 8 + h)) * 32 + dd) * 32 + v];
#pragma unroll 2
    for (int t = 0; t < 16; t++) {
        const float* qrow = Qs + t * 256 + h * 32;
        float m = 0.f;
#pragma unroll
        for (int dd = 0; dd < 32; dd++) m += qrow[dd] * kvr[dd];
        msg[((size_t)b * 4096 + t0 + t) * 256 + tid] = m * zs[t][h];
    }
}

// ---------------------------------------------------------------------------
// Launch
// ---------------------------------------------------------------------------
extern "C" void kernel_launch(void* const* d_in, const int* in_sizes, int n_in,
                              void* d_out, int out_size) {
    const float* x      = (const float*)d_in[0];
    const float* sr_w   = (const float*)d_in[1];
    const float* sr_b   = (const float*)d_in[2];
    const float* norm_g = (const float*)d_in[3];
    const float* norm_b = (const float*)d_in[4];
    const float* wq     = (const float*)d_in[5];
    const float* wk     = (const float*)d_in[6];
    const float* wv     = (const float*)d_in[7];
    const float* wm     = (const float*)d_in[8];
    const float* w1     = (const float*)d_in[9];
    const float* w2     = (const float*)d_in[10];
    const float* n1g    = (const float*)d_in[11];
    const float* n1b    = (const float*)d_in[12];
    const float* n2g    = (const float*)d_in[13];
    const float* n2b    = (const float*)d_in[14];
    float* out = (float*)d_out;

    __half *wsrB, *wqr, *wkr, *wvr, *wmr, *w1r, *w2r;
    float *part, *src, *kmat, *vmat, *kvp, *ksump, *qmat, *msg, *msgn, *hmid;
    cudaGetSymbolAddress((void**)&wsrB, g_wsrB);
    cudaGetSymbolAddress((void**)&wqr,  g_wqr);
    cudaGetSymbolAddress((void**)&wkr,  g_wkr);
    cudaGetSymbolAddress((void**)&wvr,  g_wvr);
    cudaGetSymbolAddress((void**)&wmr,  g_wmr);
    cudaGetSymbolAddress((void**)&w1r,  g_w1r);
    cudaGetSymbolAddress((void**)&w2r,  g_w2r);
    cudaGetSymbolAddress((void**)&part, g_part);
    cudaGetSymbolAddress((void**)&src,  g_src);
    cudaGetSymbolAddress((void**)&kmat, g_kmat);
    cudaGetSymbolAddress((void**)&vmat, g_vmat);
    cudaGetSymbolAddress((void**)&kvp,  g_kv);
    cudaGetSymbolAddress((void**)&ksump,g_ksum);
    cudaGetSymbolAddress((void**)&qmat, g_qmat);
    cudaGetSymbolAddress((void**)&msg,  g_msg);
    cudaGetSymbolAddress((void**)&msgn, g_msgn);
    cudaGetSymbolAddress((void**)&hmid, g_hmid);

    constexpr int SM128 = smem_req(128);
    constexpr int SM256 = smem_req(256);
    cudaFuncSetAttribute(mma_gemm<EPI_PLAIN, 2, 128>,    cudaFuncAttributeMaxDynamicSharedMemorySize, SM128);
    cudaFuncSetAttribute(mma_gemm<EPI_ELU1, 3, 128>,     cudaFuncAttributeMaxDynamicSharedMemorySize, SM128);
    cudaFuncSetAttribute(mma_gemm<EPI_ELU1, 0, 128>,     cudaFuncAttributeMaxDynamicSharedMemorySize, SM128);
    cudaFuncSetAttribute(mma_gemm<EPI_RELU, 1, 128>,     cudaFuncAttributeMaxDynamicSharedMemorySize, SM128);
    cudaFuncSetAttribute(mma_gemm<EPI_LN, 0, 256>,       cudaFuncAttributeMaxDynamicSharedMemorySize, SM256);
    cudaFuncSetAttribute(mma_gemm<EPI_LN_RESID, 0, 256>, cudaFuncAttributeMaxDynamicSharedMemorySize, SM256);

    // weight prep (fp32 -> fp16)
    repack_srw<<<256, 256>>>(sr_w, wsrB);
    round_weights<<<2560, 256>>>(wq, wk, wv, wm, w1, w2, wqr, wkr, wvr, wmr, w1r, w2r);

    // conv-as-GEMM (split-K=4 on z) + reduce/bias/LN
    mma_gemm<EPI_PLAIN, 2, 128><<<dim3(16, 2, 4), 256, SM128>>>(
        x, nullptr, wsrB, part, 1024, 4096, 256, nullptr, nullptr, nullptr, nullptr, nullptr);
    reduce_ln<<<256, 256>>>(part, sr_b, norm_g, norm_b, src);

    // fused k/v projections (M=2048): z=0 -> wk+elu -> kmat, z=1 -> wv -> vmat
    mma_gemm<EPI_ELU1, 3, 128><<<dim3(16, 2, 2), 256, SM128>>>(
        src, nullptr, wkr, kmat, 256, 256, 256, nullptr, nullptr, nullptr, wvr, vmat);

    kv_kernel<<<64, 256>>>(kmat, vmat, kvp, ksump);

    // q projection (M=32768) -> elu+1
    mma_gemm<EPI_ELU1, 0, 128><<<dim3(256, 2), 256, SM128>>>(
        x, nullptr, wqr, qmat, 256, 256, 256, nullptr, nullptr, nullptr, nullptr, nullptr);

    attn_apply<<<dim3(256, 8), 256>>>(qmat, kvp, ksump, msg);

    // merge projection + LN1 (BN=256 for row-wide LN)
    mma_gemm<EPI_LN, 0, 256><<<dim3(256, 1), 256, SM256>>>(
        msg, nullptr, wmr, msgn, 256, 256, 256, n1g, n1b, nullptr, nullptr, nullptr);

    // MLP1: concat(x, msgn) @ w1^T -> relu (Ntot=512, 4 column blocks)
    mma_gemm<EPI_RELU, 1, 128><<<dim3(256, 4), 256, SM128>>>(
        x, msgn, w1r, hmid, 512, 512, 512, nullptr, nullptr, nullptr, nullptr, nullptr);

    // MLP2 + LN2 + residual -> out (BN=256)
    mma_gemm<EPI_LN_RESID, 0, 256><<<dim3(256, 1), 256, SM256>>>(
        hmid, nullptr, w2r, out, 512, 512, 256, n2g, n2b, x, nullptr, nullptr);
}

// round 10
// speedup vs baseline: 1.5725x; 1.2556x over previous
#include <cuda_runtime.h>
#include <cuda_fp16.h>
#include <math.h>
#include <stdint.h>

#define EPS_LN  1e-5f
#define EPS_ATT 1e-6f

// ---------------------------------------------------------------------------
// helpers
// ---------------------------------------------------------------------------
__device__ __forceinline__ void mma16(float* c, const uint32_t* a, const uint32_t* b) {
    asm volatile(
        "mma.sync.aligned.m16n8k16.row.col.f32.f16.f16.f32 "
        "{%0,%1,%2,%3}, {%4,%5,%6,%7}, {%8,%9}, {%0,%1,%2,%3};"
        : "+f"(c[0]), "+f"(c[1]), "+f"(c[2]), "+f"(c[3])
        : "r"(a[0]), "r"(a[1]), "r"(a[2]), "r"(a[3]), "r"(b[0]), "r"(b[1]));
}
__device__ __forceinline__ uint32_t h2u(__half2 h) { return *(uint32_t*)&h; }

// ---------------------------------------------------------------------------
// Scratch
// ---------------------------------------------------------------------------
__device__ __half g_wsrB[256 * 4096];       // conv weight [o][k], fp16
__device__ __half g_wqr [256 * 256];
__device__ __half g_wkr [256 * 256];
__device__ __half g_wvr [256 * 256];
__device__ __half g_wmr [256 * 256];
__device__ __half g_w1r [512 * 512];
__device__ __half g_w2r [256 * 512];
__device__ __half g_xh  [8 * 4096 * 256];   // fp16 copy of x
__device__ float  g_part[4 * 2048 * 256];   // conv split-K partials (fp32)
__device__ __half g_src [2048 * 256];
__device__ __half g_kmat[2048 * 256];
__device__ __half g_vmat[2048 * 256];
__device__ float  g_kv  [64 * 32 * 32];
__device__ float  g_ksum[64 * 32];
__device__ __half g_qmat[8 * 4096 * 256];
__device__ __half g_msg [8 * 4096 * 256];
__device__ __half g_msgn[8 * 4096 * 256];
__device__ __half g_hmid[8 * 4096 * 512];

// sr_w OIHW [o][i][4][4] -> wsrB[o*4096 + rr*256 + i], fp16
__global__ void repack_srw(const float* __restrict__ w, __half* __restrict__ wb) {
    int idx = blockIdx.x * blockDim.x + threadIdx.x;   // 65536
    int o = idx >> 8, i = idx & 255;
    const float* p = w + ((size_t)(o * 256 + i)) * 16;
#pragma unroll
    for (int rr = 0; rr < 16; rr++)
        wb[(size_t)o * 4096 + rr * 256 + i] = __float2half_rn(p[rr]);
}

// Convert all 6 linear weights to fp16. 2560 blocks x 256.
__global__ void round_weights(const float* __restrict__ wq, const float* __restrict__ wk,
                              const float* __restrict__ wv, const float* __restrict__ wm,
                              const float* __restrict__ w1, const float* __restrict__ w2,
                              __half* __restrict__ oq, __half* __restrict__ ok,
                              __half* __restrict__ ov, __half* __restrict__ om,
                              __half* __restrict__ o1, __half* __restrict__ o2) {
    int bid = blockIdx.x;
    const float* src; __half* dst; int base;
    if      (bid < 256)  { src = wq; dst = oq; base = 0; }
    else if (bid < 512)  { src = wk; dst = ok; base = 256; }
    else if (bid < 768)  { src = wv; dst = ov; base = 512; }
    else if (bid < 1024) { src = wm; dst = om; base = 768; }
    else if (bid < 2048) { src = w1; dst = o1; base = 1024; }
    else                 { src = w2; dst = o2; base = 2048; }
    int idx = (bid - base) * 256 + threadIdx.x;
    dst[idx] = __float2half_rn(src[idx]);
}

// x (fp32) -> xh (fp16). 8192 blocks x 256, 4 elems/thread.
__global__ void x_to_half(const float* __restrict__ x, __half* __restrict__ xh) {
    size_t i = ((size_t)blockIdx.x * 256 + threadIdx.x) * 4;
    float4 v = *(const float4*)&x[i];
    __half2 h0 = __floats2half2_rn(v.x, v.y);
    __half2 h1 = __floats2half2_rn(v.z, v.w);
    *(uint2*)&xh[i] = make_uint2(h2u(h0), h2u(h1));
}

// ---------------------------------------------------------------------------
// Split-K(4) reduce + bias + LayerNorm -> src (fp16). grid 256, 256 thr.
// ---------------------------------------------------------------------------
__global__ void reduce_ln(const float* __restrict__ part, const float* __restrict__ bias,
                          const float* __restrict__ g, const float* __restrict__ bb,
                          __half* __restrict__ out) {
    int lane = threadIdx.x & 31, w = threadIdx.x >> 5;
    int row = blockIdx.x * 8 + w;
    float v[8];
#pragma unroll
    for (int j = 0; j < 8; j++) {
        int c = lane + j * 32;
        float s = 0.f;
#pragma unroll
        for (int ks = 0; ks < 4; ks++)
            s += part[((size_t)ks * 2048 + row) * 256 + c];
        v[j] = s + bias[c];
    }
    float sum = 0.f;
#pragma unroll
    for (int j = 0; j < 8; j++) sum += v[j];
#pragma unroll
    for (int o = 16; o; o >>= 1) sum += __shfl_xor_sync(0xffffffffu, sum, o);
    float mean = sum * (1.f / 256.f);
    float ss = 0.f;
#pragma unroll
    for (int j = 0; j < 8; j++) { float d = v[j] - mean; ss += d * d; }
#pragma unroll
    for (int o = 16; o; o >>= 1) ss += __shfl_xor_sync(0xffffffffu, ss, o);
    float inv = rsqrtf(ss * (1.f / 256.f) + EPS_LN);
#pragma unroll
    for (int j = 0; j < 8; j++) {
        int c = lane + j * 32;
        out[(size_t)row * 256 + c] = __float2half_rn((v[j] - mean) * inv * g[c] + bb[c]);
    }
}

// ---------------------------------------------------------------------------
// fp16 mma.sync m16n8k16 GEMM. BM=128, BN=NB, BK=32 halfs, 256 threads.
// A and B both fp16 in gmem. OUTH: fp16 output (epilogue packs).
// MODE: 0=plain, 1=concat(A0,A1), 2=conv gather + split-K(z), 3=fused k/v(z)
// EPI: 0 plain, 1 elu+1, 2 relu, 3 LN, 4 LN+resid
// ---------------------------------------------------------------------------
#define EPI_PLAIN    0
#define EPI_ELU1     1
#define EPI_RELU     2
#define EPI_LN       3
#define EPI_LN_RESID 4

#define RSTRIDE_H 40
#define A_ROWS    128

__host__ __device__ constexpr int stage_halfs(int NB) { return (128 + NB) * RSTRIDE_H; }
__host__ __device__ constexpr int smem_req(int NB) {
    int mainloop = 2 * stage_halfs(NB) * 2;
    int epi = (128 * (NB + 4) + 256) * 4;
    return mainloop > epi ? mainloop : epi;
}

template <int EPI, int MODE, int NB, bool OUTH>
__global__ __launch_bounds__(256, (NB == 128 ? 2 : 1))
void mma_gemm(const __half* __restrict__ A0, const __half* __restrict__ A1,
              const __half* __restrict__ Bw, void* __restrict__ Cv,
              int Kloc, int KB, int Ntot,
              const float* __restrict__ gamma, const float* __restrict__ beta,
              const float* __restrict__ resid,
              const __half* __restrict__ Bw2, void* __restrict__ C2v) {
    extern __shared__ __half dsm_h[];

    constexpr int WM    = (NB == 256) ? 2 : 4;
    constexpr int MF    = 128 / WM / 16;
    constexpr int MROWS = 128 / WM;
    constexpr int NBLD  = NB / 64;
    constexpr int STAGE = stage_halfs(NB);
    constexpr int EPIST = NB + 4;

    const int tid  = threadIdx.x;
    const int lane = tid & 31;
    const int wid  = tid >> 5;
    const int g    = lane >> 2;
    const int t    = lane & 3;
    const int warp_m = wid % WM;
    const int warp_n = wid / WM;

    const int mtile = blockIdx.x * 128;
    int ncol0 = blockIdx.y * NB, kstart = 0;
    const __half* Bsrc = Bw;
    void* Cout = Cv;
    size_t coff = 0;
    if (MODE == 2) { kstart = blockIdx.z * 1024; coff = (size_t)blockIdx.z * 2048 * 256; }
    if (MODE == 3) { if (blockIdx.z) { Bsrc = Bw2; Cout = C2v; } }
    const int KT = Kloc / 32;

    float acc[MF][8][4];
#pragma unroll
    for (int i = 0; i < MF; i++)
#pragma unroll
        for (int j = 0; j < 8; j++)
#pragma unroll
            for (int q = 0; q < 4; q++) acc[i][j][q] = 0.f;

    uint4 rA[2], rB[NBLD];

    auto ldg_tile = [&](int kt) {
        const int kbase = kstart + kt * 32;
        // A: 128 rows x 32 halfs = 512 uint4; 2 per thread
#pragma unroll
        for (int p = 0; p < 2; p++) {
            int idx = p * 256 + tid;
            int m = idx >> 2, c = idx & 3;
            int kk = kbase + c * 8;
            const __half* gp;
            if (MODE == 2) {
                int mg = mtile + m;
                int b = mg >> 8, s5 = mg & 255;
                int rr = kk >> 8, i = kk & 255;
                int n = (((s5 >> 4) * 4 + (rr >> 2)) << 6) + ((s5 & 15) << 2) + (rr & 3);
                gp = A0 + (((size_t)b << 12) + n) * 256 + i;
            } else if (MODE == 1) {
                gp = (kk < 256) ? (A0 + (size_t)(mtile + m) * 256 + kk)
                                : (A1 + (size_t)(mtile + m) * 256 + (kk - 256));
            } else {
                gp = A0 + (size_t)(mtile + m) * Kloc + kk;
            }
            rA[p] = *(const uint4*)gp;
        }
        // B: NB rows x 32 halfs
#pragma unroll
        for (int p = 0; p < NBLD; p++) {
            int idx = p * 256 + tid;
            int n = idx >> 2, c = idx & 3;
            rB[p] = *(const uint4*)(Bsrc + (size_t)(ncol0 + n) * KB + kbase + c * 8);
        }
    };
    auto sts_tile = [&](int s) {
        __half* sA = dsm_h + s * STAGE;
        __half* sB = sA + A_ROWS * RSTRIDE_H;
#pragma unroll
        for (int p = 0; p < 2; p++) {
            int idx = p * 256 + tid;
            int m = idx >> 2, c = idx & 3;
            *(uint4*)&sA[m * RSTRIDE_H + c * 8] = rA[p];
        }
#pragma unroll
        for (int p = 0; p < NBLD; p++) {
            int idx = p * 256 + tid;
            int n = idx >> 2, c = idx & 3;
            *(uint4*)&sB[n * RSTRIDE_H + c * 8] = rB[p];
        }
    };

    int arow[MF], brow[8];
#pragma unroll
    for (int mf = 0; mf < MF; mf++) arow[mf] = (warp_m * MROWS + mf * 16 + g) * 20;
#pragma unroll
    for (int nf = 0; nf < 8; nf++) brow[nf] = (warp_n * 64 + nf * 8 + g) * 20;

    // prologue
    ldg_tile(0);
    sts_tile(0);
    if (KT > 1) ldg_tile(1);
    __syncthreads();

    for (int kt = 0; kt < KT; kt++) {
        if (kt + 1 < KT) {
            sts_tile((kt + 1) & 1);
            if (kt + 2 < KT) ldg_tile(kt + 2);
            __syncthreads();
        }
        const uint32_t* As2 = (const uint32_t*)(dsm_h + (kt & 1) * STAGE);
        const uint32_t* Bs2 = As2 + A_ROWS * 20;
#pragma unroll
        for (int ks = 0; ks < 2; ks++) {
            const int base = ks * 8 + t;
            uint32_t a[MF][4], b[8][2];
#pragma unroll
            for (int mf = 0; mf < MF; mf++) {
                a[mf][0] = As2[arow[mf] + base];
                a[mf][1] = As2[arow[mf] + 160 + base];
                a[mf][2] = As2[arow[mf] + base + 4];
                a[mf][3] = As2[arow[mf] + 160 + base + 4];
            }
#pragma unroll
            for (int nf = 0; nf < 8; nf++) {
                b[nf][0] = Bs2[brow[nf] + base];
                b[nf][1] = Bs2[brow[nf] + base + 4];
            }
#pragma unroll
            for (int mf = 0; mf < MF; mf++)
#pragma unroll
                for (int nf = 0; nf < 8; nf++)
                    mma16(acc[mf][nf], a[mf], b[nf]);
        }
        __syncthreads();
    }

    // ---- epilogue: stage accumulators to smem (fp32 view) ----
    float* sepi   = (float*)dsm_h;
    float* s_mean = sepi + 128 * EPIST;
    float* s_inv  = s_mean + 128;
    const bool doAct = (MODE != 3) || (blockIdx.z == 0);

#pragma unroll
    for (int mf = 0; mf < MF; mf++) {
        int r0 = warp_m * MROWS + mf * 16 + g;
#pragma unroll
        for (int nf = 0; nf < 8; nf++) {
            int c0 = warp_n * 64 + nf * 8 + 2 * t;
            float v0 = acc[mf][nf][0], v1 = acc[mf][nf][1];
            float v2 = acc[mf][nf][2], v3 = acc[mf][nf][3];
            if (EPI == EPI_ELU1 && doAct) {
                v0 = (v0 > 0.f) ? v0 + 1.f : __expf(v0);
                v1 = (v1 > 0.f) ? v1 + 1.f : __expf(v1);
                v2 = (v2 > 0.f) ? v2 + 1.f : __expf(v2);
                v3 = (v3 > 0.f) ? v3 + 1.f : __expf(v3);
            }
            if (EPI == EPI_RELU) {
                v0 = fmaxf(v0, 0.f); v1 = fmaxf(v1, 0.f);
                v2 = fmaxf(v2, 0.f); v3 = fmaxf(v3, 0.f);
            }
            *(float2*)&sepi[r0 * EPIST + c0]       = make_float2(v0, v1);
            *(float2*)&sepi[(r0 + 8) * EPIST + c0] = make_float2(v2, v3);
        }
    }
    __syncthreads();

    if ((EPI == EPI_LN || EPI == EPI_LN_RESID) && tid < 128) {
        const float* rowp = sepi + tid * EPIST;
        float sum = 0.f, ss = 0.f;
#pragma unroll 8
        for (int j = 0; j < NB / 4; j++) {
            float4 v = *(const float4*)&rowp[j * 4];
            sum += v.x + v.y + v.z + v.w;
            ss  += v.x * v.x + v.y * v.y + v.z * v.z + v.w * v.w;
        }
        float mean = sum * (1.f / 256.f);
        float var  = ss * (1.f / 256.f) - mean * mean;
        s_mean[tid] = mean;
        s_inv[tid]  = rsqrtf(var + EPS_LN);
    }
    if (EPI == EPI_LN || EPI == EPI_LN_RESID) __syncthreads();

#pragma unroll 4
    for (int p = 0; p < NB / 8; p++) {
        int idx4 = p * 256 + tid;
        int row = idx4 / (NB / 4);
        int c4  = (idx4 % (NB / 4)) << 2;
        float4 v = *(const float4*)&sepi[row * EPIST + c4];
        if (EPI == EPI_LN || EPI == EPI_LN_RESID) {
            float m = s_mean[row], iv = s_inv[row];
            float4 gm = *(const float4*)&gamma[c4];
            float4 bt = *(const float4*)&beta[c4];
            v.x = (v.x - m) * iv * gm.x + bt.x;
            v.y = (v.y - m) * iv * gm.y + bt.y;
            v.z = (v.z - m) * iv * gm.z + bt.z;
            v.w = (v.w - m) * iv * gm.w + bt.w;
            if (EPI == EPI_LN_RESID) {
                float4 r = *(const float4*)&resid[(size_t)(mtile + row) * 256 + c4];
                v.x += r.x; v.y += r.y; v.z += r.z; v.w += r.w;
            }
        }
        size_t off = coff + (size_t)(mtile + row) * Ntot + ncol0 + c4;
        if (OUTH) {
            __half2 h0 = __floats2half2_rn(v.x, v.y);
            __half2 h1 = __floats2half2_rn(v.z, v.w);
            *(uint2*)&((__half*)Cout)[off] = make_uint2(h2u(h0), h2u(h1));
        } else {
            *(float4*)&((float*)Cout)[off] = v;
        }
    }
}

// ---------------------------------------------------------------------------
// KV = sum_s K^T V, Ksum = sum_s K. fp16 inputs, fp32 math. grid 64, 256 thr.
// ---------------------------------------------------------------------------
__global__ void kv_kernel(const __half* __restrict__ kmat, const __half* __restrict__ vmat,
                          float* __restrict__ kv, float* __restrict__ ksum) {
    __shared__ float Ks[128][32];
    __shared__ float Vs[128][32];
    int bh = blockIdx.x, b = bh >> 3, h = bh & 7;
    int tid = threadIdx.x;
    int d = tid & 31, vg = tid >> 5;
    float acc0 = 0.f, acc1 = 0.f, acc2 = 0.f, acc3 = 0.f, ka = 0.f;

    for (int ch = 0; ch < 2; ch++) {
        int sl = tid >> 3, c4 = tid & 7;
#pragma unroll
        for (int ss = 0; ss < 4; ss++) {
            int srow = ch * 128 + ss * 32 + sl;
            size_t base = ((size_t)(b * 256 + srow)) * 256 + h * 32 + c4 * 4;
            uint2 kw = *(const uint2*)&kmat[base];
            uint2 vw = *(const uint2*)&vmat[base];
            __half2* kh = (__half2*)&kw;
            __half2* vh = (__half2*)&vw;
            float2 k0 = __half22float2(kh[0]), k1 = __half22float2(kh[1]);
            float2 w0 = __half22float2(vh[0]), w1 = __half22float2(vh[1]);
            Ks[ss * 32 + sl][c4 * 4 + 0] = k0.x; Ks[ss * 32 + sl][c4 * 4 + 1] = k0.y;
            Ks[ss * 32 + sl][c4 * 4 + 2] = k1.x; Ks[ss * 32 + sl][c4 * 4 + 3] = k1.y;
            Vs[ss * 32 + sl][c4 * 4 + 0] = w0.x; Vs[ss * 32 + sl][c4 * 4 + 1] = w0.y;
            Vs[ss * 32 + sl][c4 * 4 + 2] = w1.x; Vs[ss * 32 + sl][c4 * 4 + 3] = w1.y;
        }
        __syncthreads();
#pragma unroll 4
        for (int s = 0; s < 128; s++) {
            float kd = Ks[s][d];
            float4 vv = *(float4*)&Vs[s][vg * 4];
            acc0 += kd * vv.x; acc1 += kd * vv.y;
            acc2 += kd * vv.z; acc3 += kd * vv.w;
            if (vg == 0) ka += kd;
        }
        __syncthreads();
    }
    float* kvp = kv + ((size_t)bh * 32 + d) * 32 + vg * 4;
    kvp[0] = acc0; kvp[1] = acc1; kvp[2] = acc2; kvp[3] = acc3;
    if (vg == 0) ksum[bh * 32 + d] = ka;
}

// ---------------------------------------------------------------------------
// msg = z * (Q @ KV), z = 1/(Q.Ksum + eps). fp16 q in, fp16 msg out.
// ---------------------------------------------------------------------------
__global__ void attn_apply(const __half* __restrict__ qmat, const float* __restrict__ kv,
                           const float* __restrict__ ksum, __half* __restrict__ msg) {
    __shared__ float Qs[16 * 256];
    __shared__ float zs[16][8];
    __shared__ float ksums[256];
    int b = blockIdx.y;
    int t0 = blockIdx.x * 16;
    int tid = threadIdx.x;

    const uint4* qsrc = (const uint4*)(qmat + ((size_t)b * 4096 + t0) * 256); // 512 uint4
#pragma unroll
    for (int q = 0; q < 2; q++) {
        int idx = tid + q * 256;
        uint4 w = qsrc[idx];
        __half2* hp = (__half2*)&w;
        int base = idx * 8;
#pragma unroll
        for (int j = 0; j < 4; j++) {
            float2 f = __half22float2(hp[j]);
            Qs[base + 2 * j]     = f.x;
            Qs[base + 2 * j + 1] = f.y;
        }
    }
    ksums[tid] = ksum[b * 256 + tid];
    __syncthreads();

    if (tid < 128) {
        int t = tid >> 3, h = tid & 7;
        const float* qrow = Qs + t * 256 + h * 32;
        const float* kr = ksums + h * 32;
        float z = 0.f;
#pragma unroll
        for (int dd = 0; dd < 32; dd++) z += qrow[dd] * kr[dd];
        zs[t][h] = 1.f / (z + EPS_ATT);
    }
    __syncthreads();

    int h = tid >> 5, v = tid & 31;
    float kvr[32];
#pragma unroll
    for (int dd = 0; dd < 32; dd++)
        kvr[dd] = kv[(((size_t)(b * 8 + h)) * 32 + dd) * 32 + v];
#pragma unroll 2
    for (int t = 0; t < 16; t++) {
        const float* qrow = Qs + t * 256 + h * 32;
        float m = 0.f;
#pragma unroll
        for (int dd = 0; dd < 32; dd++) m += qrow[dd] * kvr[dd];
        msg[((size_t)b * 4096 + t0 + t) * 256 + tid] = __float2half_rn(m * zs[t][h]);
    }
}

// ---------------------------------------------------------------------------
// Launch
// ---------------------------------------------------------------------------
extern "C" void kernel_launch(void* const* d_in, const int* in_sizes, int n_in,
                              void* d_out, int out_size) {
    const float* x      = (const float*)d_in[0];
    const float* sr_w   = (const float*)d_in[1];
    const float* sr_b   = (const float*)d_in[2];
    const float* norm_g = (const float*)d_in[3];
    const float* norm_b = (const float*)d_in[4];
    const float* wq     = (const float*)d_in[5];
    const float* wk     = (const float*)d_in[6];
    const float* wv     = (const float*)d_in[7];
    const float* wm     = (const float*)d_in[8];
    const float* w1     = (const float*)d_in[9];
    const float* w2     = (const float*)d_in[10];
    const float* n1g    = (const float*)d_in[11];
    const float* n1b    = (const float*)d_in[12];
    const float* n2g    = (const float*)d_in[13];
    const float* n2b    = (const float*)d_in[14];
    float* out = (float*)d_out;

    __half *wsrB, *wqr, *wkr, *wvr, *wmr, *w1r, *w2r;
    __half *xh, *src, *kmat, *vmat, *qmat, *msg, *msgn, *hmid;
    float *part, *kvp, *ksump;
    cudaGetSymbolAddress((void**)&wsrB, g_wsrB);
    cudaGetSymbolAddress((void**)&wqr,  g_wqr);
    cudaGetSymbolAddress((void**)&wkr,  g_wkr);
    cudaGetSymbolAddress((void**)&wvr,  g_wvr);
    cudaGetSymbolAddress((void**)&wmr,  g_wmr);
    cudaGetSymbolAddress((void**)&w1r,  g_w1r);
    cudaGetSymbolAddress((void**)&w2r,  g_w2r);
    cudaGetSymbolAddress((void**)&xh,   g_xh);
    cudaGetSymbolAddress((void**)&part, g_part);
    cudaGetSymbolAddress((void**)&src,  g_src);
    cudaGetSymbolAddress((void**)&kmat, g_kmat);
    cudaGetSymbolAddress((void**)&vmat, g_vmat);
    cudaGetSymbolAddress((void**)&kvp,  g_kv);
    cudaGetSymbolAddress((void**)&ksump,g_ksum);
    cudaGetSymbolAddress((void**)&qmat, g_qmat);
    cudaGetSymbolAddress((void**)&msg,  g_msg);
    cudaGetSymbolAddress((void**)&msgn, g_msgn);
    cudaGetSymbolAddress((void**)&hmid, g_hmid);

    constexpr int SM128 = smem_req(128);
    constexpr int SM256 = smem_req(256);
    cudaFuncSetAttribute(mma_gemm<EPI_PLAIN, 2, 128, false>,   cudaFuncAttributeMaxDynamicSharedMemorySize, SM128);
    cudaFuncSetAttribute(mma_gemm<EPI_ELU1, 3, 128, true>,     cudaFuncAttributeMaxDynamicSharedMemorySize, SM128);
    cudaFuncSetAttribute(mma_gemm<EPI_ELU1, 0, 128, true>,     cudaFuncAttributeMaxDynamicSharedMemorySize, SM128);
    cudaFuncSetAttribute(mma_gemm<EPI_RELU, 1, 128, true>,     cudaFuncAttributeMaxDynamicSharedMemorySize, SM128);
    cudaFuncSetAttribute(mma_gemm<EPI_LN, 0, 256, true>,       cudaFuncAttributeMaxDynamicSharedMemorySize, SM256);
    cudaFuncSetAttribute(mma_gemm<EPI_LN_RESID, 0, 256, false>,cudaFuncAttributeMaxDynamicSharedMemorySize, SM256);

    // weight prep + x fp16 copy
    repack_srw<<<256, 256>>>(sr_w, wsrB);
    round_weights<<<2560, 256>>>(wq, wk, wv, wm, w1, w2, wqr, wkr, wvr, wmr, w1r, w2r);
    x_to_half<<<8192, 256>>>(x, xh);

    // conv-as-GEMM (split-K=4 on z) + reduce/bias/LN -> src (fp16)
    mma_gemm<EPI_PLAIN, 2, 128, false><<<dim3(16, 2, 4), 256, SM128>>>(
        xh, nullptr, wsrB, part, 1024, 4096, 256, nullptr, nullptr, nullptr, nullptr, nullptr);
    reduce_ln<<<256, 256>>>(part, sr_b, norm_g, norm_b, src);

    // fused k/v projections (M=2048), fp16 out
    mma_gemm<EPI_ELU1, 3, 128, true><<<dim3(16, 2, 2), 256, SM128>>>(
        src, nullptr, wkr, kmat, 256, 256, 256, nullptr, nullptr, nullptr, wvr, vmat);

    kv_kernel<<<64, 256>>>(kmat, vmat, kvp, ksump);

    // q projection (M=32768) -> elu+1, fp16 out
    mma_gemm<EPI_ELU1, 0, 128, true><<<dim3(256, 2), 256, SM128>>>(
        xh, nullptr, wqr, qmat, 256, 256, 256, nullptr, nullptr, nullptr, nullptr, nullptr);

    attn_apply<<<dim3(256, 8), 256>>>(qmat, kvp, ksump, msg);

    // merge projection + LN1, fp16 out
    mma_gemm<EPI_LN, 0, 256, true><<<dim3(256, 1), 256, SM256>>>(
        msg, nullptr, wmr, msgn, 256, 256, 256, n1g, n1b, nullptr, nullptr, nullptr);

    // MLP1: concat(xh, msgn) @ w1^T -> relu, fp16 out
    mma_gemm<EPI_RELU, 1, 128, true><<<dim3(256, 4), 256, SM128>>>(
        xh, msgn, w1r, hmid, 512, 512, 512, nullptr, nullptr, nullptr, nullptr, nullptr);

    // MLP2 + LN2 + residual -> out (fp32)
    mma_gemm<EPI_LN_RESID, 0, 256, false><<<dim3(256, 1), 256, SM256>>>(
        hmid, nullptr, w2r, out, 512, 512, 256, n2g, n2b, x, nullptr, nullptr);
}

// round 11
// speedup vs baseline: 1.6562x; 1.0532x over previous
#include <cuda_runtime.h>
#include <cuda_fp16.h>
#include <math.h>
#include <stdint.h>

#define EPS_LN  1e-5f
#define EPS_ATT 1e-6f

// ---------------------------------------------------------------------------
// helpers
// ---------------------------------------------------------------------------
__device__ __forceinline__ uint32_t smem_u32(const void* p) {
    uint32_t a;
    asm("{ .reg .u64 t; cvta.to.shared.u64 t, %1; cvt.u32.u64 %0, t; }" : "=r"(a) : "l"(p));
    return a;
}
__device__ __forceinline__ void mma16(float* c, const uint32_t* a, const uint32_t* b) {
    asm volatile(
        "mma.sync.aligned.m16n8k16.row.col.f32.f16.f16.f32 "
        "{%0,%1,%2,%3}, {%4,%5,%6,%7}, {%8,%9}, {%0,%1,%2,%3};"
        : "+f"(c[0]), "+f"(c[1]), "+f"(c[2]), "+f"(c[3])
        : "r"(a[0]), "r"(a[1]), "r"(a[2]), "r"(a[3]), "r"(b[0]), "r"(b[1]));
}
__device__ __forceinline__ void ldsm_x4(uint32_t& r0, uint32_t& r1, uint32_t& r2, uint32_t& r3,
                                        uint32_t addr) {
    asm volatile("ldmatrix.sync.aligned.m8n8.x4.shared.b16 {%0,%1,%2,%3}, [%4];"
        : "=r"(r0), "=r"(r1), "=r"(r2), "=r"(r3) : "r"(addr));
}
__device__ __forceinline__ uint32_t h2u(__half2 h) { return *(uint32_t*)&h; }

// ---------------------------------------------------------------------------
// Scratch
// ---------------------------------------------------------------------------
__device__ __half g_wsrB[256 * 4096];
__device__ __half g_wqr [256 * 256];
__device__ __half g_wkr [256 * 256];
__device__ __half g_wvr [256 * 256];
__device__ __half g_wmr [256 * 256];
__device__ __half g_w1r [512 * 512];
__device__ __half g_w2r [256 * 512];
__device__ __half g_xh  [8 * 4096 * 256];
__device__ float  g_part[8 * 2048 * 256];
__device__ __half g_src [2048 * 256];
__device__ __half g_kmat[2048 * 256];
__device__ __half g_vmat[2048 * 256];
__device__ float  g_kv  [64 * 32 * 32];
__device__ float  g_ksum[64 * 32];
__device__ __half g_qmat[8 * 4096 * 256];
__device__ __half g_msg [8 * 4096 * 256];
__device__ __half g_msgn[8 * 4096 * 256];
__device__ __half g_hmid[8 * 4096 * 512];

__global__ void repack_srw(const float* __restrict__ w, __half* __restrict__ wb) {
    int idx = blockIdx.x * blockDim.x + threadIdx.x;
    int o = idx >> 8, i = idx & 255;
    const float* p = w + ((size_t)(o * 256 + i)) * 16;
#pragma unroll
    for (int rr = 0; rr < 16; rr++)
        wb[(size_t)o * 4096 + rr * 256 + i] = __float2half_rn(p[rr]);
}

__global__ void round_weights(const float* __restrict__ wq, const float* __restrict__ wk,
                              const float* __restrict__ wv, const float* __restrict__ wm,
                              const float* __restrict__ w1, const float* __restrict__ w2,
                              __half* __restrict__ oq, __half* __restrict__ ok,
                              __half* __restrict__ ov, __half* __restrict__ om,
                              __half* __restrict__ o1, __half* __restrict__ o2) {
    int bid = blockIdx.x;
    const float* src; __half* dst; int base;
    if      (bid < 256)  { src = wq; dst = oq; base = 0; }
    else if (bid < 512)  { src = wk; dst = ok; base = 256; }
    else if (bid < 768)  { src = wv; dst = ov; base = 512; }
    else if (bid < 1024) { src = wm; dst = om; base = 768; }
    else if (bid < 2048) { src = w1; dst = o1; base = 1024; }
    else                 { src = w2; dst = o2; base = 2048; }
    int idx = (bid - base) * 256 + threadIdx.x;
    dst[idx] = __float2half_rn(src[idx]);
}

__global__ void x_to_half(const float* __restrict__ x, __half* __restrict__ xh) {
    size_t i = ((size_t)blockIdx.x * 256 + threadIdx.x) * 4;
    float4 v = *(const float4*)&x[i];
    __half2 h0 = __floats2half2_rn(v.x, v.y);
    __half2 h1 = __floats2half2_rn(v.z, v.w);
    *(uint2*)&xh[i] = make_uint2(h2u(h0), h2u(h1));
}

// ---------------------------------------------------------------------------
// Split-K(8) reduce + bias + LayerNorm -> src (fp16). grid 256, 256 thr.
// ---------------------------------------------------------------------------
__global__ void reduce_ln(const float* __restrict__ part, const float* __restrict__ bias,
                          const float* __restrict__ g, const float* __restrict__ bb,
                          __half* __restrict__ out) {
    int lane = threadIdx.x & 31, w = threadIdx.x >> 5;
    int row = blockIdx.x * 8 + w;
    float v[8];
#pragma unroll
    for (int j = 0; j < 8; j++) {
        int c = lane + j * 32;
        float s = 0.f;
#pragma unroll
        for (int ks = 0; ks < 8; ks++)
            s += part[((size_t)ks * 2048 + row) * 256 + c];
        v[j] = s + bias[c];
    }
    float sum = 0.f;
#pragma unroll
    for (int j = 0; j < 8; j++) sum += v[j];
#pragma unroll
    for (int o = 16; o; o >>= 1) sum += __shfl_xor_sync(0xffffffffu, sum, o);
    float mean = sum * (1.f / 256.f);
    float ss = 0.f;
#pragma unroll
    for (int j = 0; j < 8; j++) { float d = v[j] - mean; ss += d * d; }
#pragma unroll
    for (int o = 16; o; o >>= 1) ss += __shfl_xor_sync(0xffffffffu, ss, o);
    float inv = rsqrtf(ss * (1.f / 256.f) + EPS_LN);
#pragma unroll
    for (int j = 0; j < 8; j++) {
        int c = lane + j * 32;
        out[(size_t)row * 256 + c] = __float2half_rn((v[j] - mean) * inv * g[c] + bb[c]);
    }
}

// ---------------------------------------------------------------------------
// fp16 mma GEMM with ldmatrix fragments. BM=128, BN=NB, BK=32 halfs, 256 thr.
// ---------------------------------------------------------------------------
#define EPI_PLAIN    0
#define EPI_ELU1     1
#define EPI_RELU     2
#define EPI_LN       3
#define EPI_LN_RESID 4

#define RSTRIDE_H 40
#define A_ROWS    128

__host__ __device__ constexpr int stage_halfs(int NB) { return (128 + NB) * RSTRIDE_H; }
__host__ __device__ constexpr int smem_req(int NB) {
    int mainloop = 2 * stage_halfs(NB) * 2;
    int epi = (128 * (NB + 4) + 256) * 4;
    return mainloop > epi ? mainloop : epi;
}

template <int EPI, int MODE, int NB, bool OUTH>
__global__ __launch_bounds__(256, (NB == 128 ? 2 : 1))
void mma_gemm(const __half* __restrict__ A0, const __half* __restrict__ A1,
              const __half* __restrict__ Bw, void* __restrict__ Cv,
              int Kloc, int KB, int Ntot,
              const float* __restrict__ gamma, const float* __restrict__ beta,
              const float* __restrict__ resid,
              const __half* __restrict__ Bw2, void* __restrict__ C2v) {
    extern __shared__ __half dsm_h[];

    constexpr int WM    = (NB == 256) ? 2 : 4;
    constexpr int MF    = 128 / WM / 16;
    constexpr int MROWS = 128 / WM;
    constexpr int NBLD  = NB / 64;
    constexpr int STAGE = stage_halfs(NB);
    constexpr int EPIST = NB + 4;

    const int tid  = threadIdx.x;
    const int lane = tid & 31;
    const int wid  = tid >> 5;
    const int g    = lane >> 2;
    const int t    = lane & 3;
    const int warp_m = wid % WM;
    const int warp_n = wid / WM;

    const int mtile = blockIdx.x * 128;
    int ncol0 = blockIdx.y * NB, kstart = 0;
    const __half* Bsrc = Bw;
    void* Cout = Cv;
    size_t coff = 0;
    if (MODE == 2) { kstart = blockIdx.z * 512; coff = (size_t)blockIdx.z * 2048 * 256; }
    if (MODE == 3) { if (blockIdx.z) { Bsrc = Bw2; Cout = C2v; } }
    const int KT = Kloc / 32;

    float acc[MF][8][4];
#pragma unroll
    for (int i = 0; i < MF; i++)
#pragma unroll
        for (int j = 0; j < 8; j++)
#pragma unroll
            for (int q = 0; q < 4; q++) acc[i][j][q] = 0.f;

    uint4 rA[2], rB[NBLD];

    auto ldg_tile = [&](int kt) {
        const int kbase = kstart + kt * 32;
#pragma unroll
        for (int p = 0; p < 2; p++) {
            int idx = p * 256 + tid;
            int m = idx >> 2, c = idx & 3;
            int kk = kbase + c * 8;
            const __half* gp;
            if (MODE == 2) {
                int mg = mtile + m;
                int b = mg >> 8, s5 = mg & 255;
                int rr = kk >> 8, i = kk & 255;
                int n = (((s5 >> 4) * 4 + (rr >> 2)) << 6) + ((s5 & 15) << 2) + (rr & 3);
                gp = A0 + (((size_t)b << 12) + n) * 256 + i;
            } else if (MODE == 1) {
                gp = (kk < 256) ? (A0 + (size_t)(mtile + m) * 256 + kk)
                                : (A1 + (size_t)(mtile + m) * 256 + (kk - 256));
            } else {
                gp = A0 + (size_t)(mtile + m) * Kloc + kk;
            }
            rA[p] = *(const uint4*)gp;
        }
#pragma unroll
        for (int p = 0; p < NBLD; p++) {
            int idx = p * 256 + tid;
            int n = idx >> 2, c = idx & 3;
            rB[p] = *(const uint4*)(Bsrc + (size_t)(ncol0 + n) * KB + kbase + c * 8);
        }
    };
    auto sts_tile = [&](int s) {
        __half* sA = dsm_h + s * STAGE;
        __half* sB = sA + A_ROWS * RSTRIDE_H;
#pragma unroll
        for (int p = 0; p < 2; p++) {
            int idx = p * 256 + tid;
            int m = idx >> 2, c = idx & 3;
            *(uint4*)&sA[m * RSTRIDE_H + c * 8] = rA[p];
        }
#pragma unroll
        for (int p = 0; p < NBLD; p++) {
            int idx = p * 256 + tid;
            int n = idx >> 2, c = idx & 3;
            *(uint4*)&sB[n * RSTRIDE_H + c * 8] = rB[p];
        }
    };

    // ldmatrix lane base offsets (bytes within stage)
    const uint32_t smb = smem_u32(dsm_h);
    const uint32_t a_l = ((warp_m * MROWS + (lane & 7) + ((lane >> 3) & 1) * 8) * RSTRIDE_H
                          + ((lane >> 4) & 1) * 8) * 2;
    const uint32_t b_l = ((A_ROWS + warp_n * 64 + (lane & 7) + ((lane >> 4) & 1) * 8) * RSTRIDE_H
                          + ((lane >> 3) & 1) * 8) * 2;

    // prologue
    ldg_tile(0);
    sts_tile(0);
    if (KT > 1) ldg_tile(1);
    __syncthreads();

    for (int kt = 0; kt < KT; kt++) {
        if (kt + 1 < KT) {
            sts_tile((kt + 1) & 1);
            if (kt + 2 < KT) ldg_tile(kt + 2);
            __syncthreads();
        }
        const uint32_t sbase = smb + (uint32_t)(kt & 1) * (STAGE * 2);
#pragma unroll
        for (int ks = 0; ks < 2; ks++) {
            const uint32_t koffB = ks * 32;      // 16 halfs
            uint32_t a[MF][4], b[8][2];
#pragma unroll
            for (int mf = 0; mf < MF; mf++)
                ldsm_x4(a[mf][0], a[mf][1], a[mf][2], a[mf][3],
                        sbase + a_l + mf * (16 * RSTRIDE_H * 2) + koffB);
#pragma unroll
            for (int p = 0; p < 4; p++)
                ldsm_x4(b[2 * p][0], b[2 * p][1], b[2 * p + 1][0], b[2 * p + 1][1],
                        sbase + b_l + p * (16 * RSTRIDE_H * 2) + koffB);
#pragma unroll
            for (int mf = 0; mf < MF; mf++)
#pragma unroll
                for (int nf = 0; nf < 8; nf++)
                    mma16(acc[mf][nf], a[mf], b[nf]);
        }
        __syncthreads();
    }

    // ---- epilogue ----
    float* sepi   = (float*)dsm_h;
    float* s_mean = sepi + 128 * EPIST;
    float* s_inv  = s_mean + 128;
    const bool doAct = (MODE != 3) || (blockIdx.z == 0);

#pragma unroll
    for (int mf = 0; mf < MF; mf++) {
        int r0 = warp_m * MROWS + mf * 16 + g;
#pragma unroll
        for (int nf = 0; nf < 8; nf++) {
            int c0 = warp_n * 64 + nf * 8 + 2 * t;
            float v0 = acc[mf][nf][0], v1 = acc[mf][nf][1];
            float v2 = acc[mf][nf][2], v3 = acc[mf][nf][3];
            if (EPI == EPI_ELU1 && doAct) {
                v0 = (v0 > 0.f) ? v0 + 1.f : __expf(v0);
                v1 = (v1 > 0.f) ? v1 + 1.f : __expf(v1);
                v2 = (v2 > 0.f) ? v2 + 1.f : __expf(v2);
                v3 = (v3 > 0.f) ? v3 + 1.f : __expf(v3);
            }
            if (EPI == EPI_RELU) {
                v0 = fmaxf(v0, 0.f); v1 = fmaxf(v1, 0.f);
                v2 = fmaxf(v2, 0.f); v3 = fmaxf(v3, 0.f);
            }
            *(float2*)&sepi[r0 * EPIST + c0]       = make_float2(v0, v1);
            *(float2*)&sepi[(r0 + 8) * EPIST + c0] = make_float2(v2, v3);
        }
    }
    __syncthreads();

    if ((EPI == EPI_LN || EPI == EPI_LN_RESID) && tid < 128) {
        const float* rowp = sepi + tid * EPIST;
        float sum = 0.f, ss = 0.f;
#pragma unroll 8
        for (int j = 0; j < NB / 4; j++) {
            float4 v = *(const float4*)&rowp[j * 4];
            sum += v.x + v.y + v.z + v.w;
            ss  += v.x * v.x + v.y * v.y + v.z * v.z + v.w * v.w;
        }
        float mean = sum * (1.f / 256.f);
        float var  = ss * (1.f / 256.f) - mean * mean;
        s_mean[tid] = mean;
        s_inv[tid]  = rsqrtf(var + EPS_LN);
    }
    if (EPI == EPI_LN || EPI == EPI_LN_RESID) __syncthreads();

#pragma unroll 4
    for (int p = 0; p < NB / 8; p++) {
        int idx4 = p * 256 + tid;
        int row = idx4 / (NB / 4);
        int c4  = (idx4 % (NB / 4)) << 2;
        float4 v = *(const float4*)&sepi[row * EPIST + c4];
        if (EPI == EPI_LN || EPI == EPI_LN_RESID) {
            float m = s_mean[row], iv = s_inv[row];
            float4 gm = *(const float4*)&gamma[c4];
            float4 bt = *(const float4*)&beta[c4];
            v.x = (v.x - m) * iv * gm.x + bt.x;
            v.y = (v.y - m) * iv * gm.y + bt.y;
            v.z = (v.z - m) * iv * gm.z + bt.z;
            v.w = (v.w - m) * iv * gm.w + bt.w;
            if (EPI == EPI_LN_RESID) {
                float4 r = *(const float4*)&resid[(size_t)(mtile + row) * 256 + c4];
                v.x += r.x; v.y += r.y; v.z += r.z; v.w += r.w;
            }
        }
        size_t off = coff + (size_t)(mtile + row) * Ntot + ncol0 + c4;
        if (OUTH) {
            __half2 h0 = __floats2half2_rn(v.x, v.y);
            __half2 h1 = __floats2half2_rn(v.z, v.w);
            *(uint2*)&((__half*)Cout)[off] = make_uint2(h2u(h0), h2u(h1));
        } else {
            *(float4*)&((float*)Cout)[off] = v;
        }
    }
}

// ---------------------------------------------------------------------------
// KV = sum_s K^T V, Ksum = sum_s K. fp16 in, fp32 math. grid 64, 256 thr.
// ---------------------------------------------------------------------------
__global__ void kv_kernel(const __half* __restrict__ kmat, const __half* __restrict__ vmat,
                          float* __restrict__ kv, float* __restrict__ ksum) {
    __shared__ float Ks[128][32];
    __shared__ float Vs[128][32];
    int bh = blockIdx.x, b = bh >> 3, h = bh & 7;
    int tid = threadIdx.x;
    int d = tid & 31, vg = tid >> 5;
    float acc0 = 0.f, acc1 = 0.f, acc2 = 0.f, acc3 = 0.f, ka = 0.f;

    for (int ch = 0; ch < 2; ch++) {
        int sl = tid >> 3, c4 = tid & 7;
#pragma unroll
        for (int ss = 0; ss < 4; ss++) {
            int srow = ch * 128 + ss * 32 + sl;
            size_t base = ((size_t)(b * 256 + srow)) * 256 + h * 32 + c4 * 4;
            uint2 kw = *(const uint2*)&kmat[base];
            uint2 vw = *(const uint2*)&vmat[base];
            __half2* kh = (__half2*)&kw;
            __half2* vh = (__half2*)&vw;
            float2 k0 = __half22float2(kh[0]), k1 = __half22float2(kh[1]);
            float2 w0 = __half22float2(vh[0]), w1 = __half22float2(vh[1]);
            Ks[ss * 32 + sl][c4 * 4 + 0] = k0.x; Ks[ss * 32 + sl][c4 * 4 + 1] = k0.y;
            Ks[ss * 32 + sl][c4 * 4 + 2] = k1.x; Ks[ss * 32 + sl][c4 * 4 + 3] = k1.y;
            Vs[ss * 32 + sl][c4 * 4 + 0] = w0.x; Vs[ss * 32 + sl][c4 * 4 + 1] = w0.y;
            Vs[ss * 32 + sl][c4 * 4 + 2] = w1.x; Vs[ss * 32 + sl][c4 * 4 + 3] = w1.y;
        }
        __syncthreads();
#pragma unroll 4
        for (int s = 0; s < 128; s++) {
            float kd = Ks[s][d];
            float4 vv = *(float4*)&Vs[s][vg * 4];
            acc0 += kd * vv.x; acc1 += kd * vv.y;
            acc2 += kd * vv.z; acc3 += kd * vv.w;
            if (vg == 0) ka += kd;
        }
        __syncthreads();
    }
    float* kvp = kv + ((size_t)bh * 32 + d) * 32 + vg * 4;
    kvp[0] = acc0; kvp[1] = acc1; kvp[2] = acc2; kvp[3] = acc3;
    if (vg == 0) ksum[bh * 32 + d] = ka;
}

// ---------------------------------------------------------------------------
// msg = z * (Q @ KV). fp16 q in, fp16 msg out. grid (256, 8).
// ---------------------------------------------------------------------------
__global__ void attn_apply(const __half* __restrict__ qmat, const float* __restrict__ kv,
                           const float* __restrict__ ksum, __half* __restrict__ msg) {
    __shared__ float Qs[16 * 256];
    __shared__ float zs[16][8];
    __shared__ float ksums[256];
    int b = blockIdx.y;
    int t0 = blockIdx.x * 16;
    int tid = threadIdx.x;

    const uint4* qsrc = (const uint4*)(qmat + ((size_t)b * 4096 + t0) * 256);
#pragma unroll
    for (int q = 0; q < 2; q++) {
        int idx = tid + q * 256;
        uint4 w = qsrc[idx];
        __half2* hp = (__half2*)&w;
        int base = idx * 8;
#pragma unroll
        for (int j = 0; j < 4; j++) {
            float2 f = __half22float2(hp[j]);
            Qs[base + 2 * j]     = f.x;
            Qs[base + 2 * j + 1] = f.y;
        }
    }
    ksums[tid] = ksum[b * 256 + tid];
    __syncthreads();

    if (tid < 128) {
        int t = tid >> 3, h = tid & 7;
        const float* qrow = Qs + t * 256 + h * 32;
        const float* kr = ksums + h * 32;
        float z = 0.f;
#pragma unroll
        for (int dd = 0; dd < 32; dd++) z += qrow[dd] * kr[dd];
        zs[t][h] = 1.f / (z + EPS_ATT);
    }
    __syncthreads();

    int h = tid >> 5, v = tid & 31;
    float kvr[32];
#pragma unroll
    for (int dd = 0; dd < 32; dd++)
        kvr[dd] = kv[(((size_t)(b * 8 + h)) * 32 + dd) * 32 + v];
#pragma unroll 2
    for (int t = 0; t < 16; t++) {
        const float* qrow = Qs + t * 256 + h * 32;
        float m = 0.f;
#pragma unroll
        for (int dd = 0; dd < 32; dd++) m += qrow[dd] * kvr[dd];
        msg[((size_t)b * 4096 + t0 + t) * 256 + tid] = __float2half_rn(m * zs[t][h]);
    }
}

// ---------------------------------------------------------------------------
// Launch
// ---------------------------------------------------------------------------
extern "C" void kernel_launch(void* const* d_in, const int* in_sizes, int n_in,
                              void* d_out, int out_size) {
    const float* x      = (const float*)d_in[0];
    const float* sr_w   = (const float*)d_in[1];
    const float* sr_b   = (const float*)d_in[2];
    const float* norm_g = (const float*)d_in[3];
    const float* norm_b = (const float*)d_in[4];
    const float* wq     = (const float*)d_in[5];
    const float* wk     = (const float*)d_in[6];
    const float* wv     = (const float*)d_in[7];
    const float* wm     = (const float*)d_in[8];
    const float* w1     = (const float*)d_in[9];
    const float* w2     = (const float*)d_in[10];
    const float* n1g    = (const float*)d_in[11];
    const float* n1b    = (const float*)d_in[12];
    const float* n2g    = (const float*)d_in[13];
    const float* n2b    = (const float*)d_in[14];
    float* out = (float*)d_out;

    __half *wsrB, *wqr, *wkr, *wvr, *wmr, *w1r, *w2r;
    __half *xh, *src, *kmat, *vmat, *qmat, *msg, *msgn, *hmid;
    float *part, *kvp, *ksump;
    cudaGetSymbolAddress((void**)&wsrB, g_wsrB);
    cudaGetSymbolAddress((void**)&wqr,  g_wqr);
    cudaGetSymbolAddress((void**)&wkr,  g_wkr);
    cudaGetSymbolAddress((void**)&wvr,  g_wvr);
    cudaGetSymbolAddress((void**)&wmr,  g_wmr);
    cudaGetSymbolAddress((void**)&w1r,  g_w1r);
    cudaGetSymbolAddress((void**)&w2r,  g_w2r);
    cudaGetSymbolAddress((void**)&xh,   g_xh);
    cudaGetSymbolAddress((void**)&part, g_part);
    cudaGetSymbolAddress((void**)&src,  g_src);
    cudaGetSymbolAddress((void**)&kmat, g_kmat);
    cudaGetSymbolAddress((void**)&vmat, g_vmat);
    cudaGetSymbolAddress((void**)&kvp,  g_kv);
    cudaGetSymbolAddress((void**)&ksump,g_ksum);
    cudaGetSymbolAddress((void**)&qmat, g_qmat);
    cudaGetSymbolAddress((void**)&msg,  g_msg);
    cudaGetSymbolAddress((void**)&msgn, g_msgn);
    cudaGetSymbolAddress((void**)&hmid, g_hmid);

    constexpr int SM128 = smem_req(128);
    constexpr int SM256 = smem_req(256);
    cudaFuncSetAttribute(mma_gemm<EPI_PLAIN, 2, 128, false>,   cudaFuncAttributeMaxDynamicSharedMemorySize, SM128);
    cudaFuncSetAttribute(mma_gemm<EPI_ELU1, 3, 128, true>,     cudaFuncAttributeMaxDynamicSharedMemorySize, SM128);
    cudaFuncSetAttribute(mma_gemm<EPI_ELU1, 0, 128, true>,     cudaFuncAttributeMaxDynamicSharedMemorySize, SM128);
    cudaFuncSetAttribute(mma_gemm<EPI_RELU, 1, 128, true>,     cudaFuncAttributeMaxDynamicSharedMemorySize, SM128);
    cudaFuncSetAttribute(mma_gemm<EPI_LN, 0, 256, true>,       cudaFuncAttributeMaxDynamicSharedMemorySize, SM256);
    cudaFuncSetAttribute(mma_gemm<EPI_LN_RESID, 0, 256, false>,cudaFuncAttributeMaxDynamicSharedMemorySize, SM256);

    // weight prep + x fp16 copy
    repack_srw<<<256, 256>>>(sr_w, wsrB);
    round_weights<<<2560, 256>>>(wq, wk, wv, wm, w1, w2, wqr, wkr, wvr, wmr, w1r, w2r);
    x_to_half<<<8192, 256>>>(x, xh);

    // conv-as-GEMM (split-K=8 on z) + reduce/bias/LN -> src (fp16)
    mma_gemm<EPI_PLAIN, 2, 128, false><<<dim3(16, 2, 8), 256, SM128>>>(
        xh, nullptr, wsrB, part, 512, 4096, 256, nullptr, nullptr, nullptr, nullptr, nullptr);
    reduce_ln<<<256, 256>>>(part, sr_b, norm_g, norm_b, src);

    // fused k/v projections (M=2048), fp16 out
    mma_gemm<EPI_ELU1, 3, 128, true><<<dim3(16, 2, 2), 256, SM128>>>(
        src, nullptr, wkr, kmat, 256, 256, 256, nullptr, nullptr, nullptr, wvr, vmat);

    kv_kernel<<<64, 256>>>(kmat, vmat, kvp, ksump);

    // q projection (M=32768) -> elu+1, fp16 out
    mma_gemm<EPI_ELU1, 0, 128, true><<<dim3(256, 2), 256, SM128>>>(
        xh, nullptr, wqr, qmat, 256, 256, 256, nullptr, nullptr, nullptr, nullptr, nullptr);

    attn_apply<<<dim3(256, 8), 256>>>(qmat, kvp, ksump, msg);

    // merge projection + LN1, fp16 out
    mma_gemm<EPI_LN, 0, 256, true><<<dim3(256, 1), 256, SM256>>>(
        msg, nullptr, wmr, msgn, 256, 256, 256, n1g, n1b, nullptr, nullptr, nullptr);

    // MLP1: concat(xh, msgn) @ w1^T -> relu, fp16 out
    mma_gemm<EPI_RELU, 1, 128, true><<<dim3(256, 4), 256, SM128>>>(
        xh, msgn, w1r, hmid, 512, 512, 512, nullptr, nullptr, nullptr, nullptr, nullptr);

    // MLP2 + LN2 + residual -> out (fp32)
    mma_gemm<EPI_LN_RESID, 0, 256, false><<<dim3(256, 1), 256, SM256>>>(
        hmid, nullptr, w2r, out, 512, 512, 256, n2g, n2b, x, nullptr, nullptr);
}

// round 12
// speedup vs baseline: 1.7624x; 1.0641x over previous
#include <cuda_runtime.h>
#include <cuda_fp16.h>
#include <math.h>
#include <stdint.h>

#define EPS_LN  1e-5f
#define EPS_ATT 1e-6f

// ---------------------------------------------------------------------------
// helpers
// ---------------------------------------------------------------------------
__device__ __forceinline__ uint32_t smem_u32(const void* p) {
    uint32_t a;
    asm("{ .reg .u64 t; cvta.to.shared.u64 t, %1; cvt.u32.u64 %0, t; }" : "=r"(a) : "l"(p));
    return a;
}
__device__ __forceinline__ void mma16(float* c, const uint32_t* a, const uint32_t* b) {
    asm volatile(
        "mma.sync.aligned.m16n8k16.row.col.f32.f16.f16.f32 "
        "{%0,%1,%2,%3}, {%4,%5,%6,%7}, {%8,%9}, {%0,%1,%2,%3};"
        : "+f"(c[0]), "+f"(c[1]), "+f"(c[2]), "+f"(c[3])
        : "r"(a[0]), "r"(a[1]), "r"(a[2]), "r"(a[3]), "r"(b[0]), "r"(b[1]));
}
__device__ __forceinline__ void ldsm_x4(uint32_t& r0, uint32_t& r1, uint32_t& r2, uint32_t& r3,
                                        uint32_t addr) {
    asm volatile("ldmatrix.sync.aligned.m8n8.x4.shared.b16 {%0,%1,%2,%3}, [%4];"
        : "=r"(r0), "=r"(r1), "=r"(r2), "=r"(r3) : "r"(addr));
}
__device__ __forceinline__ uint32_t h2u(__half2 h) { return *(uint32_t*)&h; }

// ---------------------------------------------------------------------------
// Scratch
// ---------------------------------------------------------------------------
__device__ __half g_wsrB[256 * 4096];
__device__ __half g_wqr [256 * 256];
__device__ __half g_wkr [256 * 256];
__device__ __half g_wvr [256 * 256];
__device__ __half g_wmr [256 * 256];
__device__ __half g_w1r [512 * 512];
__device__ __half g_w2r [256 * 512];
__device__ __half g_xh  [8 * 4096 * 256];
__device__ __half g_part[8 * 2048 * 256];   // conv split-K partials (fp16)
__device__ __half g_src [2048 * 256];
__device__ __half g_kmat[2048 * 256];
__device__ __half g_vmat[2048 * 256];
__device__ float  g_kv  [64 * 32 * 32];
__device__ float  g_ksum[64 * 32];
__device__ __half g_msg [8 * 4096 * 256];
__device__ __half g_msgn[8 * 4096 * 256];
__device__ __half g_hmid[8 * 4096 * 512];

// ---------------------------------------------------------------------------
// Unified prep: x->fp16, weights->fp16, conv repack. grid 11008 x 256.
// ---------------------------------------------------------------------------
__global__ void prep_all(const float* __restrict__ x,
                         const float* __restrict__ sr_w,
                         const float* __restrict__ wq, const float* __restrict__ wk,
                         const float* __restrict__ wv, const float* __restrict__ wm,
                         const float* __restrict__ w1, const float* __restrict__ w2,
                         __half* __restrict__ xh, __half* __restrict__ wsrB,
                         __half* __restrict__ oq, __half* __restrict__ ok,
                         __half* __restrict__ ov, __half* __restrict__ om,
                         __half* __restrict__ o1, __half* __restrict__ o2) {
    int bid = blockIdx.x;
    if (bid < 8192) {
        size_t i = ((size_t)bid * 256 + threadIdx.x) * 4;
        float4 v = *(const float4*)&x[i];
        __half2 h0 = __floats2half2_rn(v.x, v.y);
        __half2 h1 = __floats2half2_rn(v.z, v.w);
        *(uint2*)&xh[i] = make_uint2(h2u(h0), h2u(h1));
        return;
    }
    bid -= 8192;
    if (bid < 2560) {
        const float* src; __half* dst; int base;
        if      (bid < 256)  { src = wq; dst = oq; base = 0; }
        else if (bid < 512)  { src = wk; dst = ok; base = 256; }
        else if (bid < 768)  { src = wv; dst = ov; base = 512; }
        else if (bid < 1024) { src = wm; dst = om; base = 768; }
        else if (bid < 2048) { src = w1; dst = o1; base = 1024; }
        else                 { src = w2; dst = o2; base = 2048; }
        int idx = (bid - base) * 256 + threadIdx.x;
        dst[idx] = __float2half_rn(src[idx]);
        return;
    }
    bid -= 2560;
    {   // conv repack: sr_w OIHW -> wsrB[o*4096 + rr*256 + i]
        int idx = bid * 256 + threadIdx.x;
        int o = idx >> 8, i = idx & 255;
        const float* p = sr_w + ((size_t)(o * 256 + i)) * 16;
#pragma unroll
        for (int rr = 0; rr < 16; rr++)
            wsrB[(size_t)o * 4096 + rr * 256 + i] = __float2half_rn(p[rr]);
    }
}

// ---------------------------------------------------------------------------
// Split-K(8) reduce + bias + LayerNorm -> src (fp16). grid 256, 256 thr.
// ---------------------------------------------------------------------------
__global__ void reduce_ln(const __half* __restrict__ part, const float* __restrict__ bias,
                          const float* __restrict__ g, const float* __restrict__ bb,
                          __half* __restrict__ out) {
    int lane = threadIdx.x & 31, w = threadIdx.x >> 5;
    int row = blockIdx.x * 8 + w;
    float v[8];
#pragma unroll
    for (int j = 0; j < 8; j++) {
        int c = lane + j * 32;
        float s = 0.f;
#pragma unroll
        for (int ks = 0; ks < 8; ks++)
            s += __half2float(part[((size_t)ks * 2048 + row) * 256 + c]);
        v[j] = s + bias[c];
    }
    float sum = 0.f;
#pragma unroll
    for (int j = 0; j < 8; j++) sum += v[j];
#pragma unroll
    for (int o = 16; o; o >>= 1) sum += __shfl_xor_sync(0xffffffffu, sum, o);
    float mean = sum * (1.f / 256.f);
    float ss = 0.f;
#pragma unroll
    for (int j = 0; j < 8; j++) { float d = v[j] - mean; ss += d * d; }
#pragma unroll
    for (int o = 16; o; o >>= 1) ss += __shfl_xor_sync(0xffffffffu, ss, o);
    float inv = rsqrtf(ss * (1.f / 256.f) + EPS_LN);
#pragma unroll
    for (int j = 0; j < 8; j++) {
        int c = lane + j * 32;
        out[(size_t)row * 256 + c] = __float2half_rn((v[j] - mean) * inv * g[c] + bb[c]);
    }
}

// ---------------------------------------------------------------------------
// fp16 mma GEMM with ldmatrix fragments. BM=128, BN=NB, BK=32 halfs, 256 thr.
// EPI: 0 plain, 1 elu+1, 2 relu, 3 LN, 4 LN+resid, 5 elu+1 -> fused attention
// ---------------------------------------------------------------------------
#define EPI_PLAIN    0
#define EPI_ELU1     1
#define EPI_RELU     2
#define EPI_LN       3
#define EPI_LN_RESID 4
#define EPI_ATTN     5

#define RSTRIDE_H 40
#define A_ROWS    128

__host__ __device__ constexpr int stage_halfs(int NB) { return (128 + NB) * RSTRIDE_H; }
__host__ __device__ constexpr int smem_req(int NB, int EPI) {
    int mainloop = 2 * stage_halfs(NB) * 2;
    int epi = (128 * (NB + 4) + 256) * 4;
    if (EPI == EPI_ATTN) epi = (128 * (NB + 4) + 512 + 128 + 4096) * 4;
    return mainloop > epi ? mainloop : epi;
}

template <int EPI, int MODE, int NB, bool OUTH>
__global__ __launch_bounds__(256, (NB == 128 ? 2 : 1))
void mma_gemm(const __half* __restrict__ A0, const __half* __restrict__ A1,
              const __half* __restrict__ Bw, void* __restrict__ Cv,
              int Kloc, int KB, int Ntot,
              const float* __restrict__ gamma, const float* __restrict__ beta,
              const float* __restrict__ resid,
              const __half* __restrict__ Bw2, void* __restrict__ C2v) {
    extern __shared__ __half dsm_h[];

    constexpr int WM    = (NB == 256) ? 2 : 4;
    constexpr int MF    = 128 / WM / 16;
    constexpr int MROWS = 128 / WM;
    constexpr int NBLD  = NB / 64;
    constexpr int STAGE = stage_halfs(NB);
    constexpr int EPIST = NB + 4;

    const int tid  = threadIdx.x;
    const int lane = tid & 31;
    const int wid  = tid >> 5;
    const int g    = lane >> 2;
    const int t    = lane & 3;
    const int warp_m = wid % WM;
    const int warp_n = wid / WM;

    const int mtile = blockIdx.x * 128;
    int ncol0 = blockIdx.y * NB, kstart = 0;
    const __half* Bsrc = Bw;
    void* Cout = Cv;
    size_t coff = 0;
    if (MODE == 2) { kstart = blockIdx.z * 512; coff = (size_t)blockIdx.z * 2048 * 256; }
    if (MODE == 3) { if (blockIdx.z) { Bsrc = Bw2; Cout = C2v; } }
    const int KT = Kloc / 32;

    float acc[MF][8][4];
#pragma unroll
    for (int i = 0; i < MF; i++)
#pragma unroll
        for (int j = 0; j < 8; j++)
#pragma unroll
            for (int q = 0; q < 4; q++) acc[i][j][q] = 0.f;

    uint4 rA[2], rB[NBLD];

    auto ldg_tile = [&](int kt) {
        const int kbase = kstart + kt * 32;
#pragma unroll
        for (int p = 0; p < 2; p++) {
            int idx = p * 256 + tid;
            int m = idx >> 2, c = idx & 3;
            int kk = kbase + c * 8;
            const __half* gp;
            if (MODE == 2) {
                int mg = mtile + m;
                int b = mg >> 8, s5 = mg & 255;
                int rr = kk >> 8, i = kk & 255;
                int n = (((s5 >> 4) * 4 + (rr >> 2)) << 6) + ((s5 & 15) << 2) + (rr & 3);
                gp = A0 + (((size_t)b << 12) + n) * 256 + i;
            } else if (MODE == 1) {
                gp = (kk < 256) ? (A0 + (size_t)(mtile + m) * 256 + kk)
                                : (A1 + (size_t)(mtile + m) * 256 + (kk - 256));
            } else {
                gp = A0 + (size_t)(mtile + m) * Kloc + kk;
            }
            rA[p] = *(const uint4*)gp;
        }
#pragma unroll
        for (int p = 0; p < NBLD; p++) {
            int idx = p * 256 + tid;
            int n = idx >> 2, c = idx & 3;
            rB[p] = *(const uint4*)(Bsrc + (size_t)(ncol0 + n) * KB + kbase + c * 8);
        }
    };
    auto sts_tile = [&](int s) {
        __half* sA = dsm_h + s * STAGE;
        __half* sB = sA + A_ROWS * RSTRIDE_H;
#pragma unroll
        for (int p = 0; p < 2; p++) {
            int idx = p * 256 + tid;
            int m = idx >> 2, c = idx & 3;
            *(uint4*)&sA[m * RSTRIDE_H + c * 8] = rA[p];
        }
#pragma unroll
        for (int p = 0; p < NBLD; p++) {
            int idx = p * 256 + tid;
            int n = idx >> 2, c = idx & 3;
            *(uint4*)&sB[n * RSTRIDE_H + c * 8] = rB[p];
        }
    };

    const uint32_t smb = smem_u32(dsm_h);
    const uint32_t a_l = ((warp_m * MROWS + (lane & 7) + ((lane >> 3) & 1) * 8) * RSTRIDE_H
                          + ((lane >> 4) & 1) * 8) * 2;
    const uint32_t b_l = ((A_ROWS + warp_n * 64 + (lane & 7) + ((lane >> 4) & 1) * 8) * RSTRIDE_H
                          + ((lane >> 3) & 1) * 8) * 2;

    ldg_tile(0);
    sts_tile(0);
    if (KT > 1) ldg_tile(1);
    __syncthreads();

    for (int kt = 0; kt < KT; kt++) {
        if (kt + 1 < KT) {
            sts_tile((kt + 1) & 1);
            if (kt + 2 < KT) ldg_tile(kt + 2);
            __syncthreads();
        }
        const uint32_t sbase = smb + (uint32_t)(kt & 1) * (STAGE * 2);
#pragma unroll
        for (int ks = 0; ks < 2; ks++) {
            const uint32_t koffB = ks * 32;
            uint32_t a[MF][4], b[8][2];
#pragma unroll
            for (int mf = 0; mf < MF; mf++)
                ldsm_x4(a[mf][0], a[mf][1], a[mf][2], a[mf][3],
                        sbase + a_l + mf * (16 * RSTRIDE_H * 2) + koffB);
#pragma unroll
            for (int p = 0; p < 4; p++)
                ldsm_x4(b[2 * p][0], b[2 * p][1], b[2 * p + 1][0], b[2 * p + 1][1],
                        sbase + b_l + p * (16 * RSTRIDE_H * 2) + koffB);
#pragma unroll
            for (int mf = 0; mf < MF; mf++)
#pragma unroll
                for (int nf = 0; nf < 8; nf++)
                    mma16(acc[mf][nf], a[mf], b[nf]);
        }
        __syncthreads();
    }

    // ---- epilogue ----
    float* sepi   = (float*)dsm_h;
    float* s_mean = sepi + 128 * EPIST;
    float* s_inv  = s_mean + 128;
    // EPI_ATTN extras
    float* z_s    = sepi + 128 * EPIST;          // 512
    float* ksum_s = z_s + 512;                   // 128
    float* kv_s   = ksum_s + 128;                // 4096
    const bool doAct = (MODE != 3) || (blockIdx.z == 0);

    // For ATTN: kick off KV/Ksum loads (independent of sepi contents)
    if (EPI == EPI_ATTN) {
        const int b = mtile >> 12;
        const int H0 = blockIdx.y * 4;
        const float4* kvg = (const float4*)(gamma + (((size_t)(b * 8 + H0)) * 32) * 32); // gamma=kv base
#pragma unroll
        for (int p = 0; p < 4; p++)
            *(float4*)&kv_s[(p * 256 + tid) * 4] = kvg[p * 256 + tid];
        if (tid < 32)
            *(float4*)&ksum_s[tid * 4] = *(const float4*)(beta + b * 256 + H0 * 32 + tid * 4); // beta=ksum base
    }

#pragma unroll
    for (int mf = 0; mf < MF; mf++) {
        int r0 = warp_m * MROWS + mf * 16 + g;
#pragma unroll
        for (int nf = 0; nf < 8; nf++) {
            int c0 = warp_n * 64 + nf * 8 + 2 * t;
            float v0 = acc[mf][nf][0], v1 = acc[mf][nf][1];
            float v2 = acc[mf][nf][2], v3 = acc[mf][nf][3];
            if ((EPI == EPI_ELU1 || EPI == EPI_ATTN) && doAct) {
                v0 = (v0 > 0.f) ? v0 + 1.f : __expf(v0);
                v1 = (v1 > 0.f) ? v1 + 1.f : __expf(v1);
                v2 = (v2 > 0.f) ? v2 + 1.f : __expf(v2);
                v3 = (v3 > 0.f) ? v3 + 1.f : __expf(v3);
            }
            if (EPI == EPI_RELU) {
                v0 = fmaxf(v0, 0.f); v1 = fmaxf(v1, 0.f);
                v2 = fmaxf(v2, 0.f); v3 = fmaxf(v3, 0.f);
            }
            *(float2*)&sepi[r0 * EPIST + c0]       = make_float2(v0, v1);
            *(float2*)&sepi[(r0 + 8) * EPIST + c0] = make_float2(v2, v3);
        }
    }
    __syncthreads();

    if (EPI == EPI_ATTN) {
        // ---- z phase: 512 (row,head) pairs, 2 per thread ----
#pragma unroll
        for (int i = 0; i < 2; i++) {
            int p = tid * 2 + i;
            int row = p >> 2, hh = p & 3;
            const float4* qp = (const float4*)&sepi[row * EPIST + hh * 32];
            const float4* kp = (const float4*)&ksum_s[hh * 32];
            float z = 0.f;
#pragma unroll
            for (int q4 = 0; q4 < 8; q4++) {
                float4 qv = qp[q4], kv4 = kp[q4];
                z += qv.x * kv4.x + qv.y * kv4.y + qv.z * kv4.z + qv.w * kv4.w;
            }
            z_s[p] = 1.f / (z + EPS_ATT);
        }
        __syncthreads();

        // ---- msg phase: thread = (hh, half, c) ----
        const int c  = tid & 31;
        const int hf = (tid >> 5) & 1;
        const int hh = tid >> 6;
        float kvr[32];
#pragma unroll
        for (int d = 0; d < 32; d++) kvr[d] = kv_s[hh * 1024 + d * 32 + c];
        __half* msgp = (__half*)Cout;
        const int colg = blockIdx.y * 128 + hh * 32 + c;
#pragma unroll 2
        for (int r = 0; r < 64; r++) {
            int row = hf * 64 + r;
            const float4* qp = (const float4*)&sepi[row * EPIST + hh * 32];
            float m = 0.f;
#pragma unroll
            for (int q4 = 0; q4 < 8; q4++) {
                float4 qv = qp[q4];
                m += qv.x * kvr[q4 * 4] + qv.y * kvr[q4 * 4 + 1]
                   + qv.z * kvr[q4 * 4 + 2] + qv.w * kvr[q4 * 4 + 3];
            }
            m *= z_s[row * 4 + hh];
            msgp[(size_t)(mtile + row) * 256 + colg] = __float2half_rn(m);
        }
        return;
    }

    if ((EPI == EPI_LN || EPI == EPI_LN_RESID) && tid < 128) {
        const float* rowp = sepi + tid * EPIST;
        float sum = 0.f, ss = 0.f;
#pragma unroll 8
        for (int j = 0; j < NB / 4; j++) {
            float4 v = *(const float4*)&rowp[j * 4];
            sum += v.x + v.y + v.z + v.w;
            ss  += v.x * v.x + v.y * v.y + v.z * v.z + v.w * v.w;
        }
        float mean = sum * (1.f / 256.f);
        float var  = ss * (1.f / 256.f) - mean * mean;
        s_mean[tid] = mean;
        s_inv[tid]  = rsqrtf(var + EPS_LN);
    }
    if (EPI == EPI_LN || EPI == EPI_LN_RESID) __syncthreads();

#pragma unroll 4
    for (int p = 0; p < NB / 8; p++) {
        int idx4 = p * 256 + tid;
        int row = idx4 / (NB / 4);
        int c4  = (idx4 % (NB / 4)) << 2;
        float4 v = *(const float4*)&sepi[row * EPIST + c4];
        if (EPI == EPI_LN || EPI == EPI_LN_RESID) {
            float m = s_mean[row], iv = s_inv[row];
            float4 gm = *(const float4*)&gamma[c4];
            float4 bt = *(const float4*)&beta[c4];
            v.x = (v.x - m) * iv * gm.x + bt.x;
            v.y = (v.y - m) * iv * gm.y + bt.y;
            v.z = (v.z - m) * iv * gm.z + bt.z;
            v.w = (v.w - m) * iv * gm.w + bt.w;
            if (EPI == EPI_LN_RESID) {
                float4 r = *(const float4*)&resid[(size_t)(mtile + row) * 256 + c4];
                v.x += r.x; v.y += r.y; v.z += r.z; v.w += r.w;
            }
        }
        size_t off = coff + (size_t)(mtile + row) * Ntot + ncol0 + c4;
        if (OUTH) {
            __half2 h0 = __floats2half2_rn(v.x, v.y);
            __half2 h1 = __floats2half2_rn(v.z, v.w);
            *(uint2*)&((__half*)Cout)[off] = make_uint2(h2u(h0), h2u(h1));
        } else {
            *(float4*)&((float*)Cout)[off] = v;
        }
    }
}

// ---------------------------------------------------------------------------
// KV = sum_s K^T V, Ksum = sum_s K. fp16 in, fp32 math. grid 64, 256 thr.
// ---------------------------------------------------------------------------
__global__ void kv_kernel(const __half* __restrict__ kmat, const __half* __restrict__ vmat,
                          float* __restrict__ kv, float* __restrict__ ksum) {
    __shared__ float Ks[128][32];
    __shared__ float Vs[128][32];
    int bh = blockIdx.x, b = bh >> 3, h = bh & 7;
    int tid = threadIdx.x;
    int d = tid & 31, vg = tid >> 5;
    float acc0 = 0.f, acc1 = 0.f, acc2 = 0.f, acc3 = 0.f, ka = 0.f;

    for (int ch = 0; ch < 2; ch++) {
        int sl = tid >> 3, c4 = tid & 7;
#pragma unroll
        for (int ss = 0; ss < 4; ss++) {
            int srow = ch * 128 + ss * 32 + sl;
            size_t base = ((size_t)(b * 256 + srow)) * 256 + h * 32 + c4 * 4;
            uint2 kw = *(const uint2*)&kmat[base];
            uint2 vw = *(const uint2*)&vmat[base];
            __half2* kh = (__half2*)&kw;
            __half2* vh = (__half2*)&vw;
            float2 k0 = __half22float2(kh[0]), k1 = __half22float2(kh[1]);
            float2 w0 = __half22float2(vh[0]), w1 = __half22float2(vh[1]);
            Ks[ss * 32 + sl][c4 * 4 + 0] = k0.x; Ks[ss * 32 + sl][c4 * 4 + 1] = k0.y;
            Ks[ss * 32 + sl][c4 * 4 + 2] = k1.x; Ks[ss * 32 + sl][c4 * 4 + 3] = k1.y;
            Vs[ss * 32 + sl][c4 * 4 + 0] = w0.x; Vs[ss * 32 + sl][c4 * 4 + 1] = w0.y;
            Vs[ss * 32 + sl][c4 * 4 + 2] = w1.x; Vs[ss * 32 + sl][c4 * 4 + 3] = w1.y;
        }
        __syncthreads();
#pragma unroll 4
        for (int s = 0; s < 128; s++) {
            float kd = Ks[s][d];
            float4 vv = *(float4*)&Vs[s][vg * 4];
            acc0 += kd * vv.x; acc1 += kd * vv.y;
            acc2 += kd * vv.z; acc3 += kd * vv.w;
            if (vg == 0) ka += kd;
        }
        __syncthreads();
    }
    float* kvp = kv + ((size_t)bh * 32 + d) * 32 + vg * 4;
    kvp[0] = acc0; kvp[1] = acc1; kvp[2] = acc2; kvp[3] = acc3;
    if (vg == 0) ksum[bh * 32 + d] = ka;
}

// ---------------------------------------------------------------------------
// Launch
// ---------------------------------------------------------------------------
extern "C" void kernel_launch(void* const* d_in, const int* in_sizes, int n_in,
                              void* d_out, int out_size) {
    const float* x      = (const float*)d_in[0];
    const float* sr_w   = (const float*)d_in[1];
    const float* sr_b   = (const float*)d_in[2];
    const float* norm_g = (const float*)d_in[3];
    const float* norm_b = (const float*)d_in[4];
    const float* wq     = (const float*)d_in[5];
    const float* wk     = (const float*)d_in[6];
    const float* wv     = (const float*)d_in[7];
    const float* wm     = (const float*)d_in[8];
    const float* w1     = (const float*)d_in[9];
    const float* w2     = (const float*)d_in[10];
    const float* n1g    = (const float*)d_in[11];
    const float* n1b    = (const float*)d_in[12];
    const float* n2g    = (const float*)d_in[13];
    const float* n2b    = (const float*)d_in[14];
    float* out = (float*)d_out;

    __half *wsrB, *wqr, *wkr, *wvr, *wmr, *w1r, *w2r;
    __half *xh, *part, *src, *kmat, *vmat, *msg, *msgn, *hmid;
    float *kvp, *ksump;
    cudaGetSymbolAddress((void**)&wsrB, g_wsrB);
    cudaGetSymbolAddress((void**)&wqr,  g_wqr);
    cudaGetSymbolAddress((void**)&wkr,  g_wkr);
    cudaGetSymbolAddress((void**)&wvr,  g_wvr);
    cudaGetSymbolAddress((void**)&wmr,  g_wmr);
    cudaGetSymbolAddress((void**)&w1r,  g_w1r);
    cudaGetSymbolAddress((void**)&w2r,  g_w2r);
    cudaGetSymbolAddress((void**)&xh,   g_xh);
    cudaGetSymbolAddress((void**)&part, g_part);
    cudaGetSymbolAddress((void**)&src,  g_src);
    cudaGetSymbolAddress((void**)&kmat, g_kmat);
    cudaGetSymbolAddress((void**)&vmat, g_vmat);
    cudaGetSymbolAddress((void**)&kvp,  g_kv);
    cudaGetSymbolAddress((void**)&ksump,g_ksum);
    cudaGetSymbolAddress((void**)&msg,  g_msg);
    cudaGetSymbolAddress((void**)&msgn, g_msgn);
    cudaGetSymbolAddress((void**)&hmid, g_hmid);

    constexpr int SM128  = smem_req(128, EPI_PLAIN);
    constexpr int SMATTN = smem_req(128, EPI_ATTN);
    constexpr int SM256  = smem_req(256, EPI_LN);
    cudaFuncSetAttribute(mma_gemm<EPI_PLAIN, 2, 128, true>,    cudaFuncAttributeMaxDynamicSharedMemorySize, SM128);
    cudaFuncSetAttribute(mma_gemm<EPI_ELU1, 3, 128, true>,     cudaFuncAttributeMaxDynamicSharedMemorySize, SM128);
    cudaFuncSetAttribute(mma_gemm<EPI_ATTN, 0, 128, true>,     cudaFuncAttributeMaxDynamicSharedMemorySize, SMATTN);
    cudaFuncSetAttribute(mma_gemm<EPI_RELU, 1, 128, true>,     cudaFuncAttributeMaxDynamicSharedMemorySize, SM128);
    cudaFuncSetAttribute(mma_gemm<EPI_LN, 0, 256, true>,       cudaFuncAttributeMaxDynamicSharedMemorySize, SM256);
    cudaFuncSetAttribute(mma_gemm<EPI_LN_RESID, 0, 256, false>,cudaFuncAttributeMaxDynamicSharedMemorySize, SM256);

    // unified prep
    prep_all<<<11008, 256>>>(x, sr_w, wq, wk, wv, wm, w1, w2,
                             xh, wsrB, wqr, wkr, wvr, wmr, w1r, w2r);

    // conv-as-GEMM (split-K=8 on z, fp16 partials) + reduce/bias/LN -> src
    mma_gemm<EPI_PLAIN, 2, 128, true><<<dim3(16, 2, 8), 256, SM128>>>(
        xh, nullptr, wsrB, part, 512, 4096, 256, nullptr, nullptr, nullptr, nullptr, nullptr);
    reduce_ln<<<256, 256>>>(part, sr_b, norm_g, norm_b, src);

    // fused k/v projections (M=2048), fp16 out
    mma_gemm<EPI_ELU1, 3, 128, true><<<dim3(16, 2, 2), 256, SM128>>>(
        src, nullptr, wkr, kmat, 256, 256, 256, nullptr, nullptr, nullptr, wvr, vmat);

    kv_kernel<<<64, 256>>>(kmat, vmat, kvp, ksump);

    // q projection + FUSED linear attention -> msg (fp16)
    // gamma slot carries kv, beta slot carries ksum.
    mma_gemm<EPI_ATTN, 0, 128, true><<<dim3(256, 2), 256, SMATTN>>>(
        xh, nullptr, wqr, msg, 256, 256, 256, kvp, ksump, nullptr, nullptr, nullptr);

    // merge projection + LN1, fp16 out
    mma_gemm<EPI_LN, 0, 256, true><<<dim3(256, 1), 256, SM256>>>(
        msg, nullptr, wmr, msgn, 256, 256, 256, n1g, n1b, nullptr, nullptr, nullptr);

    // MLP1: concat(xh, msgn) @ w1^T -> relu, fp16 out
    mma_gemm<EPI_RELU, 1, 128, true><<<dim3(256, 4), 256, SM128>>>(
        xh, msgn, w1r, hmid, 512, 512, 512, nullptr, nullptr, nullptr, nullptr, nullptr);

    // MLP2 + LN2 + residual -> out (fp32)
    mma_gemm<EPI_LN_RESID, 0, 256, false><<<dim3(256, 1), 256, SM256>>>(
        hmid, nullptr, w2r, out, 512, 512, 256, n2g, n2b, x, nullptr, nullptr);
}

// round 13
// speedup vs baseline: 1.9656x; 1.1153x over previous
#include <cuda_runtime.h>
#include <cuda_fp16.h>
#include <math.h>
#include <stdint.h>

#define EPS_LN  1e-5f
#define EPS_ATT 1e-6f

// ---------------------------------------------------------------------------
// helpers
// ---------------------------------------------------------------------------
__device__ __forceinline__ uint32_t smem_u32(const void* p) {
    uint32_t a;
    asm("{ .reg .u64 t; cvta.to.shared.u64 t, %1; cvt.u32.u64 %0, t; }" : "=r"(a) : "l"(p));
    return a;
}
__device__ __forceinline__ void mma16(float* c, const uint32_t* a, const uint32_t* b) {
    asm volatile(
        "mma.sync.aligned.m16n8k16.row.col.f32.f16.f16.f32 "
        "{%0,%1,%2,%3}, {%4,%5,%6,%7}, {%8,%9}, {%0,%1,%2,%3};"
        : "+f"(c[0]), "+f"(c[1]), "+f"(c[2]), "+f"(c[3])
        : "r"(a[0]), "r"(a[1]), "r"(a[2]), "r"(a[3]), "r"(b[0]), "r"(b[1]));
}
__device__ __forceinline__ void ldsm_x4(uint32_t& r0, uint32_t& r1, uint32_t& r2, uint32_t& r3,
                                        uint32_t addr) {
    asm volatile("ldmatrix.sync.aligned.m8n8.x4.shared.b16 {%0,%1,%2,%3}, [%4];"
        : "=r"(r0), "=r"(r1), "=r"(r2), "=r"(r3) : "r"(addr));
}
__device__ __forceinline__ uint32_t h2u(__half2 h) { return *(uint32_t*)&h; }

// ---------------------------------------------------------------------------
// Scratch
// ---------------------------------------------------------------------------
__device__ __half g_wsrB[256 * 4096];
__device__ __half g_wqr [256 * 256];
__device__ __half g_wkr [256 * 256];
__device__ __half g_wvr [256 * 256];
__device__ __half g_wmr [256 * 256];
__device__ __half g_w1r [512 * 512];
__device__ __half g_w2r [256 * 512];
__device__ __half g_xh  [8 * 4096 * 256];
__device__ __half g_part[8 * 2048 * 256];
__device__ __half g_src [2048 * 256];
__device__ __half g_kmat[2048 * 256];
__device__ __half g_vmat[2048 * 256];
__device__ float  g_kv  [64 * 32 * 32];
__device__ float  g_ksum[64 * 32];
__device__ __half g_msg [8 * 4096 * 256];
__device__ __half g_msgn[8 * 4096 * 256];
__device__ __half g_hmid[8 * 4096 * 512];

// ---------------------------------------------------------------------------
// Unified prep: x->fp16, weights->fp16, conv repack. grid 11008 x 256.
// ---------------------------------------------------------------------------
__global__ void prep_all(const float* __restrict__ x,
                         const float* __restrict__ sr_w,
                         const float* __restrict__ wq, const float* __restrict__ wk,
                         const float* __restrict__ wv, const float* __restrict__ wm,
                         const float* __restrict__ w1, const float* __restrict__ w2,
                         __half* __restrict__ xh, __half* __restrict__ wsrB,
                         __half* __restrict__ oq, __half* __restrict__ ok,
                         __half* __restrict__ ov, __half* __restrict__ om,
                         __half* __restrict__ o1, __half* __restrict__ o2) {
    int bid = blockIdx.x;
    if (bid < 8192) {
        size_t i = ((size_t)bid * 256 + threadIdx.x) * 4;
        float4 v = *(const float4*)&x[i];
        __half2 h0 = __floats2half2_rn(v.x, v.y);
        __half2 h1 = __floats2half2_rn(v.z, v.w);
        *(uint2*)&xh[i] = make_uint2(h2u(h0), h2u(h1));
        return;
    }
    bid -= 8192;
    if (bid < 2560) {
        const float* src; __half* dst; int base;
        if      (bid < 256)  { src = wq; dst = oq; base = 0; }
        else if (bid < 512)  { src = wk; dst = ok; base = 256; }
        else if (bid < 768)  { src = wv; dst = ov; base = 512; }
        else if (bid < 1024) { src = wm; dst = om; base = 768; }
        else if (bid < 2048) { src = w1; dst = o1; base = 1024; }
        else                 { src = w2; dst = o2; base = 2048; }
        int idx = (bid - base) * 256 + threadIdx.x;
        dst[idx] = __float2half_rn(src[idx]);
        return;
    }
    bid -= 2560;
    {
        int idx = bid * 256 + threadIdx.x;
        int o = idx >> 8, i = idx & 255;
        const float* p = sr_w + ((size_t)(o * 256 + i)) * 16;
#pragma unroll
        for (int rr = 0; rr < 16; rr++)
            wsrB[(size_t)o * 4096 + rr * 256 + i] = __float2half_rn(p[rr]);
    }
}

// ---------------------------------------------------------------------------
// Split-K(8) reduce + bias + LayerNorm -> src (fp16). grid 256, 256 thr.
// ---------------------------------------------------------------------------
__global__ void reduce_ln(const __half* __restrict__ part, const float* __restrict__ bias,
                          const float* __restrict__ g, const float* __restrict__ bb,
                          __half* __restrict__ out) {
    int lane = threadIdx.x & 31, w = threadIdx.x >> 5;
    int row = blockIdx.x * 8 + w;
    float v[8];
#pragma unroll
    for (int j = 0; j < 8; j++) {
        int c = lane + j * 32;
        float s = 0.f;
#pragma unroll
        for (int ks = 0; ks < 8; ks++)
            s += __half2float(part[((size_t)ks * 2048 + row) * 256 + c]);
        v[j] = s + bias[c];
    }
    float sum = 0.f;
#pragma unroll
    for (int j = 0; j < 8; j++) sum += v[j];
#pragma unroll
    for (int o = 16; o; o >>= 1) sum += __shfl_xor_sync(0xffffffffu, sum, o);
    float mean = sum * (1.f / 256.f);
    float ss = 0.f;
#pragma unroll
    for (int j = 0; j < 8; j++) { float d = v[j] - mean; ss += d * d; }
#pragma unroll
    for (int o = 16; o; o >>= 1) ss += __shfl_xor_sync(0xffffffffu, ss, o);
    float inv = rsqrtf(ss * (1.f / 256.f) + EPS_LN);
#pragma unroll
    for (int j = 0; j < 8; j++) {
        int c = lane + j * 32;
        out[(size_t)row * 256 + c] = __float2half_rn((v[j] - mean) * inv * g[c] + bb[c]);
    }
}

// ---------------------------------------------------------------------------
// fp16 mma GEMM, BK=64 halfs. BM=128, BN=NB, 256 thr, ldmatrix fragments.
// EPI: 0 plain, 1 elu+1, 2 relu, 3 LN, 4 LN+resid, 5 fused attention
// ---------------------------------------------------------------------------
#define EPI_PLAIN    0
#define EPI_ELU1     1
#define EPI_RELU     2
#define EPI_LN       3
#define EPI_LN_RESID 4
#define EPI_ATTN     5

#define RSTRIDE_H 72
#define A_ROWS    128

__host__ __device__ constexpr int stage_halfs(int NB) { return (128 + NB) * RSTRIDE_H; }
__host__ __device__ constexpr int smem_req(int NB, int EPI) {
    int mainloop = 2 * stage_halfs(NB) * 2;
    int epi = (128 * (NB + 4) + 256) * 4;
    if (EPI == EPI_ATTN) epi = (128 * (NB + 4) + 512 + 128 + 4096) * 4;
    return mainloop > epi ? mainloop : epi;
}

template <int EPI, int MODE, int NB, bool OUTH>
__global__ __launch_bounds__(256, (NB == 128 ? 2 : 1))
void mma_gemm(const __half* __restrict__ A0, const __half* __restrict__ A1,
              const __half* __restrict__ Bw, void* __restrict__ Cv,
              int Kloc, int KB, int Ntot,
              const float* __restrict__ gamma, const float* __restrict__ beta,
              const float* __restrict__ resid,
              const __half* __restrict__ Bw2, void* __restrict__ C2v) {
    extern __shared__ __half dsm_h[];

    constexpr int WM    = (NB == 256) ? 2 : 4;
    constexpr int MF    = 128 / WM / 16;
    constexpr int MROWS = 128 / WM;
    constexpr int BLD   = NB / 32;            // B uint4 per thread (BK=64)
    constexpr int STAGE = stage_halfs(NB);
    constexpr int EPIST = NB + 4;

    const int tid  = threadIdx.x;
    const int lane = tid & 31;
    const int wid  = tid >> 5;
    const int g    = lane >> 2;
    const int t    = lane & 3;
    const int warp_m = wid % WM;
    const int warp_n = wid / WM;

    const int mtile = blockIdx.x * 128;
    int ncol0 = blockIdx.y * NB, kstart = 0;
    const __half* Bsrc = Bw;
    void* Cout = Cv;
    size_t coff = 0;
    if (MODE == 2) { kstart = blockIdx.z * 512; coff = (size_t)blockIdx.z * 2048 * 256; }
    if (MODE == 3) { if (blockIdx.z) { Bsrc = Bw2; Cout = C2v; } }
    const int KT = Kloc / 64;

    float acc[MF][8][4];
#pragma unroll
    for (int i = 0; i < MF; i++)
#pragma unroll
        for (int j = 0; j < 8; j++)
#pragma unroll
            for (int q = 0; q < 4; q++) acc[i][j][q] = 0.f;

    uint4 rA[4], rB[BLD];

    auto ldg_tile = [&](int kt) {
        const int kbase = kstart + kt * 64;
        // A: 128 rows x 64 halfs = 1024 uint4, 4/thread
#pragma unroll
        for (int p = 0; p < 4; p++) {
            int idx = p * 256 + tid;
            int m = idx >> 3, c = idx & 7;
            int kk = kbase + c * 8;
            const __half* gp;
            if (MODE == 2) {
                int mg = mtile + m;
                int b = mg >> 8, s5 = mg & 255;
                int rr = kk >> 8, i = kk & 255;
                int n = (((s5 >> 4) * 4 + (rr >> 2)) << 6) + ((s5 & 15) << 2) + (rr & 3);
                gp = A0 + (((size_t)b << 12) + n) * 256 + i;
            } else if (MODE == 1) {
                gp = (kk < 256) ? (A0 + (size_t)(mtile + m) * 256 + kk)
                                : (A1 + (size_t)(mtile + m) * 256 + (kk - 256));
            } else {
                gp = A0 + (size_t)(mtile + m) * Kloc + kk;
            }
            rA[p] = *(const uint4*)gp;
        }
        // B: NB rows x 64 halfs
#pragma unroll
        for (int p = 0; p < BLD; p++) {
            int idx = p * 256 + tid;
            int n = idx >> 3, c = idx & 7;
            rB[p] = *(const uint4*)(Bsrc + (size_t)(ncol0 + n) * KB + kbase + c * 8);
        }
    };
    auto sts_tile = [&](int s) {
        __half* sA = dsm_h + s * STAGE;
        __half* sB = sA + A_ROWS * RSTRIDE_H;
#pragma unroll
        for (int p = 0; p < 4; p++) {
            int idx = p * 256 + tid;
            int m = idx >> 3, c = idx & 7;
            *(uint4*)&sA[m * RSTRIDE_H + c * 8] = rA[p];
        }
#pragma unroll
        for (int p = 0; p < BLD; p++) {
            int idx = p * 256 + tid;
            int n = idx >> 3, c = idx & 7;
            *(uint4*)&sB[n * RSTRIDE_H + c * 8] = rB[p];
        }
    };

    const uint32_t smb = smem_u32(dsm_h);
    const uint32_t a_l = ((warp_m * MROWS + (lane & 7) + ((lane >> 3) & 1) * 8) * RSTRIDE_H
                          + ((lane >> 4) & 1) * 8) * 2;
    const uint32_t b_l = ((A_ROWS + warp_n * 64 + (lane & 7) + ((lane >> 4) & 1) * 8) * RSTRIDE_H
                          + ((lane >> 3) & 1) * 8) * 2;

    ldg_tile(0);
    sts_tile(0);
    if (KT > 1) ldg_tile(1);
    __syncthreads();

    for (int kt = 0; kt < KT; kt++) {
        if (kt + 1 < KT) {
            sts_tile((kt + 1) & 1);
            if (kt + 2 < KT) ldg_tile(kt + 2);
            __syncthreads();
        }
        const uint32_t sbase = smb + (uint32_t)(kt & 1) * (STAGE * 2);
#pragma unroll
        for (int ks = 0; ks < 4; ks++) {
            const uint32_t koffB = ks * 32;    // 16 halfs
            uint32_t a[MF][4], b[8][2];
#pragma unroll
            for (int mf = 0; mf < MF; mf++)
                ldsm_x4(a[mf][0], a[mf][1], a[mf][2], a[mf][3],
                        sbase + a_l + mf * (16 * RSTRIDE_H * 2) + koffB);
#pragma unroll
            for (int p = 0; p < 4; p++)
                ldsm_x4(b[2 * p][0], b[2 * p][1], b[2 * p + 1][0], b[2 * p + 1][1],
                        sbase + b_l + p * (16 * RSTRIDE_H * 2) + koffB);
#pragma unroll
            for (int mf = 0; mf < MF; mf++)
#pragma unroll
                for (int nf = 0; nf < 8; nf++)
                    mma16(acc[mf][nf], a[mf], b[nf]);
        }
        __syncthreads();
    }

    // ---- epilogue ----
    float* sepi   = (float*)dsm_h;
    float* s_mean = sepi + 128 * EPIST;
    float* s_inv  = s_mean + 128;
    float* z_s    = sepi + 128 * EPIST;
    float* ksum_s = z_s + 512;
    float* kv_s   = ksum_s + 128;
    const bool doAct = (MODE != 3) || (blockIdx.z == 0);

    if (EPI == EPI_ATTN) {
        const int b = mtile >> 12;
        const int H0 = blockIdx.y * 4;
        const float4* kvg = (const float4*)(gamma + (((size_t)(b * 8 + H0)) * 32) * 32);
#pragma unroll
        for (int p = 0; p < 4; p++)
            *(float4*)&kv_s[(p * 256 + tid) * 4] = kvg[p * 256 + tid];
        if (tid < 32)
            *(float4*)&ksum_s[tid * 4] = *(const float4*)(beta + b * 256 + H0 * 32 + tid * 4);
    }

#pragma unroll
    for (int mf = 0; mf < MF; mf++) {
        int r0 = warp_m * MROWS + mf * 16 + g;
#pragma unroll
        for (int nf = 0; nf < 8; nf++) {
            int c0 = warp_n * 64 + nf * 8 + 2 * t;
            float v0 = acc[mf][nf][0], v1 = acc[mf][nf][1];
            float v2 = acc[mf][nf][2], v3 = acc[mf][nf][3];
            if ((EPI == EPI_ELU1 || EPI == EPI_ATTN) && doAct) {
                v0 = (v0 > 0.f) ? v0 + 1.f : __expf(v0);
                v1 = (v1 > 0.f) ? v1 + 1.f : __expf(v1);
                v2 = (v2 > 0.f) ? v2 + 1.f : __expf(v2);
                v3 = (v3 > 0.f) ? v3 + 1.f : __expf(v3);
            }
            if (EPI == EPI_RELU) {
                v0 = fmaxf(v0, 0.f); v1 = fmaxf(v1, 0.f);
                v2 = fmaxf(v2, 0.f); v3 = fmaxf(v3, 0.f);
            }
            *(float2*)&sepi[r0 * EPIST + c0]       = make_float2(v0, v1);
            *(float2*)&sepi[(r0 + 8) * EPIST + c0] = make_float2(v2, v3);
        }
    }
    __syncthreads();

    if (EPI == EPI_ATTN) {
#pragma unroll
        for (int i = 0; i < 2; i++) {
            int p = tid * 2 + i;
            int row = p >> 2, hh = p & 3;
            const float4* qp = (const float4*)&sepi[row * EPIST + hh * 32];
            const float4* kp = (const float4*)&ksum_s[hh * 32];
            float z = 0.f;
#pragma unroll
            for (int q4 = 0; q4 < 8; q4++) {
                float4 qv = qp[q4], kv4 = kp[q4];
                z += qv.x * kv4.x + qv.y * kv4.y + qv.z * kv4.z + qv.w * kv4.w;
            }
            z_s[p] = 1.f / (z + EPS_ATT);
        }
        __syncthreads();

        const int c  = tid & 31;
        const int hf = (tid >> 5) & 1;
        const int hh = tid >> 6;
        float kvr[32];
#pragma unroll
        for (int d = 0; d < 32; d++) kvr[d] = kv_s[hh * 1024 + d * 32 + c];
        __half* msgp = (__half*)Cout;
        const int colg = blockIdx.y * 128 + hh * 32 + c;
#pragma unroll 2
        for (int r = 0; r < 64; r++) {
            int row = hf * 64 + r;
            const float4* qp = (const float4*)&sepi[row * EPIST + hh * 32];
            float m = 0.f;
#pragma unroll
            for (int q4 = 0; q4 < 8; q4++) {
                float4 qv = qp[q4];
                m += qv.x * kvr[q4 * 4] + qv.y * kvr[q4 * 4 + 1]
                   + qv.z * kvr[q4 * 4 + 2] + qv.w * kvr[q4 * 4 + 3];
            }
            m *= z_s[row * 4 + hh];
            msgp[(size_t)(mtile + row) * 256 + colg] = __float2half_rn(m);
        }
        return;
    }

    if ((EPI == EPI_LN || EPI == EPI_LN_RESID) && tid < 128) {
        const float* rowp = sepi + tid * EPIST;
        float sum = 0.f, ss = 0.f;
#pragma unroll 8
        for (int j = 0; j < NB / 4; j++) {
            float4 v = *(const float4*)&rowp[j * 4];
            sum += v.x + v.y + v.z + v.w;
            ss  += v.x * v.x + v.y * v.y + v.z * v.z + v.w * v.w;
        }
        float mean = sum * (1.f / 256.f);
        float var  = ss * (1.f / 256.f) - mean * mean;
        s_mean[tid] = mean;
        s_inv[tid]  = rsqrtf(var + EPS_LN);
    }
    if (EPI == EPI_LN || EPI == EPI_LN_RESID) __syncthreads();

#pragma unroll 4
    for (int p = 0; p < NB / 8; p++) {
        int idx4 = p * 256 + tid;
        int row = idx4 / (NB / 4);
        int c4  = (idx4 % (NB / 4)) << 2;
        float4 v = *(const float4*)&sepi[row * EPIST + c4];
        if (EPI == EPI_LN || EPI == EPI_LN_RESID) {
            float m = s_mean[row], iv = s_inv[row];
            float4 gm = *(const float4*)&gamma[c4];
            float4 bt = *(const float4*)&beta[c4];
            v.x = (v.x - m) * iv * gm.x + bt.x;
            v.y = (v.y - m) * iv * gm.y + bt.y;
            v.z = (v.z - m) * iv * gm.z + bt.z;
            v.w = (v.w - m) * iv * gm.w + bt.w;
            if (EPI == EPI_LN_RESID) {
                float4 r = *(const float4*)&resid[(size_t)(mtile + row) * 256 + c4];
                v.x += r.x; v.y += r.y; v.z += r.z; v.w += r.w;
            }
        }
        size_t off = coff + (size_t)(mtile + row) * Ntot + ncol0 + c4;
        if (OUTH) {
            __half2 h0 = __floats2half2_rn(v.x, v.y);
            __half2 h1 = __floats2half2_rn(v.z, v.w);
            *(uint2*)&((__half*)Cout)[off] = make_uint2(h2u(h0), h2u(h1));
        } else {
            *(float4*)&((float*)Cout)[off] = v;
        }
    }
}

// ---------------------------------------------------------------------------
// KV = sum_s K^T V, Ksum = sum_s K. fp16 in, fp32 math. grid 64, 256 thr.
// ---------------------------------------------------------------------------
__global__ void kv_kernel(const __half* __restrict__ kmat, const __half* __restrict__ vmat,
                          float* __restrict__ kv, float* __restrict__ ksum) {
    __shared__ float Ks[128][32];
    __shared__ float Vs[128][32];
    int bh = blockIdx.x, b = bh >> 3, h = bh & 7;
    int tid = threadIdx.x;
    int d = tid & 31, vg = tid >> 5;
    float acc0 = 0.f, acc1 = 0.f, acc2 = 0.f, acc3 = 0.f, ka = 0.f;

    for (int ch = 0; ch < 2; ch++) {
        int sl = tid >> 3, c4 = tid & 7;
#pragma unroll
        for (int ss = 0; ss < 4; ss++) {
            int srow = ch * 128 + ss * 32 + sl;
            size_t base = ((size_t)(b * 256 + srow)) * 256 + h * 32 + c4 * 4;
            uint2 kw = *(const uint2*)&kmat[base];
            uint2 vw = *(const uint2*)&vmat[base];
            __half2* kh = (__half2*)&kw;
            __half2* vh = (__half2*)&vw;
            float2 k0 = __half22float2(kh[0]), k1 = __half22float2(kh[1]);
            float2 w0 = __half22float2(vh[0]), w1 = __half22float2(vh[1]);
            Ks[ss * 32 + sl][c4 * 4 + 0] = k0.x; Ks[ss * 32 + sl][c4 * 4 + 1] = k0.y;
            Ks[ss * 32 + sl][c4 * 4 + 2] = k1.x; Ks[ss * 32 + sl][c4 * 4 + 3] = k1.y;
            Vs[ss * 32 + sl][c4 * 4 + 0] = w0.x; Vs[ss * 32 + sl][c4 * 4 + 1] = w0.y;
            Vs[ss * 32 + sl][c4 * 4 + 2] = w1.x; Vs[ss * 32 + sl][c4 * 4 + 3] = w1.y;
        }
        __syncthreads();
#pragma unroll 4
        for (int s = 0; s < 128; s++) {
            float kd = Ks[s][d];
            float4 vv = *(float4*)&Vs[s][vg * 4];
            acc0 += kd * vv.x; acc1 += kd * vv.y;
            acc2 += kd * vv.z; acc3 += kd * vv.w;
            if (vg == 0) ka += kd;
        }
        __syncthreads();
    }
    float* kvp = kv + ((size_t)bh * 32 + d) * 32 + vg * 4;
    kvp[0] = acc0; kvp[1] = acc1; kvp[2] = acc2; kvp[3] = acc3;
    if (vg == 0) ksum[bh * 32 + d] = ka;
}

// ---------------------------------------------------------------------------
// Launch
// ---------------------------------------------------------------------------
extern "C" void kernel_launch(void* const* d_in, const int* in_sizes, int n_in,
                              void* d_out, int out_size) {
    const float* x      = (const float*)d_in[0];
    const float* sr_w   = (const float*)d_in[1];
    const float* sr_b   = (const float*)d_in[2];
    const float* norm_g = (const float*)d_in[3];
    const float* norm_b = (const float*)d_in[4];
    const float* wq     = (const float*)d_in[5];
    const float* wk     = (const float*)d_in[6];
    const float* wv     = (const float*)d_in[7];
    const float* wm     = (const float*)d_in[8];
    const float* w1     = (const float*)d_in[9];
    const float* w2     = (const float*)d_in[10];
    const float* n1g    = (const float*)d_in[11];
    const float* n1b    = (const float*)d_in[12];
    const float* n2g    = (const float*)d_in[13];
    const float* n2b    = (const float*)d_in[14];
    float* out = (float*)d_out;

    __half *wsrB, *wqr, *wkr, *wvr, *wmr, *w1r, *w2r;
    __half *xh, *part, *src, *kmat, *vmat, *msg, *msgn, *hmid;
    float *kvp, *ksump;
    cudaGetSymbolAddress((void**)&wsrB, g_wsrB);
    cudaGetSymbolAddress((void**)&wqr,  g_wqr);
    cudaGetSymbolAddress((void**)&wkr,  g_wkr);
    cudaGetSymbolAddress((void**)&wvr,  g_wvr);
    cudaGetSymbolAddress((void**)&wmr,  g_wmr);
    cudaGetSymbolAddress((void**)&w1r,  g_w1r);
    cudaGetSymbolAddress((void**)&w2r,  g_w2r);
    cudaGetSymbolAddress((void**)&xh,   g_xh);
    cudaGetSymbolAddress((void**)&part, g_part);
    cudaGetSymbolAddress((void**)&src,  g_src);
    cudaGetSymbolAddress((void**)&kmat, g_kmat);
    cudaGetSymbolAddress((void**)&vmat, g_vmat);
    cudaGetSymbolAddress((void**)&kvp,  g_kv);
    cudaGetSymbolAddress((void**)&ksump,g_ksum);
    cudaGetSymbolAddress((void**)&msg,  g_msg);
    cudaGetSymbolAddress((void**)&msgn, g_msgn);
    cudaGetSymbolAddress((void**)&hmid, g_hmid);

    constexpr int SM128  = smem_req(128, EPI_PLAIN);
    constexpr int SMATTN = smem_req(128, EPI_ATTN);
    constexpr int SM256  = smem_req(256, EPI_LN);
    cudaFuncSetAttribute(mma_gemm<EPI_PLAIN, 2, 128, true>,    cudaFuncAttributeMaxDynamicSharedMemorySize, SM128);
    cudaFuncSetAttribute(mma_gemm<EPI_ELU1, 3, 128, true>,     cudaFuncAttributeMaxDynamicSharedMemorySize, SM128);
    cudaFuncSetAttribute(mma_gemm<EPI_ATTN, 0, 128, true>,     cudaFuncAttributeMaxDynamicSharedMemorySize, SMATTN);
    cudaFuncSetAttribute(mma_gemm<EPI_RELU, 1, 128, true>,     cudaFuncAttributeMaxDynamicSharedMemorySize, SM128);
    cudaFuncSetAttribute(mma_gemm<EPI_LN, 0, 256, true>,       cudaFuncAttributeMaxDynamicSharedMemorySize, SM256);
    cudaFuncSetAttribute(mma_gemm<EPI_LN_RESID, 0, 256, false>,cudaFuncAttributeMaxDynamicSharedMemorySize, SM256);

    prep_all<<<11008, 256>>>(x, sr_w, wq, wk, wv, wm, w1, w2,
                             xh, wsrB, wqr, wkr, wvr, wmr, w1r, w2r);

    // conv-as-GEMM (split-K=8 on z) + reduce/bias/LN -> src
    mma_gemm<EPI_PLAIN, 2, 128, true><<<dim3(16, 2, 8), 256, SM128>>>(
        xh, nullptr, wsrB, part, 512, 4096, 256, nullptr, nullptr, nullptr, nullptr, nullptr);
    reduce_ln<<<256, 256>>>(part, sr_b, norm_g, norm_b, src);

    // fused k/v projections (M=2048)
    mma_gemm<EPI_ELU1, 3, 128, true><<<dim3(16, 2, 2), 256, SM128>>>(
        src, nullptr, wkr, kmat, 256, 256, 256, nullptr, nullptr, nullptr, wvr, vmat);

    kv_kernel<<<64, 256>>>(kmat, vmat, kvp, ksump);

    // q projection + fused linear attention -> msg
    mma_gemm<EPI_ATTN, 0, 128, true><<<dim3(256, 2), 256, SMATTN>>>(
        xh, nullptr, wqr, msg, 256, 256, 256, kvp, ksump, nullptr, nullptr, nullptr);

    // merge projection + LN1
    mma_gemm<EPI_LN, 0, 256, true><<<dim3(256, 1), 256, SM256>>>(
        msg, nullptr, wmr, msgn, 256, 256, 256, n1g, n1b, nullptr, nullptr, nullptr);

    // MLP1: concat(xh, msgn) @ w1^T -> relu
    mma_gemm<EPI_RELU, 1, 128, true><<<dim3(256, 4), 256, SM128>>>(
        xh, msgn, w1r, hmid, 512, 512, 512, nullptr, nullptr, nullptr, nullptr, nullptr);

    // MLP2 + LN2 + residual -> out (fp32)
    mma_gemm<EPI_LN_RESID, 0, 256, false><<<dim3(256, 1), 256, SM256>>>(
        hmid, nullptr, w2r, out, 512, 512, 256, n2g, n2b, x, nullptr, nullptr);
}